// round 2
// baseline (speedup 1.0000x reference)
#include <cuda_runtime.h>
#include <math.h>

// ---------------- problem constants ----------------
#define BN   8
#define TT   1024
#define CCH  768
#define HH   12
#define HSZ  64
#define EE   8
#define FF   3072
#define NT   (BN*TT)        // 8192 tokens
#define BH   (BN*HH)        // 96

// ---------------- static scratch (no allocs allowed) ----------------
__device__ float g_h1[NT*CCH];
__device__ float g_q [BH*TT*HSZ];
__device__ float g_k [BH*TT*HSZ];
__device__ float g_v [BH*TT*HSZ];
__device__ float g_S [(size_t)BH*TT*TT];    // 402 MB attention scores/probs
__device__ float g_ao[NT*CCH];
__device__ float g_x2[NT*CCH];
__device__ float g_h2[NT*CCH];
__device__ float g_gw[NT*2];
__device__ int   g_pos[NT*2];
__device__ int   g_tok[EE*NT];
__device__ int   g_cnt[EE];
__device__ float g_t1[NT*FF];
__device__ float g_t2[NT*FF];
__device__ float g_t3[NT*CCH];
__device__ float g_ob[(size_t)EE*NT*CCH];   // expert outputs by global slot

__device__ __forceinline__ float geluf(float v){
    return 0.5f*v*(1.f + erff(v*0.70710678118654752440f));
}

// ---------------- reset per-replay state ----------------
__global__ void k_reset(){ if(threadIdx.x < EE) g_cnt[threadIdx.x] = 0; }

// ---------------- row LayerNorm: out = LN(in)*g+b, rows of 768 ----------------
__global__ void k_ln(const float* __restrict__ in, const float* __restrict__ gam,
                     const float* __restrict__ bet, float* __restrict__ out){
    int n = blockIdx.x, t = threadIdx.x;
    const float* row = in + (size_t)n*CCH;
    float v[3], s = 0.f, s2 = 0.f;
#pragma unroll
    for(int i=0;i<3;i++){ v[i]=row[t+256*i]; s+=v[i]; s2+=v[i]*v[i]; }
    __shared__ float shs[8], shq[8];
#pragma unroll
    for(int o=16;o;o>>=1){ s+=__shfl_xor_sync(~0u,s,o); s2+=__shfl_xor_sync(~0u,s2,o); }
    if((t&31)==0){ shs[t>>5]=s; shq[t>>5]=s2; }
    __syncthreads();
    s=0.f; s2=0.f;
#pragma unroll
    for(int i=0;i<8;i++){ s+=shs[i]; s2+=shq[i]; }
    float mean = s*(1.f/768.f);
    float var  = s2*(1.f/768.f) - mean*mean;
    float r = rsqrtf(var + 1e-5f);
#pragma unroll
    for(int i=0;i<3;i++){
        int c = t+256*i;
        out[(size_t)n*CCH+c] = (v[i]-mean)*r*gam[c] + bet[c];
    }
}

// ---------------- QKV projection: per (b,h,{q,k,v}) 64x64 tiles ----------------
__global__ void k_qkv(const float* __restrict__ h1, const float* __restrict__ wq,
                      const float* __restrict__ wk, const float* __restrict__ wv){
    int tb = blockIdx.x, bh = blockIdx.y, which = blockIdx.z;
    int b = bh / HH, h = bh % HH;
    const float* W = (which==0? wq : which==1? wk : wv) + (size_t)h*CCH*HSZ;
    float* O = (which==0? g_q : which==1? g_k : g_v) + (size_t)bh*TT*HSZ;
    __shared__ float As[16][68];
    __shared__ float Bs[16][64];
    int tid = threadIdx.x, ty = tid>>4, tx = tid&15;
    int arow = tid>>2, akq = (tid&3)*4;
    const float* Ap = h1 + ((size_t)b*TT + tb*64 + arow)*CCH;
    int brow = tid>>4, bd = (tid&15)*4;
    float acc[4][4] = {};
    for(int k0=0;k0<CCH;k0+=16){
        float4 av = *(const float4*)(Ap + k0 + akq);
        As[akq+0][arow]=av.x; As[akq+1][arow]=av.y; As[akq+2][arow]=av.z; As[akq+3][arow]=av.w;
        *(float4*)&Bs[brow][bd] = *(const float4*)(W + (size_t)(k0+brow)*HSZ + bd);
        __syncthreads();
#pragma unroll
        for(int kk=0;kk<16;kk++){
            float a[4], bb[4];
#pragma unroll
            for(int i=0;i<4;i++) a[i]=As[kk][ty*4+i];
#pragma unroll
            for(int j=0;j<4;j++) bb[j]=Bs[kk][tx*4+j];
#pragma unroll
            for(int i=0;i<4;i++)
#pragma unroll
                for(int j=0;j<4;j++) acc[i][j]+=a[i]*bb[j];
        }
        __syncthreads();
    }
#pragma unroll
    for(int i=0;i<4;i++)
#pragma unroll
        for(int j=0;j<4;j++)
            O[(size_t)(tb*64+ty*4+i)*HSZ + tx*4+j] = acc[i][j];
}

// ---------------- scores: S = scale * Q K^T with causal mask ----------------
__global__ void k_scores(){
    int sb = blockIdx.x, tb = blockIdx.y, bh = blockIdx.z;
    if(sb > tb) return;                // strictly-upper tiles never read (softmax zeros tail)
    __shared__ float Qs[64][65];       // [d][t]
    __shared__ float Ks[64][65];       // [d][s]
    const float* Q = g_q + (size_t)bh*TT*HSZ + (size_t)tb*64*HSZ;
    const float* K = g_k + (size_t)bh*TT*HSZ + (size_t)sb*64*HSZ;
    int tid = threadIdx.x;
#pragma unroll
    for(int i=0;i<4;i++){
        int idx = tid + i*256;
        int r = idx>>4, d4 = (idx&15)*4;
        float4 qv = *(const float4*)(Q + r*HSZ + d4);
        Qs[d4+0][r]=qv.x; Qs[d4+1][r]=qv.y; Qs[d4+2][r]=qv.z; Qs[d4+3][r]=qv.w;
        float4 kv = *(const float4*)(K + r*HSZ + d4);
        Ks[d4+0][r]=kv.x; Ks[d4+1][r]=kv.y; Ks[d4+2][r]=kv.z; Ks[d4+3][r]=kv.w;
    }
    __syncthreads();
    int ty = tid>>4, tx = tid&15;
    float acc[4][4] = {};
#pragma unroll
    for(int k=0;k<64;k++){
        float a[4], bb[4];
#pragma unroll
        for(int i=0;i<4;i++) a[i]=Qs[k][ty*4+i];
#pragma unroll
        for(int j=0;j<4;j++) bb[j]=Ks[k][tx*4+j];
#pragma unroll
        for(int i=0;i<4;i++)
#pragma unroll
            for(int j=0;j<4;j++) acc[i][j]+=a[i]*bb[j];
    }
    const float scale = 0.036084391824351615f;  // 768^-0.5
    float* S = g_S + (size_t)bh*TT*TT;
#pragma unroll
    for(int i=0;i<4;i++){
        int tg = tb*64+ty*4+i;
#pragma unroll
        for(int j=0;j<4;j++){
            int sg = sb*64+tx*4+j;
            S[(size_t)tg*TT + sg] = (sg<=tg) ? acc[i][j]*scale : -1e30f;
        }
    }
}

// ---------------- row softmax over [0,t], zero tail ----------------
__global__ void k_softmax(){
    int row = blockIdx.x;
    int bh = row>>10, t = row & (TT-1);
    float* S = g_S + (size_t)bh*TT*TT + (size_t)t*TT;
    int len = t+1, tid = threadIdx.x;
    __shared__ float sh[8];
    float m = -1e30f;
    for(int s=tid;s<len;s+=256) m = fmaxf(m, S[s]);
#pragma unroll
    for(int o=16;o;o>>=1) m = fmaxf(m, __shfl_xor_sync(~0u,m,o));
    if((tid&31)==0) sh[tid>>5]=m;
    __syncthreads();
    m = sh[0];
#pragma unroll
    for(int i=1;i<8;i++) m = fmaxf(m, sh[i]);
    __syncthreads();
    float sum = 0.f;
    for(int s=tid;s<len;s+=256){ float e = expf(S[s]-m); S[s]=e; sum+=e; }
#pragma unroll
    for(int o=16;o;o>>=1) sum += __shfl_xor_sync(~0u,sum,o);
    if((tid&31)==0) sh[tid>>5]=sum;
    __syncthreads();
    sum = 0.f;
#pragma unroll
    for(int i=0;i<8;i++) sum += sh[i];
    float inv = 1.f/sum;
    for(int s=tid;s<TT;s+=256) S[s] = (s<len) ? S[s]*inv : 0.f;
}

// ---------------- O = P @ V, write to [b,t,h*HS+d] ----------------
__global__ void k_av(){
    int tb = blockIdx.x, bh = blockIdx.y;
    const float* P = g_S + (size_t)bh*TT*TT;
    const float* V = g_v + (size_t)bh*TT*HSZ;
    __shared__ float As[16][68];
    __shared__ float Bs[16][64];
    int tid = threadIdx.x, ty = tid>>4, tx = tid&15;
    int arow = tid>>2, akq = (tid&3)*4;
    int brow = tid>>4, bd = (tid&15)*4;
    int kmax = (tb+1)*64;              // P is zero for s > t
    float acc[4][4] = {};
    for(int k0=0;k0<kmax;k0+=16){
        float4 av = *(const float4*)(P + (size_t)(tb*64+arow)*TT + k0 + akq);
        As[akq+0][arow]=av.x; As[akq+1][arow]=av.y; As[akq+2][arow]=av.z; As[akq+3][arow]=av.w;
        *(float4*)&Bs[brow][bd] = *(const float4*)(V + (size_t)(k0+brow)*HSZ + bd);
        __syncthreads();
#pragma unroll
        for(int kk=0;kk<16;kk++){
            float a[4], bb[4];
#pragma unroll
            for(int i=0;i<4;i++) a[i]=As[kk][ty*4+i];
#pragma unroll
            for(int j=0;j<4;j++) bb[j]=Bs[kk][tx*4+j];
#pragma unroll
            for(int i=0;i<4;i++)
#pragma unroll
                for(int j=0;j<4;j++) acc[i][j]+=a[i]*bb[j];
        }
        __syncthreads();
    }
    int b = bh/HH, h = bh%HH;
#pragma unroll
    for(int i=0;i<4;i++)
#pragma unroll
        for(int j=0;j<4;j++)
            g_ao[((size_t)b*TT + tb*64+ty*4+i)*CCH + h*HSZ + tx*4+j] = acc[i][j];
}

// ---------------- generic 128x128x8 SGEMM w/ epilogue options ----------------
// EPI: 0 = bias, 1 = bias+GELU. Optional gather (tok) and dynamic M (cnt),
// optional residual added after epilogue.
template<int EPI>
__global__ void __launch_bounds__(256)
k_gemm128(const float* __restrict__ A, const float* __restrict__ Bm,
          const float* __restrict__ bias, const float* __restrict__ resid,
          float* __restrict__ Co, int M, int Nn, int K,
          const int* __restrict__ tok, const int* __restrict__ cnt){
    if(cnt) M = *cnt;
    int by = blockIdx.y;
    if(by*128 >= M) return;
    int bx = blockIdx.x;
    __shared__ float As[8][132];
    __shared__ float Bs[8][128];
    int tid = threadIdx.x;
    int arow = tid>>1, akq = (tid&1)*4;
    int grow = by*128 + arow;
    bool aval = grow < M;
    int asrc = aval ? (tok ? tok[grow] : grow) : 0;
    const float* Ap = A + (size_t)asrc*K;
    int brow = tid>>5, bcol = (tid&31)*4;
    const float* Bp = Bm + (size_t)brow*Nn + bx*128 + bcol;
    float acc[8][8] = {};
    int rm = (tid>>4)*8, cn = (tid&15)*8;
    for(int k0=0;k0<K;k0+=8){
        float4 av = aval ? *(const float4*)(Ap + k0 + akq) : make_float4(0,0,0,0);
        As[akq+0][arow]=av.x; As[akq+1][arow]=av.y; As[akq+2][arow]=av.z; As[akq+3][arow]=av.w;
        *(float4*)&Bs[brow][bcol] = *(const float4*)(Bp + (size_t)k0*Nn);
        __syncthreads();
#pragma unroll
        for(int kk=0;kk<8;kk++){
            float a[8], bb[8];
            *(float4*)(a  ) = *(const float4*)&As[kk][rm  ];
            *(float4*)(a+4) = *(const float4*)&As[kk][rm+4];
            *(float4*)(bb  ) = *(const float4*)&Bs[kk][cn  ];
            *(float4*)(bb+4) = *(const float4*)&Bs[kk][cn+4];
#pragma unroll
            for(int i=0;i<8;i++)
#pragma unroll
                for(int j=0;j<8;j++) acc[i][j] += a[i]*bb[j];
        }
        __syncthreads();
    }
#pragma unroll
    for(int i=0;i<8;i++){
        int r = by*128+rm+i;
        if(r >= M) break;
        size_t off = (size_t)r*Nn + bx*128+cn;
#pragma unroll
        for(int j=0;j<8;j++){
            float v = acc[i][j] + (bias ? bias[bx*128+cn+j] : 0.f);
            if(EPI==1) v = geluf(v);
            if(resid) v += resid[off+j];
            Co[off+j] = v;
        }
    }
}

// ---------------- noisy top-2 router, builds per-expert token lists ----------------
__global__ void k_router(const float* __restrict__ wr, const float* __restrict__ br,
                         const float* __restrict__ wn, const float* __restrict__ bnn,
                         const float* __restrict__ temp, const float* __restrict__ noise){
    int warp = threadIdx.x>>5, lane = threadIdx.x&31;
    int n = blockIdx.x*8 + warp;
    const float* hp = g_h2 + (size_t)n*CCH;
    float r[8] = {}, q[8] = {};
    for(int c=lane;c<CCH;c+=32){
        float hv = hp[c];
        const float* wrp = wr + c*EE;
        const float* wnp = wn + c*EE;
#pragma unroll
        for(int e=0;e<8;e++){ r[e]+=hv*wrp[e]; q[e]+=hv*wnp[e]; }
    }
#pragma unroll
    for(int e=0;e<8;e++)
#pragma unroll
        for(int o=16;o;o>>=1){
            r[e]+=__shfl_xor_sync(~0u,r[e],o);
            q[e]+=__shfl_xor_sync(~0u,q[e],o);
        }
    if(lane==0){
        float t = fminf(fmaxf(temp[0], 0.5f), 2.0f);
        float noisy[8];
#pragma unroll
        for(int e=0;e<8;e++){
            float lg = r[e]+br[e];
            float z  = q[e]+bnn[e];
            float sp = (z > 20.f) ? z : log1pf(expf(z));
            noisy[e] = lg + t*noise[(size_t)n*EE+e]*sp;
        }
        int i1 = 0;
#pragma unroll
        for(int e=1;e<8;e++) if(noisy[e] > noisy[i1]) i1 = e;
        int i2 = -1;
#pragma unroll
        for(int e=0;e<8;e++){ if(e==i1) continue; if(i2<0 || noisy[e]>noisy[i2]) i2=e; }
        float m = noisy[i1];
        float e2 = expf(noisy[i2]-m);
        float ssum = 1.f + e2;
        float gv[2] = { 1.f/ssum, e2/ssum };
        int   id[2] = { i1, i2 };
#pragma unroll
        for(int k2=0;k2<2;k2++){
            int e = id[k2];
            int row = atomicAdd(&g_cnt[e], 1);
            g_tok[e*NT+row] = n;
            g_pos[n*2+k2]   = e*NT+row;
            g_gw [n*2+k2]   = gv[k2];
        }
    }
}

// ---------------- per-expert residual LayerNorm, scatter to slot buffer ----------------
__global__ void k_resln(const float* __restrict__ t3, int e,
                        const float* __restrict__ gam, const float* __restrict__ bet){
    int r = blockIdx.x;
    if(r >= g_cnt[e]) return;
    int n = g_tok[e*NT + r];
    int t = threadIdx.x;
    float v[3], s=0.f, s2=0.f;
#pragma unroll
    for(int i=0;i<3;i++){
        int c = t+256*i;
        v[i] = g_h2[(size_t)n*CCH+c] + t3[(size_t)r*CCH+c];
        s += v[i]; s2 += v[i]*v[i];
    }
    __shared__ float shs[8], shq[8];
#pragma unroll
    for(int o=16;o;o>>=1){ s+=__shfl_xor_sync(~0u,s,o); s2+=__shfl_xor_sync(~0u,s2,o); }
    if((t&31)==0){ shs[t>>5]=s; shq[t>>5]=s2; }
    __syncthreads();
    s=0.f; s2=0.f;
#pragma unroll
    for(int i=0;i<8;i++){ s+=shs[i]; s2+=shq[i]; }
    float mean = s*(1.f/768.f);
    float var  = s2*(1.f/768.f) - mean*mean;
    float rs = rsqrtf(var + 1e-5f);
    float* ob = g_ob + (size_t)(e*NT + r)*CCH;
#pragma unroll
    for(int i=0;i<3;i++){
        int c = t+256*i;
        ob[c] = (v[i]-mean)*rs*gam[c] + bet[c];
    }
}

// ---------------- final gated combine + residual ----------------
__global__ void k_combine(float* __restrict__ out){
    int n = blockIdx.x, t = threadIdx.x;
    float g0 = g_gw[n*2], g1 = g_gw[n*2+1];
    const float* o0 = g_ob + (size_t)g_pos[n*2  ]*CCH;
    const float* o1 = g_ob + (size_t)g_pos[n*2+1]*CCH;
#pragma unroll
    for(int i=0;i<3;i++){
        int c = t+256*i;
        out[(size_t)n*CCH+c] = g_x2[(size_t)n*CCH+c] + g0*o0[c] + g1*o1[c];
    }
}

// ---------------- host orchestration ----------------
extern "C" void kernel_launch(void* const* d_in, const int* in_sizes, int n_in,
                              void* d_out, int out_size){
    const float* x       = (const float*)d_in[0];
    const float* rnoise  = (const float*)d_in[1];
    const float* wq      = (const float*)d_in[2];
    const float* wk      = (const float*)d_in[3];
    const float* wv      = (const float*)d_in[4];
    const float* w_proj  = (const float*)d_in[5];
    const float* b_proj  = (const float*)d_in[6];
    const float* ln1_g   = (const float*)d_in[7];
    const float* ln1_b   = (const float*)d_in[8];
    const float* ln2_g   = (const float*)d_in[9];
    const float* ln2_b   = (const float*)d_in[10];
    const float* w_route = (const float*)d_in[11];
    const float* b_route = (const float*)d_in[12];
    const float* w_noise = (const float*)d_in[13];
    const float* b_noise = (const float*)d_in[14];
    const float* temp    = (const float*)d_in[15];
    const float* dw1     = (const float*)d_in[16];
    const float* db1     = (const float*)d_in[17];
    const float* dw2     = (const float*)d_in[18];
    const float* db2     = (const float*)d_in[19];
    const float* dw3     = (const float*)d_in[20];
    const float* db3     = (const float*)d_in[21];
    const float* dlng    = (const float*)d_in[22];
    const float* dlnb    = (const float*)d_in[23];
    const float* sw1     = (const float*)d_in[24];
    const float* sb1     = (const float*)d_in[25];
    const float* sw2     = (const float*)d_in[26];
    const float* sb2     = (const float*)d_in[27];
    const float* slng    = (const float*)d_in[28];
    const float* slnb    = (const float*)d_in[29];
    float* out = (float*)d_out;

    // resolve scratch addresses (not allocations)
    float *p_h1, *p_ao, *p_x2, *p_h2, *p_t1, *p_t2, *p_t3;
    int *p_tok, *p_cnt;
    cudaGetSymbolAddress((void**)&p_h1, g_h1);
    cudaGetSymbolAddress((void**)&p_ao, g_ao);
    cudaGetSymbolAddress((void**)&p_x2, g_x2);
    cudaGetSymbolAddress((void**)&p_h2, g_h2);
    cudaGetSymbolAddress((void**)&p_t1, g_t1);
    cudaGetSymbolAddress((void**)&p_t2, g_t2);
    cudaGetSymbolAddress((void**)&p_t3, g_t3);
    cudaGetSymbolAddress((void**)&p_tok, g_tok);
    cudaGetSymbolAddress((void**)&p_cnt, g_cnt);

    k_reset<<<1,32>>>();
    // attention
    k_ln<<<NT,256>>>(x, ln1_g, ln1_b, p_h1);
    k_qkv<<<dim3(TT/64, BH, 3),256>>>(p_h1, wq, wk, wv);
    k_scores<<<dim3(16,16,BH),256>>>();
    k_softmax<<<BH*TT,256>>>();
    k_av<<<dim3(16,BH),256>>>();
    k_gemm128<0><<<dim3(CCH/128, NT/128),256>>>(p_ao, w_proj, b_proj, x, p_x2,
                                                NT, CCH, CCH, nullptr, nullptr);
    // router
    k_ln<<<NT,256>>>(p_x2, ln2_g, ln2_b, p_h2);
    k_router<<<NT/8,256>>>(w_route, b_route, w_noise, b_noise, temp, rnoise);

    // deep experts (0,1): C->F gelu, F->F gelu, F->C, residual LN
    for(int e=0;e<2;e++){
        k_gemm128<1><<<dim3(FF/128, NT/128),256>>>(p_h2, dw1+(size_t)e*CCH*FF, db1+e*FF,
                nullptr, p_t1, NT, FF, CCH, p_tok+e*NT, p_cnt+e);
        k_gemm128<1><<<dim3(FF/128, NT/128),256>>>(p_t1, dw2+(size_t)e*FF*FF, db2+e*FF,
                nullptr, p_t2, NT, FF, FF, nullptr, p_cnt+e);
        k_gemm128<0><<<dim3(CCH/128, NT/128),256>>>(p_t2, dw3+(size_t)e*FF*CCH, db3+e*CCH,
                nullptr, p_t3, NT, CCH, FF, nullptr, p_cnt+e);
        k_resln<<<NT,256>>>(p_t3, e, dlng+e*CCH, dlnb+e*CCH);
    }
    // simple experts (2..7): C->F gelu, F->C, residual LN
    for(int e=0;e<6;e++){
        int ge = 2+e;
        k_gemm128<1><<<dim3(FF/128, NT/128),256>>>(p_h2, sw1+(size_t)e*CCH*FF, sb1+e*FF,
                nullptr, p_t1, NT, FF, CCH, p_tok+ge*NT, p_cnt+ge);
        k_gemm128<0><<<dim3(CCH/128, NT/128),256>>>(p_t1, sw2+(size_t)e*FF*CCH, sb2+e*CCH,
                nullptr, p_t3, NT, CCH, FF, nullptr, p_cnt+ge);
        k_resln<<<NT,256>>>(p_t3, ge, slng+e*CCH, slnb+e*CCH);
    }
    // combine
    k_combine<<<NT,256>>>(out);
}

// round 4
// speedup vs baseline: 2.7019x; 2.7019x over previous
#include <cuda_runtime.h>
#include <cuda_bf16.h>
#include <stdint.h>
#include <math.h>

#define BN 8
#define TT 1024
#define CCH 768
#define HH 12
#define HSZ 64
#define EE 8
#define FF 3072
#define NT (BN*TT)
#define BH (BN*HH)
typedef __nv_bfloat16 bf16;

// ---- static scratch ----
__device__ float g_q[BH*TT*HSZ];
__device__ float g_k[BH*TT*HSZ];
__device__ float g_v[BH*TT*HSZ];
__device__ float g_S[(size_t)BH*TT*TT];
__device__ bf16  g_h1h[NT*CCH], g_h1l[NT*CCH];
__device__ bf16  g_aoh[NT*CCH], g_aol[NT*CCH];
__device__ float g_x2[NT*CCH];
__device__ float g_h2[NT*CCH];
__device__ bf16  g_h2h[NT*CCH], g_h2l[NT*CCH];
__device__ float g_gw[NT*2];
__device__ int   g_pos[NT*2];
__device__ int   g_tok[EE*NT];
__device__ int   g_cnt[EE];
__device__ bf16  g_t1h[NT*FF], g_t1l[NT*FF];
__device__ bf16  g_t2h[NT*FF], g_t2l[NT*FF];
__device__ float g_t3[NT*CCH];
__device__ float g_ob[(size_t)EE*NT*CCH];
__device__ bf16  g_Bqh[3*CCH*CCH], g_Bql[3*CCH*CCH];
__device__ bf16  g_Bph[CCH*CCH],  g_Bpl[CCH*CCH];
__device__ bf16  g_Bd1h[2*CCH*FF], g_Bd1l[2*CCH*FF];
__device__ bf16  g_Bd2h[(size_t)2*FF*FF], g_Bd2l[(size_t)2*FF*FF];
__device__ bf16  g_Bd3h[2*CCH*FF], g_Bd3l[2*CCH*FF];
__device__ bf16  g_Bs1h[(size_t)6*CCH*FF], g_Bs1l[(size_t)6*CCH*FF];
__device__ bf16  g_Bs2h[(size_t)6*CCH*FF], g_Bs2l[(size_t)6*CCH*FF];

__device__ __forceinline__ float geluf(float v){
    return 0.5f*v*(1.f + erff(v*0.70710678118654752440f));
}
__device__ __forceinline__ uint32_t smem_u32(const void* p){
    uint32_t a;
    asm("{ .reg .u64 t; cvta.to.shared.u64 t, %1; cvt.u32.u64 %0, t; }" : "=r"(a) : "l"(p));
    return a;
}
__device__ __forceinline__ void cp16(uint32_t d, const void* s){
    asm volatile("cp.async.cg.shared.global [%0], [%1], 16;" :: "r"(d), "l"(s));
}
__device__ __forceinline__ void ldsm4(uint32_t a, uint32_t* r){
    asm volatile("ldmatrix.sync.aligned.m8n8.x4.shared.b16 {%0,%1,%2,%3}, [%4];"
        : "=r"(r[0]),"=r"(r[1]),"=r"(r[2]),"=r"(r[3]) : "r"(a));
}
__device__ __forceinline__ void mma16816(float* c, const uint32_t* a, const uint32_t* b){
    asm volatile("mma.sync.aligned.m16n8k16.row.col.f32.bf16.bf16.f32 "
        "{%0,%1,%2,%3},{%4,%5,%6,%7},{%8,%9},{%0,%1,%2,%3};"
        : "+f"(c[0]),"+f"(c[1]),"+f"(c[2]),"+f"(c[3])
        : "r"(a[0]),"r"(a[1]),"r"(a[2]),"r"(a[3]), "r"(b[0]),"r"(b[1]));
}

__global__ void k_reset(){ if(threadIdx.x < EE) g_cnt[threadIdx.x] = 0; }

// W[K][N] -> out[N][K] hi/lo bf16
__global__ void k_wsplit(const float* __restrict__ W, bf16* __restrict__ oh,
                         bf16* __restrict__ ol, int K, int N){
    int e = blockIdx.z;
    W += (size_t)e*K*N; oh += (size_t)e*K*N; ol += (size_t)e*K*N;
    __shared__ float s[32][33];
    int n0 = blockIdx.x*32, k0 = blockIdx.y*32;
    int tx = threadIdx.x, ty = threadIdx.y;
#pragma unroll
    for(int r=0;r<4;r++){ int kk=ty+r*8; s[kk][tx] = W[(size_t)(k0+kk)*N + n0+tx]; }
    __syncthreads();
#pragma unroll
    for(int r=0;r<4;r++){
        int kk = ty+r*8;
        float v = s[tx][kk];
        bf16 hi = __float2bfloat16(v);
        size_t o = (size_t)(n0+kk)*K + k0+tx;
        oh[o]=hi; ol[o]=__float2bfloat16(v - __bfloat162float(hi));
    }
}

// LayerNorm: optional fp32 out, optional hi/lo out
__global__ void k_ln(const float* __restrict__ in, const float* __restrict__ gam,
                     const float* __restrict__ bet, float* __restrict__ out,
                     bf16* __restrict__ oh, bf16* __restrict__ ol){
    int n = blockIdx.x, t = threadIdx.x;
    const float* row = in + (size_t)n*CCH;
    float v[3], s=0.f, s2=0.f;
#pragma unroll
    for(int i=0;i<3;i++){ v[i]=row[t+256*i]; s+=v[i]; s2+=v[i]*v[i]; }
    __shared__ float shs[8], shq[8];
#pragma unroll
    for(int o=16;o;o>>=1){ s+=__shfl_xor_sync(~0u,s,o); s2+=__shfl_xor_sync(~0u,s2,o); }
    if((t&31)==0){ shs[t>>5]=s; shq[t>>5]=s2; }
    __syncthreads();
    s=0.f; s2=0.f;
#pragma unroll
    for(int i=0;i<8;i++){ s+=shs[i]; s2+=shq[i]; }
    float mean=s*(1.f/768.f), var=s2*(1.f/768.f)-mean*mean, r=rsqrtf(var+1e-5f);
#pragma unroll
    for(int i=0;i<3;i++){
        int c=t+256*i;
        float o=(v[i]-mean)*r*gam[c]+bet[c];
        if(out) out[(size_t)n*CCH+c]=o;
        if(oh){
            bf16 hi=__float2bfloat16(o);
            oh[(size_t)n*CCH+c]=hi;
            ol[(size_t)n*CCH+c]=__float2bfloat16(o-__bfloat162float(hi));
        }
    }
}

// ---- mma.sync split-bf16 GEMM: D = (Ah+Al)(Bh+Bl)^T ----
// tile 128x128, BK=32, 8 warps (warp 32x64), cp.async double buffer
// EPI: 0 QKV scatter, 1 bias+resid->out32, 2 bias+GELU->hi/lo, 3 bias->out32
#define PITCH 80
#define TILEB 10240
#define STAGEB 40960
#define SMEMSZ (2*STAGEB)

template<int EPI>
__global__ void __launch_bounds__(256,1)
k_mma(const bf16* __restrict__ Ah, const bf16* __restrict__ Al,
      const bf16* __restrict__ Bh, const bf16* __restrict__ Bl,
      const float* __restrict__ bias, const float* __restrict__ resid,
      float* __restrict__ out32, bf16* __restrict__ outH, bf16* __restrict__ outL,
      int M, int Nn, int K, const int* __restrict__ tok, const int* __restrict__ cnt){
    if(cnt) M = *cnt;
    int by = blockIdx.y, bx = blockIdx.x;
    if(by*128 >= M) return;
    extern __shared__ char smem[];
    uint32_t su = smem_u32(smem);
    int tid=threadIdx.x, lane=tid&31, wid=tid>>5;
    int wm=wid&3, wn=wid>>2;
    const int KT = K/32;

    float acc[2][8][4];
#pragma unroll
    for(int a=0;a<2;a++)
#pragma unroll
        for(int b=0;b<8;b++)
#pragma unroll
            for(int c=0;c<4;c++) acc[a][b][c]=0.f;

    // stage loader
    auto load_stage = [&](int kt){
        uint32_t sb = su + (kt&1)*STAGEB;
#pragma unroll
        for(int i=0;i<8;i++){
            int c = tid + i*256;
            int tile=c>>9, w=c&511, row=w>>2, q=w&3;
            uint32_t d = sb + tile*TILEB + row*PITCH + q*16;
            const bf16* src;
            if(tile<2){
                int rg=by*128+row; if(rg>=M) rg=M-1;
                int asrc = tok ? tok[rg] : rg;
                src = (tile==0?Ah:Al) + (size_t)asrc*K + kt*32 + q*8;
            } else {
                int ng=bx*128+row;
                src = (tile==2?Bh:Bl) + (size_t)ng*K + kt*32 + q*8;
            }
            cp16(d, src);
        }
        asm volatile("cp.async.commit_group;" ::: "memory");
    };

    load_stage(0);
    for(int kt=0; kt<KT; kt++){
        if(kt+1<KT){
            load_stage(kt+1);
            asm volatile("cp.async.wait_group 1;" ::: "memory");
        } else {
            asm volatile("cp.async.wait_group 0;" ::: "memory");
        }
        __syncthreads();
        uint32_t sb = su + (kt&1)*STAGEB;
#pragma unroll
        for(int kh=0; kh<2; kh++){
            uint32_t aH[2][4], aL[2][4];
            int arow = wm*32 + (lane&15);
            uint32_t ako = kh*32 + (lane>>4)*16;
#pragma unroll
            for(int mt=0;mt<2;mt++){
                uint32_t ad = sb + (arow+mt*16)*PITCH + ako;
                ldsm4(ad, aH[mt]);
                ldsm4(ad + TILEB, aL[mt]);
            }
            uint32_t bHf[4][4], bLf[4][4];
            int brow = wn*64 + ((lane&7) | ((lane&16)>>1));
            uint32_t bko = kh*32 + ((lane>>3)&1)*16;
#pragma unroll
            for(int nt=0;nt<4;nt++){
                uint32_t bd = sb + 2*TILEB + (brow+nt*16)*PITCH + bko;
                ldsm4(bd, bHf[nt]);
                ldsm4(bd + TILEB, bLf[nt]);
            }
#pragma unroll
            for(int mt=0;mt<2;mt++)
#pragma unroll
            for(int n8=0;n8<8;n8++){
                uint32_t* bh = &bHf[n8>>1][(n8&1)*2];
                uint32_t* bl = &bLf[n8>>1][(n8&1)*2];
                mma16816(acc[mt][n8], aH[mt], bh);
                mma16816(acc[mt][n8], aH[mt], bl);
                mma16816(acc[mt][n8], aL[mt], bh);
            }
        }
        __syncthreads();
    }

    // epilogue: frag (mt,n8): rows by*128+wm*32+mt*16+g(+8), cols bx*128+wn*64+n8*8+t4*2
    int g = lane>>2, t4 = lane&3;
#pragma unroll
    for(int mt=0;mt<2;mt++)
#pragma unroll
    for(int n8=0;n8<8;n8++){
        int col = bx*128 + wn*64 + n8*8 + t4*2;
#pragma unroll
        for(int hf=0; hf<2; hf++){
            int row = by*128 + wm*32 + mt*16 + g + hf*8;
            if(row >= M) continue;
            float v0 = acc[mt][n8][hf*2+0];
            float v1 = acc[mt][n8][hf*2+1];
            if(EPI==0){
                int which = col/CCH, rem = col - which*CCH;
                int h = rem>>6, d0 = rem&63;
                int b = row>>10, t = row&1023;
                float* dst = (which==0? g_q : which==1? g_k : g_v)
                           + (((size_t)(b*HH+h)*TT + t)*HSZ + d0);
                *reinterpret_cast<float2*>(dst) = make_float2(v0, v1);
            } else if(EPI==1){
                size_t o=(size_t)row*Nn+col;
                out32[o]   = v0 + bias[col]   + resid[o];
                out32[o+1] = v1 + bias[col+1] + resid[o+1];
            } else if(EPI==2){
                size_t o=(size_t)row*Nn+col;
                float u0 = geluf(v0 + bias[col]);
                float u1 = geluf(v1 + bias[col+1]);
                bf16 h0=__float2bfloat16(u0), h1=__float2bfloat16(u1);
                __nv_bfloat162 hp; hp.x=h0; hp.y=h1;
                __nv_bfloat162 lp;
                lp.x=__float2bfloat16(u0-__bfloat162float(h0));
                lp.y=__float2bfloat16(u1-__bfloat162float(h1));
                *reinterpret_cast<__nv_bfloat162*>(&outH[o]) = hp;
                *reinterpret_cast<__nv_bfloat162*>(&outL[o]) = lp;
            } else {
                size_t o=(size_t)row*Nn+col;
                out32[o]   = v0 + bias[col];
                out32[o+1] = v1 + bias[col+1];
            }
        }
    }
}

// ---- attention fp32 ----
__global__ void k_scores(){
    int sb=blockIdx.x, tb=blockIdx.y, bh=blockIdx.z;
    if(sb>tb) return;
    __shared__ float Qs[64][65], Ks[64][65];
    const float* Q = g_q + (size_t)bh*TT*HSZ + (size_t)tb*64*HSZ;
    const float* K = g_k + (size_t)bh*TT*HSZ + (size_t)sb*64*HSZ;
    int tid=threadIdx.x;
#pragma unroll
    for(int i=0;i<4;i++){
        int idx=tid+i*256, r=idx>>4, d4=(idx&15)*4;
        float4 qv=*(const float4*)(Q+r*HSZ+d4);
        Qs[d4][r]=qv.x; Qs[d4+1][r]=qv.y; Qs[d4+2][r]=qv.z; Qs[d4+3][r]=qv.w;
        float4 kv=*(const float4*)(K+r*HSZ+d4);
        Ks[d4][r]=kv.x; Ks[d4+1][r]=kv.y; Ks[d4+2][r]=kv.z; Ks[d4+3][r]=kv.w;
    }
    __syncthreads();
    int ty=tid>>4, tx=tid&15;
    float acc[4][4]={};
#pragma unroll
    for(int k=0;k<64;k++){
        float a[4],bb[4];
#pragma unroll
        for(int i=0;i<4;i++) a[i]=Qs[k][ty*4+i];
#pragma unroll
        for(int j=0;j<4;j++) bb[j]=Ks[k][tx*4+j];
#pragma unroll
        for(int i=0;i<4;i++)
#pragma unroll
            for(int j=0;j<4;j++) acc[i][j]+=a[i]*bb[j];
    }
    const float scale=0.036084391824351615f;
    float* S = g_S + (size_t)bh*TT*TT;
#pragma unroll
    for(int i=0;i<4;i++){
        int tg=tb*64+ty*4+i;
#pragma unroll
        for(int j=0;j<4;j++){
            int sg=sb*64+tx*4+j;
            S[(size_t)tg*TT+sg] = (sg<=tg)? acc[i][j]*scale : -1e30f;
        }
    }
}
__global__ void k_softmax(){
    int row=blockIdx.x, bh=row>>10, t=row&(TT-1);
    float* S = g_S + (size_t)bh*TT*TT + (size_t)t*TT;
    int len=t+1, tid=threadIdx.x;
    __shared__ float sh[8];
    float m=-1e30f;
    for(int s=tid;s<len;s+=256) m=fmaxf(m,S[s]);
#pragma unroll
    for(int o=16;o;o>>=1) m=fmaxf(m,__shfl_xor_sync(~0u,m,o));
    if((tid&31)==0) sh[tid>>5]=m;
    __syncthreads();
    m=sh[0];
#pragma unroll
    for(int i=1;i<8;i++) m=fmaxf(m,sh[i]);
    __syncthreads();
    float sum=0.f;
    for(int s=tid;s<len;s+=256){ float e=expf(S[s]-m); S[s]=e; sum+=e; }
#pragma unroll
    for(int o=16;o;o>>=1) sum+=__shfl_xor_sync(~0u,sum,o);
    if((tid&31)==0) sh[tid>>5]=sum;
    __syncthreads();
    sum=0.f;
#pragma unroll
    for(int i=0;i<8;i++) sum+=sh[i];
    float inv=1.f/sum;
    for(int s=tid;s<TT;s+=256) S[s]=(s<len)? S[s]*inv : 0.f;
}
__global__ void k_av(){
    int tb=blockIdx.x, bh=blockIdx.y;
    const float* P = g_S + (size_t)bh*TT*TT;
    const float* V = g_v + (size_t)bh*TT*HSZ;
    __shared__ float As[16][68], Bs[16][64];
    int tid=threadIdx.x, ty=tid>>4, tx=tid&15;
    int arow=tid>>2, akq=(tid&3)*4;
    int brow=tid>>4, bd=(tid&15)*4;
    int kmax=(tb+1)*64;
    float acc[4][4]={};
    for(int k0=0;k0<kmax;k0+=16){
        float4 av=*(const float4*)(P+(size_t)(tb*64+arow)*TT+k0+akq);
        As[akq][arow]=av.x; As[akq+1][arow]=av.y; As[akq+2][arow]=av.z; As[akq+3][arow]=av.w;
        *(float4*)&Bs[brow][bd]=*(const float4*)(V+(size_t)(k0+brow)*HSZ+bd);
        __syncthreads();
#pragma unroll
        for(int kk=0;kk<16;kk++){
            float a[4],bb[4];
#pragma unroll
            for(int i=0;i<4;i++) a[i]=As[kk][ty*4+i];
#pragma unroll
            for(int j=0;j<4;j++) bb[j]=Bs[kk][tx*4+j];
#pragma unroll
            for(int i=0;i<4;i++)
#pragma unroll
                for(int j=0;j<4;j++) acc[i][j]+=a[i]*bb[j];
        }
        __syncthreads();
    }
    int b=bh/HH, h=bh%HH;
#pragma unroll
    for(int i=0;i<4;i++)
#pragma unroll
        for(int j=0;j<4;j++){
            size_t o=((size_t)b*TT+tb*64+ty*4+i)*CCH + h*HSZ + tx*4+j;
            float v=acc[i][j];
            bf16 hi=__float2bfloat16(v);
            g_aoh[o]=hi; g_aol[o]=__float2bfloat16(v-__bfloat162float(hi));
        }
}

__global__ void k_router(const float* __restrict__ wr, const float* __restrict__ br,
                         const float* __restrict__ wn, const float* __restrict__ bnn,
                         const float* __restrict__ temp, const float* __restrict__ noise){
    int warp=threadIdx.x>>5, lane=threadIdx.x&31;
    int n=blockIdx.x*8+warp;
    const float* hp = g_h2 + (size_t)n*CCH;
    float r[8]={}, q[8]={};
    for(int c=lane;c<CCH;c+=32){
        float hv=hp[c];
        const float* wrp=wr+c*EE; const float* wnp=wn+c*EE;
#pragma unroll
        for(int e=0;e<8;e++){ r[e]+=hv*wrp[e]; q[e]+=hv*wnp[e]; }
    }
#pragma unroll
    for(int e=0;e<8;e++)
#pragma unroll
        for(int o=16;o;o>>=1){
            r[e]+=__shfl_xor_sync(~0u,r[e],o);
            q[e]+=__shfl_xor_sync(~0u,q[e],o);
        }
    if(lane==0){
        float t=fminf(fmaxf(temp[0],0.5f),2.0f);
        float ny[8];
#pragma unroll
        for(int e=0;e<8;e++){
            float z=q[e]+bnn[e];
            float sp=(z>20.f)? z : log1pf(expf(z));
            ny[e]=r[e]+br[e] + t*noise[(size_t)n*EE+e]*sp;
        }
        int i1=0;
#pragma unroll
        for(int e=1;e<8;e++) if(ny[e]>ny[i1]) i1=e;
        int i2=-1;
#pragma unroll
        for(int e=0;e<8;e++){ if(e==i1) continue; if(i2<0||ny[e]>ny[i2]) i2=e; }
        float e2=expf(ny[i2]-ny[i1]);
        float gv[2]={1.f/(1.f+e2), e2/(1.f+e2)};
        int id[2]={i1,i2};
#pragma unroll
        for(int k2=0;k2<2;k2++){
            int e=id[k2];
            int row=atomicAdd(&g_cnt[e],1);
            g_tok[e*NT+row]=n;
            g_pos[n*2+k2]=e*NT+row;
            g_gw[n*2+k2]=gv[k2];
        }
    }
}

__global__ void k_resln(const float* __restrict__ t3, int e,
                        const float* __restrict__ gam, const float* __restrict__ bet){
    int r=blockIdx.x;
    if(r>=g_cnt[e]) return;
    int n=g_tok[e*NT+r], t=threadIdx.x;
    float v[3], s=0.f, s2=0.f;
#pragma unroll
    for(int i=0;i<3;i++){
        int c=t+256*i;
        v[i]=g_h2[(size_t)n*CCH+c]+t3[(size_t)r*CCH+c];
        s+=v[i]; s2+=v[i]*v[i];
    }
    __shared__ float shs[8], shq[8];
#pragma unroll
    for(int o=16;o;o>>=1){ s+=__shfl_xor_sync(~0u,s,o); s2+=__shfl_xor_sync(~0u,s2,o); }
    if((t&31)==0){ shs[t>>5]=s; shq[t>>5]=s2; }
    __syncthreads();
    s=0.f; s2=0.f;
#pragma unroll
    for(int i=0;i<8;i++){ s+=shs[i]; s2+=shq[i]; }
    float mean=s*(1.f/768.f), var=s2*(1.f/768.f)-mean*mean, rs=rsqrtf(var+1e-5f);
    float* ob = g_ob + (size_t)(e*NT+r)*CCH;
#pragma unroll
    for(int i=0;i<3;i++){ int c=t+256*i; ob[c]=(v[i]-mean)*rs*gam[c]+bet[c]; }
}

__global__ void k_combine(float* __restrict__ out){
    int n=blockIdx.x, t=threadIdx.x;
    float g0=g_gw[n*2], g1=g_gw[n*2+1];
    const float* o0 = g_ob + (size_t)g_pos[n*2]*CCH;
    const float* o1 = g_ob + (size_t)g_pos[n*2+1]*CCH;
#pragma unroll
    for(int i=0;i<3;i++){
        int c=t+256*i;
        out[(size_t)n*CCH+c]=g_x2[(size_t)n*CCH+c]+g0*o0[c]+g1*o1[c];
    }
}

extern "C" void kernel_launch(void* const* d_in, const int* in_sizes, int n_in,
                              void* d_out, int out_size){
    const float *x=(const float*)d_in[0], *rno=(const float*)d_in[1];
    const float *wq=(const float*)d_in[2], *wk=(const float*)d_in[3], *wv=(const float*)d_in[4];
    const float *w_proj=(const float*)d_in[5], *b_proj=(const float*)d_in[6];
    const float *ln1g=(const float*)d_in[7], *ln1b=(const float*)d_in[8];
    const float *ln2g=(const float*)d_in[9], *ln2b=(const float*)d_in[10];
    const float *wr=(const float*)d_in[11], *br=(const float*)d_in[12];
    const float *wn=(const float*)d_in[13], *bn=(const float*)d_in[14];
    const float *temp=(const float*)d_in[15];
    const float *dw1=(const float*)d_in[16], *db1=(const float*)d_in[17];
    const float *dw2=(const float*)d_in[18], *db2=(const float*)d_in[19];
    const float *dw3=(const float*)d_in[20], *db3=(const float*)d_in[21];
    const float *dlng=(const float*)d_in[22], *dlnb=(const float*)d_in[23];
    const float *sw1=(const float*)d_in[24], *sb1=(const float*)d_in[25];
    const float *sw2=(const float*)d_in[26], *sb2=(const float*)d_in[27];
    const float *slng=(const float*)d_in[28], *slnb=(const float*)d_in[29];
    float* out=(float*)d_out;

    cudaFuncSetAttribute(k_mma<0>, cudaFuncAttributeMaxDynamicSharedMemorySize, SMEMSZ);
    cudaFuncSetAttribute(k_mma<1>, cudaFuncAttributeMaxDynamicSharedMemorySize, SMEMSZ);
    cudaFuncSetAttribute(k_mma<2>, cudaFuncAttributeMaxDynamicSharedMemorySize, SMEMSZ);
    cudaFuncSetAttribute(k_mma<3>, cudaFuncAttributeMaxDynamicSharedMemorySize, SMEMSZ);

    bf16 *Bqh,*Bql,*Bph,*Bpl,*Bd1h,*Bd1l,*Bd2h,*Bd2l,*Bd3h,*Bd3l,*Bs1h,*Bs1l,*Bs2h,*Bs2l;
    bf16 *h1h,*h1l,*aoh,*aol,*h2h,*h2l,*t1h,*t1l,*t2h,*t2l;
    float *x2,*h2,*t3; int *tok,*cnt;
    cudaGetSymbolAddress((void**)&Bqh,g_Bqh); cudaGetSymbolAddress((void**)&Bql,g_Bql);
    cudaGetSymbolAddress((void**)&Bph,g_Bph); cudaGetSymbolAddress((void**)&Bpl,g_Bpl);
    cudaGetSymbolAddress((void**)&Bd1h,g_Bd1h); cudaGetSymbolAddress((void**)&Bd1l,g_Bd1l);
    cudaGetSymbolAddress((void**)&Bd2h,g_Bd2h); cudaGetSymbolAddress((void**)&Bd2l,g_Bd2l);
    cudaGetSymbolAddress((void**)&Bd3h,g_Bd3h); cudaGetSymbolAddress((void**)&Bd3l,g_Bd3l);
    cudaGetSymbolAddress((void**)&Bs1h,g_Bs1h); cudaGetSymbolAddress((void**)&Bs1l,g_Bs1l);
    cudaGetSymbolAddress((void**)&Bs2h,g_Bs2h); cudaGetSymbolAddress((void**)&Bs2l,g_Bs2l);
    cudaGetSymbolAddress((void**)&h1h,g_h1h); cudaGetSymbolAddress((void**)&h1l,g_h1l);
    cudaGetSymbolAddress((void**)&aoh,g_aoh); cudaGetSymbolAddress((void**)&aol,g_aol);
    cudaGetSymbolAddress((void**)&h2h,g_h2h); cudaGetSymbolAddress((void**)&h2l,g_h2l);
    cudaGetSymbolAddress((void**)&t1h,g_t1h); cudaGetSymbolAddress((void**)&t1l,g_t1l);
    cudaGetSymbolAddress((void**)&t2h,g_t2h); cudaGetSymbolAddress((void**)&t2l,g_t2l);
    cudaGetSymbolAddress((void**)&x2,g_x2); cudaGetSymbolAddress((void**)&h2,g_h2);
    cudaGetSymbolAddress((void**)&t3,g_t3);
    cudaGetSymbolAddress((void**)&tok,g_tok); cudaGetSymbolAddress((void**)&cnt,g_cnt);

    dim3 wb(32,8);
    k_reset<<<1,32>>>();
    k_wsplit<<<dim3(2,24,12),wb>>>(wq, Bqh,           Bql,           CCH, HSZ);
    k_wsplit<<<dim3(2,24,12),wb>>>(wk, Bqh+CCH*CCH,   Bql+CCH*CCH,   CCH, HSZ);
    k_wsplit<<<dim3(2,24,12),wb>>>(wv, Bqh+2*CCH*CCH, Bql+2*CCH*CCH, CCH, HSZ);
    k_wsplit<<<dim3(24,24,1),wb>>>(w_proj, Bph, Bpl, CCH, CCH);
    k_wsplit<<<dim3(96,24,2),wb>>>(dw1, Bd1h, Bd1l, CCH, FF);
    k_wsplit<<<dim3(96,96,2),wb>>>(dw2, Bd2h, Bd2l, FF, FF);
    k_wsplit<<<dim3(24,96,2),wb>>>(dw3, Bd3h, Bd3l, FF, CCH);
    k_wsplit<<<dim3(96,24,6),wb>>>(sw1, Bs1h, Bs1l, CCH, FF);
    k_wsplit<<<dim3(24,96,6),wb>>>(sw2, Bs2h, Bs2l, FF, CCH);
    // attention
    k_ln<<<NT,256>>>(x, ln1g, ln1b, nullptr, h1h, h1l);
    k_mma<0><<<dim3(18,64),256,SMEMSZ>>>(h1h,h1l,Bqh,Bql,nullptr,nullptr,nullptr,nullptr,nullptr,
                                         NT,3*CCH,CCH,nullptr,nullptr);
    k_scores<<<dim3(16,16,BH),256>>>();
    k_softmax<<<BH*TT,256>>>();
    k_av<<<dim3(16,BH),256>>>();
    k_mma<1><<<dim3(6,64),256,SMEMSZ>>>(aoh,aol,Bph,Bpl,b_proj,x,x2,nullptr,nullptr,
                                        NT,CCH,CCH,nullptr,nullptr);
    // router
    k_ln<<<NT,256>>>(x2, ln2g, ln2b, h2, h2h, h2l);
    k_router<<<NT/8,256>>>(wr,br,wn,bn,temp,rno);
    // deep experts
    for(int e=0;e<2;e++){
        k_mma<2><<<dim3(24,64),256,SMEMSZ>>>(h2h,h2l,Bd1h+(size_t)e*CCH*FF,Bd1l+(size_t)e*CCH*FF,
            db1+e*FF,nullptr,nullptr,t1h,t1l, NT,FF,CCH, tok+e*NT, cnt+e);
        k_mma<2><<<dim3(24,64),256,SMEMSZ>>>(t1h,t1l,Bd2h+(size_t)e*FF*FF,Bd2l+(size_t)e*FF*FF,
            db2+e*FF,nullptr,nullptr,t2h,t2l, NT,FF,FF, nullptr, cnt+e);
        k_mma<3><<<dim3(6,64),256,SMEMSZ>>>(t2h,t2l,Bd3h+(size_t)e*CCH*FF,Bd3l+(size_t)e*CCH*FF,
            db3+e*CCH,nullptr,t3,nullptr,nullptr, NT,CCH,FF, nullptr, cnt+e);
        k_resln<<<NT,256>>>(t3, e, dlng+e*CCH, dlnb+e*CCH);
    }
    // simple experts
    for(int e=0;e<6;e++){
        int ge=2+e;
        k_mma<2><<<dim3(24,64),256,SMEMSZ>>>(h2h,h2l,Bs1h+(size_t)e*CCH*FF,Bs1l+(size_t)e*CCH*FF,
            sb1+e*FF,nullptr,nullptr,t1h,t1l, NT,FF,CCH, tok+ge*NT, cnt+ge);
        k_mma<3><<<dim3(6,64),256,SMEMSZ>>>(t1h,t1l,Bs2h+(size_t)e*CCH*FF,Bs2l+(size_t)e*CCH*FF,
            sb2+e*CCH,nullptr,t3,nullptr,nullptr, NT,CCH,FF, nullptr, cnt+ge);
        k_resln<<<NT,256>>>(t3, ge, slng+e*CCH, slnb+e*CCH);
    }
    k_combine<<<NT,256>>>(out);
}

// round 5
// speedup vs baseline: 3.0084x; 1.1134x over previous
#include <cuda_runtime.h>
#include <cuda_bf16.h>
#include <stdint.h>
#include <math.h>

#define BN 8
#define TT 1024
#define CCH 768
#define HH 12
#define HSZ 64
#define EE 8
#define FF 3072
#define NT (BN*TT)
#define BH (BN*HH)
typedef __nv_bfloat16 bf16;

// ---- static scratch ----
__device__ bf16  g_qh[BH*TT*HSZ], g_ql[BH*TT*HSZ];
__device__ bf16  g_kh[BH*TT*HSZ], g_kl[BH*TT*HSZ];
__device__ bf16  g_vh[BH*TT*HSZ], g_vl[BH*TT*HSZ];
__device__ bf16  g_h1h[NT*CCH], g_h1l[NT*CCH];
__device__ bf16  g_aoh[NT*CCH], g_aol[NT*CCH];
__device__ float g_x2[NT*CCH];
__device__ float g_h2[NT*CCH];
__device__ bf16  g_h2h[NT*CCH], g_h2l[NT*CCH];
__device__ float g_gw[NT*2];
__device__ int   g_pos[NT*2];
__device__ int   g_tok[EE*NT];
__device__ int   g_cnt[EE];
__device__ bf16  g_t1h[NT*FF], g_t1l[NT*FF];
__device__ bf16  g_t2h[NT*FF], g_t2l[NT*FF];
__device__ float g_t3[NT*CCH];
__device__ float g_ob[(size_t)EE*NT*CCH];
__device__ bf16  g_Bqh[3*CCH*CCH], g_Bql[3*CCH*CCH];
__device__ bf16  g_Bph[CCH*CCH],  g_Bpl[CCH*CCH];
__device__ bf16  g_Bd1h[2*CCH*FF], g_Bd1l[2*CCH*FF];
__device__ bf16  g_Bd2h[(size_t)2*FF*FF], g_Bd2l[(size_t)2*FF*FF];
__device__ bf16  g_Bd3h[2*CCH*FF], g_Bd3l[2*CCH*FF];
__device__ bf16  g_Bs1h[(size_t)6*CCH*FF], g_Bs1l[(size_t)6*CCH*FF];
__device__ bf16  g_Bs2h[(size_t)6*CCH*FF], g_Bs2l[(size_t)6*CCH*FF];

__device__ __forceinline__ float geluf(float v){
    return 0.5f*v*(1.f + erff(v*0.70710678118654752440f));
}
__device__ __forceinline__ uint32_t smem_u32(const void* p){
    uint32_t a;
    asm("{ .reg .u64 t; cvta.to.shared.u64 t, %1; cvt.u32.u64 %0, t; }" : "=r"(a) : "l"(p));
    return a;
}
__device__ __forceinline__ void cp16(uint32_t d, const void* s){
    asm volatile("cp.async.cg.shared.global [%0], [%1], 16;" :: "r"(d), "l"(s));
}
__device__ __forceinline__ void ldsm4(uint32_t a, uint32_t* r){
    asm volatile("ldmatrix.sync.aligned.m8n8.x4.shared.b16 {%0,%1,%2,%3}, [%4];"
        : "=r"(r[0]),"=r"(r[1]),"=r"(r[2]),"=r"(r[3]) : "r"(a));
}
__device__ __forceinline__ void mma16816(float* c, const uint32_t* a, const uint32_t* b){
    asm volatile("mma.sync.aligned.m16n8k16.row.col.f32.bf16.bf16.f32 "
        "{%0,%1,%2,%3},{%4,%5,%6,%7},{%8,%9},{%0,%1,%2,%3};"
        : "+f"(c[0]),"+f"(c[1]),"+f"(c[2]),"+f"(c[3])
        : "r"(a[0]),"r"(a[1]),"r"(a[2]),"r"(a[3]), "r"(b[0]),"r"(b[1]));
}
__device__ __forceinline__ uint32_t packbf(float a, float b){
    __nv_bfloat162 p; p.x=__float2bfloat16(a); p.y=__float2bfloat16(b);
    return *reinterpret_cast<uint32_t*>(&p);
}

__global__ void k_reset(){ if(threadIdx.x < EE) g_cnt[threadIdx.x] = 0; }

// W[K][N] -> out[N][K] hi/lo bf16
__global__ void k_wsplit(const float* __restrict__ W, bf16* __restrict__ oh,
                         bf16* __restrict__ ol, int K, int N){
    int e = blockIdx.z;
    W += (size_t)e*K*N; oh += (size_t)e*K*N; ol += (size_t)e*K*N;
    __shared__ float s[32][33];
    int n0 = blockIdx.x*32, k0 = blockIdx.y*32;
    int tx = threadIdx.x, ty = threadIdx.y;
#pragma unroll
    for(int r=0;r<4;r++){ int kk=ty+r*8; s[kk][tx] = W[(size_t)(k0+kk)*N + n0+tx]; }
    __syncthreads();
#pragma unroll
    for(int r=0;r<4;r++){
        int kk = ty+r*8;
        float v = s[tx][kk];
        bf16 hi = __float2bfloat16(v);
        size_t o = (size_t)(n0+kk)*K + k0+tx;
        oh[o]=hi; ol[o]=__float2bfloat16(v - __bfloat162float(hi));
    }
}

__global__ void k_ln(const float* __restrict__ in, const float* __restrict__ gam,
                     const float* __restrict__ bet, float* __restrict__ out,
                     bf16* __restrict__ oh, bf16* __restrict__ ol){
    int n = blockIdx.x, t = threadIdx.x;
    const float* row = in + (size_t)n*CCH;
    float v[3], s=0.f, s2=0.f;
#pragma unroll
    for(int i=0;i<3;i++){ v[i]=row[t+256*i]; s+=v[i]; s2+=v[i]*v[i]; }
    __shared__ float shs[8], shq[8];
#pragma unroll
    for(int o=16;o;o>>=1){ s+=__shfl_xor_sync(~0u,s,o); s2+=__shfl_xor_sync(~0u,s2,o); }
    if((t&31)==0){ shs[t>>5]=s; shq[t>>5]=s2; }
    __syncthreads();
    s=0.f; s2=0.f;
#pragma unroll
    for(int i=0;i<8;i++){ s+=shs[i]; s2+=shq[i]; }
    float mean=s*(1.f/768.f), var=s2*(1.f/768.f)-mean*mean, r=rsqrtf(var+1e-5f);
#pragma unroll
    for(int i=0;i<3;i++){
        int c=t+256*i;
        float o=(v[i]-mean)*r*gam[c]+bet[c];
        if(out) out[(size_t)n*CCH+c]=o;
        if(oh){
            bf16 hi=__float2bfloat16(o);
            oh[(size_t)n*CCH+c]=hi;
            ol[(size_t)n*CCH+c]=__float2bfloat16(o-__bfloat162float(hi));
        }
    }
}

// ---- mma.sync split-bf16 GEMM (as round 4) ----
#define PITCH 80
#define TILEB 10240
#define STAGEB 40960
#define SMEMSZ (2*STAGEB)
template<int EPI>
__global__ void __launch_bounds__(256,1)
k_mma(const bf16* __restrict__ Ah, const bf16* __restrict__ Al,
      const bf16* __restrict__ Bh, const bf16* __restrict__ Bl,
      const float* __restrict__ bias, const float* __restrict__ resid,
      float* __restrict__ out32, bf16* __restrict__ outH, bf16* __restrict__ outL,
      int M, int Nn, int K, const int* __restrict__ tok, const int* __restrict__ cnt){
    if(cnt) M = *cnt;
    int by = blockIdx.y, bx = blockIdx.x;
    if(by*128 >= M) return;
    extern __shared__ char smem[];
    uint32_t su = smem_u32(smem);
    int tid=threadIdx.x, lane=tid&31, wid=tid>>5;
    int wm=wid&3, wn=wid>>2;
    const int KT = K/32;
    float acc[2][8][4];
#pragma unroll
    for(int a=0;a<2;a++)
#pragma unroll
        for(int b=0;b<8;b++)
#pragma unroll
            for(int c=0;c<4;c++) acc[a][b][c]=0.f;
    auto load_stage = [&](int kt){
        uint32_t sb = su + (kt&1)*STAGEB;
#pragma unroll
        for(int i=0;i<8;i++){
            int c = tid + i*256;
            int tile=c>>9, w=c&511, row=w>>2, q=w&3;
            uint32_t d = sb + tile*TILEB + row*PITCH + q*16;
            const bf16* src;
            if(tile<2){
                int rg=by*128+row; if(rg>=M) rg=M-1;
                int asrc = tok ? tok[rg] : rg;
                src = (tile==0?Ah:Al) + (size_t)asrc*K + kt*32 + q*8;
            } else {
                int ng=bx*128+row;
                src = (tile==2?Bh:Bl) + (size_t)ng*K + kt*32 + q*8;
            }
            cp16(d, src);
        }
        asm volatile("cp.async.commit_group;" ::: "memory");
    };
    load_stage(0);
    for(int kt=0; kt<KT; kt++){
        if(kt+1<KT){
            load_stage(kt+1);
            asm volatile("cp.async.wait_group 1;" ::: "memory");
        } else {
            asm volatile("cp.async.wait_group 0;" ::: "memory");
        }
        __syncthreads();
        uint32_t sb = su + (kt&1)*STAGEB;
#pragma unroll
        for(int kh=0; kh<2; kh++){
            uint32_t aH[2][4], aL[2][4];
            int arow = wm*32 + (lane&15);
            uint32_t ako = kh*32 + (lane>>4)*16;
#pragma unroll
            for(int mt=0;mt<2;mt++){
                uint32_t ad = sb + (arow+mt*16)*PITCH + ako;
                ldsm4(ad, aH[mt]);
                ldsm4(ad + TILEB, aL[mt]);
            }
            uint32_t bHf[4][4], bLf[4][4];
            int brow = wn*64 + ((lane&7) | ((lane&16)>>1));
            uint32_t bko = kh*32 + ((lane>>3)&1)*16;
#pragma unroll
            for(int nt=0;nt<4;nt++){
                uint32_t bd = sb + 2*TILEB + (brow+nt*16)*PITCH + bko;
                ldsm4(bd, bHf[nt]);
                ldsm4(bd + TILEB, bLf[nt]);
            }
#pragma unroll
            for(int mt=0;mt<2;mt++)
#pragma unroll
            for(int n8=0;n8<8;n8++){
                uint32_t* bh = &bHf[n8>>1][(n8&1)*2];
                uint32_t* bl = &bLf[n8>>1][(n8&1)*2];
                mma16816(acc[mt][n8], aH[mt], bh);
                mma16816(acc[mt][n8], aH[mt], bl);
                mma16816(acc[mt][n8], aL[mt], bh);
            }
        }
        __syncthreads();
    }
    int g = lane>>2, t4 = lane&3;
#pragma unroll
    for(int mt=0;mt<2;mt++)
#pragma unroll
    for(int n8=0;n8<8;n8++){
        int col = bx*128 + wn*64 + n8*8 + t4*2;
#pragma unroll
        for(int hf=0; hf<2; hf++){
            int row = by*128 + wm*32 + mt*16 + g + hf*8;
            if(row >= M) continue;
            float v0 = acc[mt][n8][hf*2+0];
            float v1 = acc[mt][n8][hf*2+1];
            if(EPI==0){
                int which = col/CCH, rem = col - which*CCH;
                int h = rem>>6, d0 = rem&63;
                int b = row>>10, t = row&1023;
                size_t o = ((size_t)(b*HH+h)*TT + t)*HSZ + d0;
                bf16* dh = which==0? g_qh : which==1? g_kh : g_vh;
                bf16* dl = which==0? g_ql : which==1? g_kl : g_vl;
                bf16 h0=__float2bfloat16(v0), h1=__float2bfloat16(v1);
                __nv_bfloat162 hp; hp.x=h0; hp.y=h1;
                __nv_bfloat162 lp;
                lp.x=__float2bfloat16(v0-__bfloat162float(h0));
                lp.y=__float2bfloat16(v1-__bfloat162float(h1));
                *reinterpret_cast<__nv_bfloat162*>(&dh[o]) = hp;
                *reinterpret_cast<__nv_bfloat162*>(&dl[o]) = lp;
            } else if(EPI==1){
                size_t o=(size_t)row*Nn+col;
                out32[o]   = v0 + bias[col]   + resid[o];
                out32[o+1] = v1 + bias[col+1] + resid[o+1];
            } else if(EPI==2){
                size_t o=(size_t)row*Nn+col;
                float u0 = geluf(v0 + bias[col]);
                float u1 = geluf(v1 + bias[col+1]);
                bf16 h0=__float2bfloat16(u0), h1=__float2bfloat16(u1);
                __nv_bfloat162 hp; hp.x=h0; hp.y=h1;
                __nv_bfloat162 lp;
                lp.x=__float2bfloat16(u0-__bfloat162float(h0));
                lp.y=__float2bfloat16(u1-__bfloat162float(h1));
                *reinterpret_cast<__nv_bfloat162*>(&outH[o]) = hp;
                *reinterpret_cast<__nv_bfloat162*>(&outL[o]) = lp;
            } else {
                size_t o=(size_t)row*Nn+col;
                out32[o]   = v0 + bias[col];
                out32[o+1] = v1 + bias[col+1];
            }
        }
    }
}

// ---- flash attention, split-bf16 mma, online softmax ----
#define FP 72
#define FT (64*FP*2)     // 9216 B per tile
#define FSM (6*FT)       // 55296 B
__global__ void __launch_bounds__(128,1) k_flash(){
    int tb = blockIdx.x, bh = blockIdx.y;
    extern __shared__ char fsm[];
    uint32_t su = smem_u32(fsm);
    bf16* Qh = (bf16*)fsm;            // +0
    // offsets: Qh 0, Ql FT, Kh 2FT, Kl 3FT, Vth 4FT, Vtl 5FT
    int tid=threadIdx.x, lane=tid&31, w=tid>>5;
    const size_t hb = (size_t)bh*TT*HSZ;
    // load Q tile (rows tb*64..+63)
    for(int i=tid;i<2048;i+=128){
        int r=i>>5, c2=i&31;
        size_t go = hb + (size_t)(tb*64+r)*HSZ + c2*2;
        *(__nv_bfloat162*)((char*)fsm + 0*FT + (r*FP+c2*2)*2) = *(const __nv_bfloat162*)&g_qh[go];
        *(__nv_bfloat162*)((char*)fsm + 1*FT + (r*FP+c2*2)*2) = *(const __nv_bfloat162*)&g_ql[go];
    }
    float m0=-1e30f, m1=-1e30f, l0=0.f, l1=0.f;
    float O[8][4];
#pragma unroll
    for(int n8=0;n8<8;n8++)
#pragma unroll
        for(int c=0;c<4;c++) O[n8][c]=0.f;
    const float scale=0.036084391824351615f;
    int brow = (lane&7) | ((lane&16)>>1);
    int t4 = lane&3, g = lane>>2;
    for(int sb=0; sb<=tb; sb++){
        __syncthreads();
        // load K tile + V tile (transposed)
        for(int i=tid;i<2048;i+=128){
            int r=i>>5, c2=i&31;
            size_t go = hb + (size_t)(sb*64+r)*HSZ + c2*2;
            *(__nv_bfloat162*)((char*)fsm + 2*FT + (r*FP+c2*2)*2) = *(const __nv_bfloat162*)&g_kh[go];
            *(__nv_bfloat162*)((char*)fsm + 3*FT + (r*FP+c2*2)*2) = *(const __nv_bfloat162*)&g_kl[go];
            __nv_bfloat162 vh = *(const __nv_bfloat162*)&g_vh[go];
            __nv_bfloat162 vl = *(const __nv_bfloat162*)&g_vl[go];
            bf16* Vth = (bf16*)((char*)fsm + 4*FT);
            bf16* Vtl = (bf16*)((char*)fsm + 5*FT);
            Vth[(c2*2  )*FP + r] = vh.x;
            Vth[(c2*2+1)*FP + r] = vh.y;
            Vtl[(c2*2  )*FP + r] = vl.x;
            Vtl[(c2*2+1)*FP + r] = vl.y;
        }
        __syncthreads();
        // S = Q K^T
        float S[8][4];
#pragma unroll
        for(int n8=0;n8<8;n8++)
#pragma unroll
            for(int c=0;c<4;c++) S[n8][c]=0.f;
#pragma unroll
        for(int kc=0;kc<4;kc++){
            uint32_t aH[4], aL[4];
            uint32_t ad = su + (w*16+(lane&15))*144 + kc*32 + (lane>>4)*16;
            ldsm4(ad, aH); ldsm4(ad+FT, aL);
            uint32_t bH[4][4], bL[4][4];
#pragma unroll
            for(int nt=0;nt<4;nt++){
                uint32_t bd = su + 2*FT + ((nt*16+brow)*144) + kc*32 + ((lane>>3)&1)*16;
                ldsm4(bd, bH[nt]); ldsm4(bd+FT, bL[nt]);
            }
#pragma unroll
            for(int n8=0;n8<8;n8++){
                uint32_t* bh2=&bH[n8>>1][(n8&1)*2];
                uint32_t* bl2=&bL[n8>>1][(n8&1)*2];
                mma16816(S[n8], aH, bh2);
                mma16816(S[n8], aH, bl2);
                mma16816(S[n8], aL, bh2);
            }
        }
        // scale + causal mask
        int rg0 = tb*64 + w*16 + g;
#pragma unroll
        for(int n8=0;n8<8;n8++)
#pragma unroll
            for(int c=0;c<4;c++){
                S[n8][c] *= scale;
                if(sb==tb){
                    int sg = sb*64 + n8*8 + t4*2 + (c&1);
                    int rg = rg0 + ((c>=2)?8:0);
                    if(sg > rg) S[n8][c] = -1e30f;
                }
            }
        // row max
        float mx0=-1e30f, mx1=-1e30f;
#pragma unroll
        for(int n8=0;n8<8;n8++){
            mx0=fmaxf(mx0,fmaxf(S[n8][0],S[n8][1]));
            mx1=fmaxf(mx1,fmaxf(S[n8][2],S[n8][3]));
        }
        mx0=fmaxf(mx0,__shfl_xor_sync(~0u,mx0,1)); mx0=fmaxf(mx0,__shfl_xor_sync(~0u,mx0,2));
        mx1=fmaxf(mx1,__shfl_xor_sync(~0u,mx1,1)); mx1=fmaxf(mx1,__shfl_xor_sync(~0u,mx1,2));
        float mn0=fmaxf(m0,mx0), mn1=fmaxf(m1,mx1);
        float f0=expf(m0-mn0), f1=expf(m1-mn1);
        m0=mn0; m1=mn1;
        float rs0=0.f, rs1=0.f;
#pragma unroll
        for(int n8=0;n8<8;n8++){
            S[n8][0]=expf(S[n8][0]-mn0); S[n8][1]=expf(S[n8][1]-mn0);
            S[n8][2]=expf(S[n8][2]-mn1); S[n8][3]=expf(S[n8][3]-mn1);
            rs0+=S[n8][0]+S[n8][1]; rs1+=S[n8][2]+S[n8][3];
        }
        rs0+=__shfl_xor_sync(~0u,rs0,1); rs0+=__shfl_xor_sync(~0u,rs0,2);
        rs1+=__shfl_xor_sync(~0u,rs1,1); rs1+=__shfl_xor_sync(~0u,rs1,2);
        l0=l0*f0+rs0; l1=l1*f1+rs1;
#pragma unroll
        for(int n8=0;n8<8;n8++){
            O[n8][0]*=f0; O[n8][1]*=f0; O[n8][2]*=f1; O[n8][3]*=f1;
        }
        // P @ V  (P hi/lo from S regs; B from Vt tiles)
#pragma unroll
        for(int j=0;j<4;j++){
            float p00=S[2*j][0], p01=S[2*j][1], p02=S[2*j][2], p03=S[2*j][3];
            float p10=S[2*j+1][0], p11=S[2*j+1][1], p12=S[2*j+1][2], p13=S[2*j+1][3];
            uint32_t aPh[4], aPl[4];
            aPh[0]=packbf(p00,p01); aPh[1]=packbf(p02,p03);
            aPh[2]=packbf(p10,p11); aPh[3]=packbf(p12,p13);
            __nv_bfloat162* hp;
            // lo residuals
            {
                __nv_bfloat162 t;
                t=*(__nv_bfloat162*)&aPh[0];
                aPl[0]=packbf(p00-__bfloat162float(t.x), p01-__bfloat162float(t.y));
                t=*(__nv_bfloat162*)&aPh[1];
                aPl[1]=packbf(p02-__bfloat162float(t.x), p03-__bfloat162float(t.y));
                t=*(__nv_bfloat162*)&aPh[2];
                aPl[2]=packbf(p10-__bfloat162float(t.x), p11-__bfloat162float(t.y));
                t=*(__nv_bfloat162*)&aPh[3];
                aPl[3]=packbf(p12-__bfloat162float(t.x), p13-__bfloat162float(t.y));
            }
            (void)hp;
            uint32_t bH[4][4], bL[4][4];
#pragma unroll
            for(int nt=0;nt<4;nt++){
                uint32_t bd = su + 4*FT + ((nt*16+brow)*144) + j*32 + ((lane>>3)&1)*16;
                ldsm4(bd, bH[nt]); ldsm4(bd+FT, bL[nt]);
            }
#pragma unroll
            for(int n8=0;n8<8;n8++){
                uint32_t* bh2=&bH[n8>>1][(n8&1)*2];
                uint32_t* bl2=&bL[n8>>1][(n8&1)*2];
                mma16816(O[n8], aPh, bh2);
                mma16816(O[n8], aPh, bl2);
                mma16816(O[n8], aPl, bh2);
            }
        }
    }
    // finalize: O /= l, write hi/lo to g_aoh/g_aol
    float i0=1.f/l0, i1=1.f/l1;
    int b = bh/HH, h = bh%HH;
#pragma unroll
    for(int n8=0;n8<8;n8++){
        int col = h*64 + n8*8 + t4*2;
#pragma unroll
        for(int hf=0;hf<2;hf++){
            int tokr = b*1024 + tb*64 + w*16 + g + hf*8;
            float v0 = O[n8][hf*2+0]*(hf?i1:i0);
            float v1 = O[n8][hf*2+1]*(hf?i1:i0);
            size_t o=(size_t)tokr*CCH+col;
            bf16 h0=__float2bfloat16(v0), h1=__float2bfloat16(v1);
            __nv_bfloat162 hp2; hp2.x=h0; hp2.y=h1;
            __nv_bfloat162 lp;
            lp.x=__float2bfloat16(v0-__bfloat162float(h0));
            lp.y=__float2bfloat16(v1-__bfloat162float(h1));
            *reinterpret_cast<__nv_bfloat162*>(&g_aoh[o]) = hp2;
            *reinterpret_cast<__nv_bfloat162*>(&g_aol[o]) = lp;
        }
    }
}

__global__ void k_router(const float* __restrict__ wr, const float* __restrict__ br,
                         const float* __restrict__ wn, const float* __restrict__ bnn,
                         const float* __restrict__ temp, const float* __restrict__ noise){
    int warp=threadIdx.x>>5, lane=threadIdx.x&31;
    int n=blockIdx.x*8+warp;
    const float* hp = g_h2 + (size_t)n*CCH;
    float r[8]={}, q[8]={};
    for(int c=lane;c<CCH;c+=32){
        float hv=hp[c];
        const float* wrp=wr+c*EE; const float* wnp=wn+c*EE;
#pragma unroll
        for(int e=0;e<8;e++){ r[e]+=hv*wrp[e]; q[e]+=hv*wnp[e]; }
    }
#pragma unroll
    for(int e=0;e<8;e++)
#pragma unroll
        for(int o=16;o;o>>=1){
            r[e]+=__shfl_xor_sync(~0u,r[e],o);
            q[e]+=__shfl_xor_sync(~0u,q[e],o);
        }
    if(lane==0){
        float t=fminf(fmaxf(temp[0],0.5f),2.0f);
        float ny[8];
#pragma unroll
        for(int e=0;e<8;e++){
            float z=q[e]+bnn[e];
            float sp=(z>20.f)? z : log1pf(expf(z));
            ny[e]=r[e]+br[e] + t*noise[(size_t)n*EE+e]*sp;
        }
        int i1=0;
#pragma unroll
        for(int e=1;e<8;e++) if(ny[e]>ny[i1]) i1=e;
        int i2=-1;
#pragma unroll
        for(int e=0;e<8;e++){ if(e==i1) continue; if(i2<0||ny[e]>ny[i2]) i2=e; }
        float e2=expf(ny[i2]-ny[i1]);
        float gv[2]={1.f/(1.f+e2), e2/(1.f+e2)};
        int id[2]={i1,i2};
#pragma unroll
        for(int k2=0;k2<2;k2++){
            int e=id[k2];
            int row=atomicAdd(&g_cnt[e],1);
            g_tok[e*NT+row]=n;
            g_pos[n*2+k2]=e*NT+row;
            g_gw[n*2+k2]=gv[k2];
        }
    }
}

__global__ void k_resln(const float* __restrict__ t3, int e,
                        const float* __restrict__ gam, const float* __restrict__ bet){
    int r=blockIdx.x;
    if(r>=g_cnt[e]) return;
    int n=g_tok[e*NT+r], t=threadIdx.x;
    float v[3], s=0.f, s2=0.f;
#pragma unroll
    for(int i=0;i<3;i++){
        int c=t+256*i;
        v[i]=g_h2[(size_t)n*CCH+c]+t3[(size_t)r*CCH+c];
        s+=v[i]; s2+=v[i]*v[i];
    }
    __shared__ float shs[8], shq[8];
#pragma unroll
    for(int o=16;o;o>>=1){ s+=__shfl_xor_sync(~0u,s,o); s2+=__shfl_xor_sync(~0u,s2,o); }
    if((t&31)==0){ shs[t>>5]=s; shq[t>>5]=s2; }
    __syncthreads();
    s=0.f; s2=0.f;
#pragma unroll
    for(int i=0;i<8;i++){ s+=shs[i]; s2+=shq[i]; }
    float mean=s*(1.f/768.f), var=s2*(1.f/768.f)-mean*mean, rs=rsqrtf(var+1e-5f);
    float* ob = g_ob + (size_t)(e*NT+r)*CCH;
#pragma unroll
    for(int i=0;i<3;i++){ int c=t+256*i; ob[c]=(v[i]-mean)*rs*gam[c]+bet[c]; }
}

__global__ void k_combine(float* __restrict__ out){
    int n=blockIdx.x, t=threadIdx.x;
    float g0=g_gw[n*2], g1=g_gw[n*2+1];
    const float* o0 = g_ob + (size_t)g_pos[n*2]*CCH;
    const float* o1 = g_ob + (size_t)g_pos[n*2+1]*CCH;
#pragma unroll
    for(int i=0;i<3;i++){
        int c=t+256*i;
        out[(size_t)n*CCH+c]=g_x2[(size_t)n*CCH+c]+g0*o0[c]+g1*o1[c];
    }
}

extern "C" void kernel_launch(void* const* d_in, const int* in_sizes, int n_in,
                              void* d_out, int out_size){
    const float *x=(const float*)d_in[0], *rno=(const float*)d_in[1];
    const float *wq=(const float*)d_in[2], *wk=(const float*)d_in[3], *wv=(const float*)d_in[4];
    const float *w_proj=(const float*)d_in[5], *b_proj=(const float*)d_in[6];
    const float *ln1g=(const float*)d_in[7], *ln1b=(const float*)d_in[8];
    const float *ln2g=(const float*)d_in[9], *ln2b=(const float*)d_in[10];
    const float *wr=(const float*)d_in[11], *br=(const float*)d_in[12];
    const float *wn=(const float*)d_in[13], *bn=(const float*)d_in[14];
    const float *temp=(const float*)d_in[15];
    const float *dw1=(const float*)d_in[16], *db1=(const float*)d_in[17];
    const float *dw2=(const float*)d_in[18], *db2=(const float*)d_in[19];
    const float *dw3=(const float*)d_in[20], *db3=(const float*)d_in[21];
    const float *dlng=(const float*)d_in[22], *dlnb=(const float*)d_in[23];
    const float *sw1=(const float*)d_in[24], *sb1=(const float*)d_in[25];
    const float *sw2=(const float*)d_in[26], *sb2=(const float*)d_in[27];
    const float *slng=(const float*)d_in[28], *slnb=(const float*)d_in[29];
    float* out=(float*)d_out;

    cudaFuncSetAttribute(k_mma<0>, cudaFuncAttributeMaxDynamicSharedMemorySize, SMEMSZ);
    cudaFuncSetAttribute(k_mma<1>, cudaFuncAttributeMaxDynamicSharedMemorySize, SMEMSZ);
    cudaFuncSetAttribute(k_mma<2>, cudaFuncAttributeMaxDynamicSharedMemorySize, SMEMSZ);
    cudaFuncSetAttribute(k_mma<3>, cudaFuncAttributeMaxDynamicSharedMemorySize, SMEMSZ);
    cudaFuncSetAttribute(k_flash, cudaFuncAttributeMaxDynamicSharedMemorySize, FSM);

    bf16 *Bqh,*Bql,*Bph,*Bpl,*Bd1h,*Bd1l,*Bd2h,*Bd2l,*Bd3h,*Bd3l,*Bs1h,*Bs1l,*Bs2h,*Bs2l;
    bf16 *h1h,*h1l,*aoh,*aol,*h2h,*h2l,*t1h,*t1l,*t2h,*t2l;
    float *x2,*h2,*t3; int *tok,*cnt;
    cudaGetSymbolAddress((void**)&Bqh,g_Bqh); cudaGetSymbolAddress((void**)&Bql,g_Bql);
    cudaGetSymbolAddress((void**)&Bph,g_Bph); cudaGetSymbolAddress((void**)&Bpl,g_Bpl);
    cudaGetSymbolAddress((void**)&Bd1h,g_Bd1h); cudaGetSymbolAddress((void**)&Bd1l,g_Bd1l);
    cudaGetSymbolAddress((void**)&Bd2h,g_Bd2h); cudaGetSymbolAddress((void**)&Bd2l,g_Bd2l);
    cudaGetSymbolAddress((void**)&Bd3h,g_Bd3h); cudaGetSymbolAddress((void**)&Bd3l,g_Bd3l);
    cudaGetSymbolAddress((void**)&Bs1h,g_Bs1h); cudaGetSymbolAddress((void**)&Bs1l,g_Bs1l);
    cudaGetSymbolAddress((void**)&Bs2h,g_Bs2h); cudaGetSymbolAddress((void**)&Bs2l,g_Bs2l);
    cudaGetSymbolAddress((void**)&h1h,g_h1h); cudaGetSymbolAddress((void**)&h1l,g_h1l);
    cudaGetSymbolAddress((void**)&aoh,g_aoh); cudaGetSymbolAddress((void**)&aol,g_aol);
    cudaGetSymbolAddress((void**)&h2h,g_h2h); cudaGetSymbolAddress((void**)&h2l,g_h2l);
    cudaGetSymbolAddress((void**)&t1h,g_t1h); cudaGetSymbolAddress((void**)&t1l,g_t1l);
    cudaGetSymbolAddress((void**)&t2h,g_t2h); cudaGetSymbolAddress((void**)&t2l,g_t2l);
    cudaGetSymbolAddress((void**)&x2,g_x2); cudaGetSymbolAddress((void**)&h2,g_h2);
    cudaGetSymbolAddress((void**)&t3,g_t3);
    cudaGetSymbolAddress((void**)&tok,g_tok); cudaGetSymbolAddress((void**)&cnt,g_cnt);

    dim3 wb(32,8);
    k_reset<<<1,32>>>();
    k_wsplit<<<dim3(2,24,12),wb>>>(wq, Bqh,           Bql,           CCH, HSZ);
    k_wsplit<<<dim3(2,24,12),wb>>>(wk, Bqh+CCH*CCH,   Bql+CCH*CCH,   CCH, HSZ);
    k_wsplit<<<dim3(2,24,12),wb>>>(wv, Bqh+2*CCH*CCH, Bql+2*CCH*CCH, CCH, HSZ);
    k_wsplit<<<dim3(24,24,1),wb>>>(w_proj, Bph, Bpl, CCH, CCH);
    k_wsplit<<<dim3(96,24,2),wb>>>(dw1, Bd1h, Bd1l, CCH, FF);
    k_wsplit<<<dim3(96,96,2),wb>>>(dw2, Bd2h, Bd2l, FF, FF);
    k_wsplit<<<dim3(24,96,2),wb>>>(dw3, Bd3h, Bd3l, FF, CCH);
    k_wsplit<<<dim3(96,24,6),wb>>>(sw1, Bs1h, Bs1l, CCH, FF);
    k_wsplit<<<dim3(24,96,6),wb>>>(sw2, Bs2h, Bs2l, FF, CCH);
    // attention
    k_ln<<<NT,256>>>(x, ln1g, ln1b, nullptr, h1h, h1l);
    k_mma<0><<<dim3(18,64),256,SMEMSZ>>>(h1h,h1l,Bqh,Bql,nullptr,nullptr,nullptr,nullptr,nullptr,
                                         NT,3*CCH,CCH,nullptr,nullptr);
    k_flash<<<dim3(16,BH),128,FSM>>>();
    k_mma<1><<<dim3(6,64),256,SMEMSZ>>>(aoh,aol,Bph,Bpl,b_proj,x,x2,nullptr,nullptr,
                                        NT,CCH,CCH,nullptr,nullptr);
    // router
    k_ln<<<NT,256>>>(x2, ln2g, ln2b, h2, h2h, h2l);
    k_router<<<NT/8,256>>>(wr,br,wn,bn,temp,rno);
    // deep experts
    for(int e=0;e<2;e++){
        k_mma<2><<<dim3(24,64),256,SMEMSZ>>>(h2h,h2l,Bd1h+(size_t)e*CCH*FF,Bd1l+(size_t)e*CCH*FF,
            db1+e*FF,nullptr,nullptr,t1h,t1l, NT,FF,CCH, tok+e*NT, cnt+e);
        k_mma<2><<<dim3(24,64),256,SMEMSZ>>>(t1h,t1l,Bd2h+(size_t)e*FF*FF,Bd2l+(size_t)e*FF*FF,
            db2+e*FF,nullptr,nullptr,t2h,t2l, NT,FF,FF, nullptr, cnt+e);
        k_mma<3><<<dim3(6,64),256,SMEMSZ>>>(t2h,t2l,Bd3h+(size_t)e*CCH*FF,Bd3l+(size_t)e*CCH*FF,
            db3+e*CCH,nullptr,t3,nullptr,nullptr, NT,CCH,FF, nullptr, cnt+e);
        k_resln<<<NT,256>>>(t3, e, dlng+e*CCH, dlnb+e*CCH);
    }
    // simple experts
    for(int e=0;e<6;e++){
        int ge=2+e;
        k_mma<2><<<dim3(24,64),256,SMEMSZ>>>(h2h,h2l,Bs1h+(size_t)e*CCH*FF,Bs1l+(size_t)e*CCH*FF,
            sb1+e*FF,nullptr,nullptr,t1h,t1l, NT,FF,CCH, tok+ge*NT, cnt+ge);
        k_mma<3><<<dim3(6,64),256,SMEMSZ>>>(t1h,t1l,Bs2h+(size_t)e*CCH*FF,Bs2l+(size_t)e*CCH*FF,
            sb2+e*CCH,nullptr,t3,nullptr,nullptr, NT,CCH,FF, nullptr, cnt+ge);
        k_resln<<<NT,256>>>(t3, ge, slng+e*CCH, slnb+e*CCH);
    }
    k_combine<<<NT,256>>>(out);
}

// round 6
// speedup vs baseline: 3.3063x; 1.0990x over previous
#include <cuda_runtime.h>
#include <cuda_bf16.h>
#include <stdint.h>
#include <math.h>

#define BN 8
#define TT 1024
#define CCH 768
#define HH 12
#define HSZ 64
#define EE 8
#define FF 3072
#define NT (BN*TT)
#define BH (BN*HH)
typedef __nv_bfloat16 bf16;

// ---- static scratch ----
__device__ bf16  g_qh[BH*TT*HSZ], g_ql[BH*TT*HSZ];
__device__ bf16  g_kh[BH*TT*HSZ], g_kl[BH*TT*HSZ];
__device__ bf16  g_vh[BH*TT*HSZ], g_vl[BH*TT*HSZ];
__device__ bf16  g_h1h[NT*CCH], g_h1l[NT*CCH];
__device__ bf16  g_aoh[NT*CCH], g_aol[NT*CCH];
__device__ float g_x2[NT*CCH];
__device__ float g_h2[NT*CCH];
__device__ bf16  g_h2h[NT*CCH], g_h2l[NT*CCH];
__device__ float g_gw[NT*2];
__device__ int   g_pos[NT*2];
__device__ int   g_tok[EE*NT];
__device__ int   g_cnt[EE];
__device__ bf16  g_t1h[(size_t)EE*NT*FF], g_t1l[(size_t)EE*NT*FF];
__device__ bf16  g_t2h[(size_t)2*NT*FF],  g_t2l[(size_t)2*NT*FF];
__device__ float g_t3[(size_t)EE*NT*CCH];
__device__ float g_ob[(size_t)EE*NT*CCH];
__device__ bf16  g_Bqh[3*CCH*CCH], g_Bql[3*CCH*CCH];
__device__ bf16  g_Bph[CCH*CCH],  g_Bpl[CCH*CCH];
__device__ bf16  g_Bd1h[2*CCH*FF], g_Bd1l[2*CCH*FF];
__device__ bf16  g_Bd2h[(size_t)2*FF*FF], g_Bd2l[(size_t)2*FF*FF];
__device__ bf16  g_Bd3h[2*CCH*FF], g_Bd3l[2*CCH*FF];
__device__ bf16  g_Bs1h[(size_t)6*CCH*FF], g_Bs1l[(size_t)6*CCH*FF];
__device__ bf16  g_Bs2h[(size_t)6*CCH*FF], g_Bs2l[(size_t)6*CCH*FF];

__device__ __forceinline__ float geluf(float v){
    return 0.5f*v*(1.f + erff(v*0.70710678118654752440f));
}
__device__ __forceinline__ uint32_t smem_u32(const void* p){
    uint32_t a;
    asm("{ .reg .u64 t; cvta.to.shared.u64 t, %1; cvt.u32.u64 %0, t; }" : "=r"(a) : "l"(p));
    return a;
}
__device__ __forceinline__ void cp16(uint32_t d, const void* s){
    asm volatile("cp.async.cg.shared.global [%0], [%1], 16;" :: "r"(d), "l"(s));
}
__device__ __forceinline__ void ldsm4(uint32_t a, uint32_t* r){
    asm volatile("ldmatrix.sync.aligned.m8n8.x4.shared.b16 {%0,%1,%2,%3}, [%4];"
        : "=r"(r[0]),"=r"(r[1]),"=r"(r[2]),"=r"(r[3]) : "r"(a));
}
__device__ __forceinline__ void mma16816(float* c, const uint32_t* a, const uint32_t* b){
    asm volatile("mma.sync.aligned.m16n8k16.row.col.f32.bf16.bf16.f32 "
        "{%0,%1,%2,%3},{%4,%5,%6,%7},{%8,%9},{%0,%1,%2,%3};"
        : "+f"(c[0]),"+f"(c[1]),"+f"(c[2]),"+f"(c[3])
        : "r"(a[0]),"r"(a[1]),"r"(a[2]),"r"(a[3]), "r"(b[0]),"r"(b[1]));
}
__device__ __forceinline__ uint32_t packbf(float a, float b){
    __nv_bfloat162 p; p.x=__float2bfloat16(a); p.y=__float2bfloat16(b);
    return *reinterpret_cast<uint32_t*>(&p);
}

__global__ void k_reset(){ if(threadIdx.x < EE) g_cnt[threadIdx.x] = 0; }

// W[K][N] -> out[N][K] hi/lo bf16
__global__ void k_wsplit(const float* __restrict__ W, bf16* __restrict__ oh,
                         bf16* __restrict__ ol, int K, int N){
    int e = blockIdx.z;
    W += (size_t)e*K*N; oh += (size_t)e*K*N; ol += (size_t)e*K*N;
    __shared__ float s[32][33];
    int n0 = blockIdx.x*32, k0 = blockIdx.y*32;
    int tx = threadIdx.x, ty = threadIdx.y;
#pragma unroll
    for(int r=0;r<4;r++){ int kk=ty+r*8; s[kk][tx] = W[(size_t)(k0+kk)*N + n0+tx]; }
    __syncthreads();
#pragma unroll
    for(int r=0;r<4;r++){
        int kk = ty+r*8;
        float v = s[tx][kk];
        bf16 hi = __float2bfloat16(v);
        size_t o = (size_t)(n0+kk)*K + k0+tx;
        oh[o]=hi; ol[o]=__float2bfloat16(v - __bfloat162float(hi));
    }
}

__global__ void k_ln(const float* __restrict__ in, const float* __restrict__ gam,
                     const float* __restrict__ bet, float* __restrict__ out,
                     bf16* __restrict__ oh, bf16* __restrict__ ol){
    int n = blockIdx.x, t = threadIdx.x;
    const float* row = in + (size_t)n*CCH;
    float v[3], s=0.f, s2=0.f;
#pragma unroll
    for(int i=0;i<3;i++){ v[i]=row[t+256*i]; s+=v[i]; s2+=v[i]*v[i]; }
    __shared__ float shs[8], shq[8];
#pragma unroll
    for(int o=16;o;o>>=1){ s+=__shfl_xor_sync(~0u,s,o); s2+=__shfl_xor_sync(~0u,s2,o); }
    if((t&31)==0){ shs[t>>5]=s; shq[t>>5]=s2; }
    __syncthreads();
    s=0.f; s2=0.f;
#pragma unroll
    for(int i=0;i<8;i++){ s+=shs[i]; s2+=shq[i]; }
    float mean=s*(1.f/768.f), var=s2*(1.f/768.f)-mean*mean, r=rsqrtf(var+1e-5f);
#pragma unroll
    for(int i=0;i<3;i++){
        int c=t+256*i;
        float o=(v[i]-mean)*r*gam[c]+bet[c];
        if(out) out[(size_t)n*CCH+c]=o;
        if(oh){
            bf16 hi=__float2bfloat16(o);
            oh[(size_t)n*CCH+c]=hi;
            ol[(size_t)n*CCH+c]=__float2bfloat16(o-__bfloat162float(hi));
        }
    }
}

// ---- mma.sync split-bf16 GEMM, 3-stage cp.async, z-batched ----
#define PITCH 80
#define TILEB 10240
#define STAGEB 40960
#define SMEMSZ (3*STAGEB)
template<int EPI>
__global__ void __launch_bounds__(256,1)
k_mma(const bf16* __restrict__ Ah, const bf16* __restrict__ Al, size_t zsA,
      const bf16* __restrict__ Bh, const bf16* __restrict__ Bl, size_t zsB,
      const float* __restrict__ bias, int zsBias,
      const float* __restrict__ resid,
      float* __restrict__ out32, bf16* __restrict__ outH, bf16* __restrict__ outL,
      size_t zsOut, int M, int Nn, int K,
      const int* __restrict__ tok, const int* __restrict__ cnt){
    int z = blockIdx.z;
    if(cnt) M = cnt[z];
    int by = blockIdx.y, bx = blockIdx.x;
    if(by*128 >= M) return;
    Ah += (size_t)z*zsA; Al += (size_t)z*zsA;
    Bh += (size_t)z*zsB; Bl += (size_t)z*zsB;
    if(bias) bias += (size_t)z*zsBias;
    if(out32) out32 += (size_t)z*zsOut;
    if(outH){ outH += (size_t)z*zsOut; outL += (size_t)z*zsOut; }
    if(tok) tok += (size_t)z*NT;
    extern __shared__ char smem[];
    uint32_t su = smem_u32(smem);
    int tid=threadIdx.x, lane=tid&31, wid=tid>>5;
    int wm=wid&3, wn=wid>>2;
    const int KT = K/32;
    float acc[2][8][4];
#pragma unroll
    for(int a=0;a<2;a++)
#pragma unroll
        for(int b=0;b<8;b++)
#pragma unroll
            for(int c=0;c<4;c++) acc[a][b][c]=0.f;
    auto load_stage = [&](int kt){
        uint32_t sb = su + (kt%3)*STAGEB;
#pragma unroll
        for(int i=0;i<8;i++){
            int c = tid + i*256;
            int tile=c>>9, w=c&511, row=w>>2, q=w&3;
            uint32_t d = sb + tile*TILEB + row*PITCH + q*16;
            const bf16* src;
            if(tile<2){
                int rg=by*128+row; if(rg>=M) rg=M-1;
                int asrc = tok ? tok[rg] : rg;
                src = (tile==0?Ah:Al) + (size_t)asrc*K + kt*32 + q*8;
            } else {
                int ng=bx*128+row;
                src = (tile==2?Bh:Bl) + (size_t)ng*K + kt*32 + q*8;
            }
            cp16(d, src);
        }
        asm volatile("cp.async.commit_group;" ::: "memory");
    };
    load_stage(0);
    if(KT>1) load_stage(1);
    for(int kt=0; kt<KT; kt++){
        if(kt+2<KT) load_stage(kt+2);
        if(kt+2<KT)      asm volatile("cp.async.wait_group 2;" ::: "memory");
        else if(kt+1<KT) asm volatile("cp.async.wait_group 1;" ::: "memory");
        else             asm volatile("cp.async.wait_group 0;" ::: "memory");
        __syncthreads();
        uint32_t sb = su + (kt%3)*STAGEB;
#pragma unroll
        for(int kh=0; kh<2; kh++){
            uint32_t aH[2][4], aL[2][4];
            int arow = wm*32 + (lane&15);
            uint32_t ako = kh*32 + (lane>>4)*16;
#pragma unroll
            for(int mt=0;mt<2;mt++){
                uint32_t ad = sb + (arow+mt*16)*PITCH + ako;
                ldsm4(ad, aH[mt]);
                ldsm4(ad + TILEB, aL[mt]);
            }
            uint32_t bHf[4][4], bLf[4][4];
            int brow = wn*64 + ((lane&7) | ((lane&16)>>1));
            uint32_t bko = kh*32 + ((lane>>3)&1)*16;
#pragma unroll
            for(int nt=0;nt<4;nt++){
                uint32_t bd = sb + 2*TILEB + (brow+nt*16)*PITCH + bko;
                ldsm4(bd, bHf[nt]);
                ldsm4(bd + TILEB, bLf[nt]);
            }
#pragma unroll
            for(int mt=0;mt<2;mt++)
#pragma unroll
            for(int n8=0;n8<8;n8++){
                uint32_t* bh = &bHf[n8>>1][(n8&1)*2];
                uint32_t* bl = &bLf[n8>>1][(n8&1)*2];
                mma16816(acc[mt][n8], aH[mt], bh);
                mma16816(acc[mt][n8], aH[mt], bl);
                mma16816(acc[mt][n8], aL[mt], bh);
            }
        }
        __syncthreads();
    }
    int g = lane>>2, t4 = lane&3;
#pragma unroll
    for(int mt=0;mt<2;mt++)
#pragma unroll
    for(int n8=0;n8<8;n8++){
        int col = bx*128 + wn*64 + n8*8 + t4*2;
#pragma unroll
        for(int hf=0; hf<2; hf++){
            int row = by*128 + wm*32 + mt*16 + g + hf*8;
            if(row >= M) continue;
            float v0 = acc[mt][n8][hf*2+0];
            float v1 = acc[mt][n8][hf*2+1];
            if(EPI==0){
                int which = col/CCH, rem = col - which*CCH;
                int h = rem>>6, d0 = rem&63;
                int b = row>>10, t = row&1023;
                size_t o = ((size_t)(b*HH+h)*TT + t)*HSZ + d0;
                bf16* dh = which==0? g_qh : which==1? g_kh : g_vh;
                bf16* dl = which==0? g_ql : which==1? g_kl : g_vl;
                bf16 h0=__float2bfloat16(v0), h1=__float2bfloat16(v1);
                __nv_bfloat162 hp; hp.x=h0; hp.y=h1;
                __nv_bfloat162 lp;
                lp.x=__float2bfloat16(v0-__bfloat162float(h0));
                lp.y=__float2bfloat16(v1-__bfloat162float(h1));
                *reinterpret_cast<__nv_bfloat162*>(&dh[o]) = hp;
                *reinterpret_cast<__nv_bfloat162*>(&dl[o]) = lp;
            } else if(EPI==1){
                size_t o=(size_t)row*Nn+col;
                out32[o]   = v0 + bias[col]   + resid[o];
                out32[o+1] = v1 + bias[col+1] + resid[o+1];
            } else if(EPI==2){
                size_t o=(size_t)row*Nn+col;
                float u0 = geluf(v0 + bias[col]);
                float u1 = geluf(v1 + bias[col+1]);
                bf16 h0=__float2bfloat16(u0), h1=__float2bfloat16(u1);
                __nv_bfloat162 hp; hp.x=h0; hp.y=h1;
                __nv_bfloat162 lp;
                lp.x=__float2bfloat16(u0-__bfloat162float(h0));
                lp.y=__float2bfloat16(u1-__bfloat162float(h1));
                *reinterpret_cast<__nv_bfloat162*>(&outH[o]) = hp;
                *reinterpret_cast<__nv_bfloat162*>(&outL[o]) = lp;
            } else {
                size_t o=(size_t)row*Nn+col;
                out32[o]   = v0 + bias[col];
                out32[o+1] = v1 + bias[col+1];
            }
        }
    }
}

// ---- flash attention (unchanged from round 5) ----
#define FP 72
#define FT (64*FP*2)
#define FSM (6*FT)
__global__ void __launch_bounds__(128,1) k_flash(){
    int tb = blockIdx.x, bh = blockIdx.y;
    extern __shared__ char fsm[];
    uint32_t su = smem_u32(fsm);
    int tid=threadIdx.x, lane=tid&31, w=tid>>5;
    const size_t hb = (size_t)bh*TT*HSZ;
    for(int i=tid;i<2048;i+=128){
        int r=i>>5, c2=i&31;
        size_t go = hb + (size_t)(tb*64+r)*HSZ + c2*2;
        *(__nv_bfloat162*)((char*)fsm + 0*FT + (r*FP+c2*2)*2) = *(const __nv_bfloat162*)&g_qh[go];
        *(__nv_bfloat162*)((char*)fsm + 1*FT + (r*FP+c2*2)*2) = *(const __nv_bfloat162*)&g_ql[go];
    }
    float m0=-1e30f, m1=-1e30f, l0=0.f, l1=0.f;
    float O[8][4];
#pragma unroll
    for(int n8=0;n8<8;n8++)
#pragma unroll
        for(int c=0;c<4;c++) O[n8][c]=0.f;
    const float scale=0.036084391824351615f;
    int brow = (lane&7) | ((lane&16)>>1);
    int t4 = lane&3, g = lane>>2;
    for(int sb=0; sb<=tb; sb++){
        __syncthreads();
        for(int i=tid;i<2048;i+=128){
            int r=i>>5, c2=i&31;
            size_t go = hb + (size_t)(sb*64+r)*HSZ + c2*2;
            *(__nv_bfloat162*)((char*)fsm + 2*FT + (r*FP+c2*2)*2) = *(const __nv_bfloat162*)&g_kh[go];
            *(__nv_bfloat162*)((char*)fsm + 3*FT + (r*FP+c2*2)*2) = *(const __nv_bfloat162*)&g_kl[go];
            __nv_bfloat162 vh = *(const __nv_bfloat162*)&g_vh[go];
            __nv_bfloat162 vl = *(const __nv_bfloat162*)&g_vl[go];
            bf16* Vth = (bf16*)((char*)fsm + 4*FT);
            bf16* Vtl = (bf16*)((char*)fsm + 5*FT);
            Vth[(c2*2  )*FP + r] = vh.x;
            Vth[(c2*2+1)*FP + r] = vh.y;
            Vtl[(c2*2  )*FP + r] = vl.x;
            Vtl[(c2*2+1)*FP + r] = vl.y;
        }
        __syncthreads();
        float S[8][4];
#pragma unroll
        for(int n8=0;n8<8;n8++)
#pragma unroll
            for(int c=0;c<4;c++) S[n8][c]=0.f;
#pragma unroll
        for(int kc=0;kc<4;kc++){
            uint32_t aH[4], aL[4];
            uint32_t ad = su + (w*16+(lane&15))*144 + kc*32 + (lane>>4)*16;
            ldsm4(ad, aH); ldsm4(ad+FT, aL);
            uint32_t bH[4][4], bL[4][4];
#pragma unroll
            for(int nt=0;nt<4;nt++){
                uint32_t bd = su + 2*FT + ((nt*16+brow)*144) + kc*32 + ((lane>>3)&1)*16;
                ldsm4(bd, bH[nt]); ldsm4(bd+FT, bL[nt]);
            }
#pragma unroll
            for(int n8=0;n8<8;n8++){
                uint32_t* bh2=&bH[n8>>1][(n8&1)*2];
                uint32_t* bl2=&bL[n8>>1][(n8&1)*2];
                mma16816(S[n8], aH, bh2);
                mma16816(S[n8], aH, bl2);
                mma16816(S[n8], aL, bh2);
            }
        }
        int rg0 = tb*64 + w*16 + g;
#pragma unroll
        for(int n8=0;n8<8;n8++)
#pragma unroll
            for(int c=0;c<4;c++){
                S[n8][c] *= scale;
                if(sb==tb){
                    int sg = sb*64 + n8*8 + t4*2 + (c&1);
                    int rg = rg0 + ((c>=2)?8:0);
                    if(sg > rg) S[n8][c] = -1e30f;
                }
            }
        float mx0=-1e30f, mx1=-1e30f;
#pragma unroll
        for(int n8=0;n8<8;n8++){
            mx0=fmaxf(mx0,fmaxf(S[n8][0],S[n8][1]));
            mx1=fmaxf(mx1,fmaxf(S[n8][2],S[n8][3]));
        }
        mx0=fmaxf(mx0,__shfl_xor_sync(~0u,mx0,1)); mx0=fmaxf(mx0,__shfl_xor_sync(~0u,mx0,2));
        mx1=fmaxf(mx1,__shfl_xor_sync(~0u,mx1,1)); mx1=fmaxf(mx1,__shfl_xor_sync(~0u,mx1,2));
        float mn0=fmaxf(m0,mx0), mn1=fmaxf(m1,mx1);
        float f0=expf(m0-mn0), f1=expf(m1-mn1);
        m0=mn0; m1=mn1;
        float rs0=0.f, rs1=0.f;
#pragma unroll
        for(int n8=0;n8<8;n8++){
            S[n8][0]=expf(S[n8][0]-mn0); S[n8][1]=expf(S[n8][1]-mn0);
            S[n8][2]=expf(S[n8][2]-mn1); S[n8][3]=expf(S[n8][3]-mn1);
            rs0+=S[n8][0]+S[n8][1]; rs1+=S[n8][2]+S[n8][3];
        }
        rs0+=__shfl_xor_sync(~0u,rs0,1); rs0+=__shfl_xor_sync(~0u,rs0,2);
        rs1+=__shfl_xor_sync(~0u,rs1,1); rs1+=__shfl_xor_sync(~0u,rs1,2);
        l0=l0*f0+rs0; l1=l1*f1+rs1;
#pragma unroll
        for(int n8=0;n8<8;n8++){
            O[n8][0]*=f0; O[n8][1]*=f0; O[n8][2]*=f1; O[n8][3]*=f1;
        }
#pragma unroll
        for(int j=0;j<4;j++){
            float p00=S[2*j][0], p01=S[2*j][1], p02=S[2*j][2], p03=S[2*j][3];
            float p10=S[2*j+1][0], p11=S[2*j+1][1], p12=S[2*j+1][2], p13=S[2*j+1][3];
            uint32_t aPh[4], aPl[4];
            aPh[0]=packbf(p00,p01); aPh[1]=packbf(p02,p03);
            aPh[2]=packbf(p10,p11); aPh[3]=packbf(p12,p13);
            {
                __nv_bfloat162 t;
                t=*(__nv_bfloat162*)&aPh[0];
                aPl[0]=packbf(p00-__bfloat162float(t.x), p01-__bfloat162float(t.y));
                t=*(__nv_bfloat162*)&aPh[1];
                aPl[1]=packbf(p02-__bfloat162float(t.x), p03-__bfloat162float(t.y));
                t=*(__nv_bfloat162*)&aPh[2];
                aPl[2]=packbf(p10-__bfloat162float(t.x), p11-__bfloat162float(t.y));
                t=*(__nv_bfloat162*)&aPh[3];
                aPl[3]=packbf(p12-__bfloat162float(t.x), p13-__bfloat162float(t.y));
            }
            uint32_t bH[4][4], bL[4][4];
#pragma unroll
            for(int nt=0;nt<4;nt++){
                uint32_t bd = su + 4*FT + ((nt*16+brow)*144) + j*32 + ((lane>>3)&1)*16;
                ldsm4(bd, bH[nt]); ldsm4(bd+FT, bL[nt]);
            }
#pragma unroll
            for(int n8=0;n8<8;n8++){
                uint32_t* bh2=&bH[n8>>1][(n8&1)*2];
                uint32_t* bl2=&bL[n8>>1][(n8&1)*2];
                mma16816(O[n8], aPh, bh2);
                mma16816(O[n8], aPh, bl2);
                mma16816(O[n8], aPl, bh2);
            }
        }
    }
    float i0=1.f/l0, i1=1.f/l1;
    int b = bh/HH, h = bh%HH;
#pragma unroll
    for(int n8=0;n8<8;n8++){
        int col = h*64 + n8*8 + t4*2;
#pragma unroll
        for(int hf=0;hf<2;hf++){
            int tokr = b*1024 + tb*64 + w*16 + g + hf*8;
            float v0 = O[n8][hf*2+0]*(hf?i1:i0);
            float v1 = O[n8][hf*2+1]*(hf?i1:i0);
            size_t o=(size_t)tokr*CCH+col;
            bf16 h0=__float2bfloat16(v0), h1=__float2bfloat16(v1);
            __nv_bfloat162 hp2; hp2.x=h0; hp2.y=h1;
            __nv_bfloat162 lp;
            lp.x=__float2bfloat16(v0-__bfloat162float(h0));
            lp.y=__float2bfloat16(v1-__bfloat162float(h1));
            *reinterpret_cast<__nv_bfloat162*>(&g_aoh[o]) = hp2;
            *reinterpret_cast<__nv_bfloat162*>(&g_aol[o]) = lp;
        }
    }
}

__global__ void k_router(const float* __restrict__ wr, const float* __restrict__ br,
                         const float* __restrict__ wn, const float* __restrict__ bnn,
                         const float* __restrict__ temp, const float* __restrict__ noise){
    int warp=threadIdx.x>>5, lane=threadIdx.x&31;
    int n=blockIdx.x*8+warp;
    const float* hp = g_h2 + (size_t)n*CCH;
    float r[8]={}, q[8]={};
    for(int c=lane;c<CCH;c+=32){
        float hv=hp[c];
        const float* wrp=wr+c*EE; const float* wnp=wn+c*EE;
#pragma unroll
        for(int e=0;e<8;e++){ r[e]+=hv*wrp[e]; q[e]+=hv*wnp[e]; }
    }
#pragma unroll
    for(int e=0;e<8;e++)
#pragma unroll
        for(int o=16;o;o>>=1){
            r[e]+=__shfl_xor_sync(~0u,r[e],o);
            q[e]+=__shfl_xor_sync(~0u,q[e],o);
        }
    if(lane==0){
        float t=fminf(fmaxf(temp[0],0.5f),2.0f);
        float ny[8];
#pragma unroll
        for(int e=0;e<8;e++){
            float z=q[e]+bnn[e];
            float sp=(z>20.f)? z : log1pf(expf(z));
            ny[e]=r[e]+br[e] + t*noise[(size_t)n*EE+e]*sp;
        }
        int i1=0;
#pragma unroll
        for(int e=1;e<8;e++) if(ny[e]>ny[i1]) i1=e;
        int i2=-1;
#pragma unroll
        for(int e=0;e<8;e++){ if(e==i1) continue; if(i2<0||ny[e]>ny[i2]) i2=e; }
        float e2=expf(ny[i2]-ny[i1]);
        float gv[2]={1.f/(1.f+e2), e2/(1.f+e2)};
        int id[2]={i1,i2};
#pragma unroll
        for(int k2=0;k2<2;k2++){
            int e=id[k2];
            int row=atomicAdd(&g_cnt[e],1);
            g_tok[e*NT+row]=n;
            g_pos[n*2+k2]=e*NT+row;
            g_gw[n*2+k2]=gv[k2];
        }
    }
}

// batched residual-LN over all experts
__global__ void k_resln(const float* __restrict__ t3,
                        const float* __restrict__ dg, const float* __restrict__ db_,
                        const float* __restrict__ sg, const float* __restrict__ sb_){
    int e = blockIdx.y, r = blockIdx.x;
    if(r >= g_cnt[e]) return;
    const float* gam = (e<2)? dg + e*CCH : sg + (e-2)*CCH;
    const float* bet = (e<2)? db_ + e*CCH : sb_ + (e-2)*CCH;
    const float* t3e = t3 + (size_t)e*NT*CCH + (size_t)r*CCH;
    int n = g_tok[e*NT+r], t = threadIdx.x;
    float v[3], s=0.f, s2=0.f;
#pragma unroll
    for(int i=0;i<3;i++){
        int c=t+256*i;
        v[i]=g_h2[(size_t)n*CCH+c]+t3e[c];
        s+=v[i]; s2+=v[i]*v[i];
    }
    __shared__ float shs[8], shq[8];
#pragma unroll
    for(int o=16;o;o>>=1){ s+=__shfl_xor_sync(~0u,s,o); s2+=__shfl_xor_sync(~0u,s2,o); }
    if((t&31)==0){ shs[t>>5]=s; shq[t>>5]=s2; }
    __syncthreads();
    s=0.f; s2=0.f;
#pragma unroll
    for(int i=0;i<8;i++){ s+=shs[i]; s2+=shq[i]; }
    float mean=s*(1.f/768.f), var=s2*(1.f/768.f)-mean*mean, rs=rsqrtf(var+1e-5f);
    float* ob = g_ob + (size_t)(e*NT+r)*CCH;
#pragma unroll
    for(int i=0;i<3;i++){ int c=t+256*i; ob[c]=(v[i]-mean)*rs*gam[c]+bet[c]; }
}

__global__ void k_combine(float* __restrict__ out){
    int n=blockIdx.x, t=threadIdx.x;
    float g0=g_gw[n*2], g1=g_gw[n*2+1];
    const float* o0 = g_ob + (size_t)g_pos[n*2]*CCH;
    const float* o1 = g_ob + (size_t)g_pos[n*2+1]*CCH;
#pragma unroll
    for(int i=0;i<3;i++){
        int c=t+256*i;
        out[(size_t)n*CCH+c]=g_x2[(size_t)n*CCH+c]+g0*o0[c]+g1*o1[c];
    }
}

extern "C" void kernel_launch(void* const* d_in, const int* in_sizes, int n_in,
                              void* d_out, int out_size){
    const float *x=(const float*)d_in[0], *rno=(const float*)d_in[1];
    const float *wq=(const float*)d_in[2], *wk=(const float*)d_in[3], *wv=(const float*)d_in[4];
    const float *w_proj=(const float*)d_in[5], *b_proj=(const float*)d_in[6];
    const float *ln1g=(const float*)d_in[7], *ln1b=(const float*)d_in[8];
    const float *ln2g=(const float*)d_in[9], *ln2b=(const float*)d_in[10];
    const float *wr=(const float*)d_in[11], *br=(const float*)d_in[12];
    const float *wn=(const float*)d_in[13], *bn=(const float*)d_in[14];
    const float *temp=(const float*)d_in[15];
    const float *dw1=(const float*)d_in[16], *db1=(const float*)d_in[17];
    const float *dw2=(const float*)d_in[18], *db2=(const float*)d_in[19];
    const float *dw3=(const float*)d_in[20], *db3=(const float*)d_in[21];
    const float *dlng=(const float*)d_in[22], *dlnb=(const float*)d_in[23];
    const float *sw1=(const float*)d_in[24], *sb1=(const float*)d_in[25];
    const float *sw2=(const float*)d_in[26], *sb2=(const float*)d_in[27];
    const float *slng=(const float*)d_in[28], *slnb=(const float*)d_in[29];
    float* out=(float*)d_out;

    cudaFuncSetAttribute(k_mma<0>, cudaFuncAttributeMaxDynamicSharedMemorySize, SMEMSZ);
    cudaFuncSetAttribute(k_mma<1>, cudaFuncAttributeMaxDynamicSharedMemorySize, SMEMSZ);
    cudaFuncSetAttribute(k_mma<2>, cudaFuncAttributeMaxDynamicSharedMemorySize, SMEMSZ);
    cudaFuncSetAttribute(k_mma<3>, cudaFuncAttributeMaxDynamicSharedMemorySize, SMEMSZ);
    cudaFuncSetAttribute(k_flash, cudaFuncAttributeMaxDynamicSharedMemorySize, FSM);

    bf16 *Bqh,*Bql,*Bph,*Bpl,*Bd1h,*Bd1l,*Bd2h,*Bd2l,*Bd3h,*Bd3l,*Bs1h,*Bs1l,*Bs2h,*Bs2l;
    bf16 *h1h,*h1l,*aoh,*aol,*h2h,*h2l,*t1h,*t1l,*t2h,*t2l;
    float *x2,*h2,*t3; int *tok,*cnt;
    cudaGetSymbolAddress((void**)&Bqh,g_Bqh); cudaGetSymbolAddress((void**)&Bql,g_Bql);
    cudaGetSymbolAddress((void**)&Bph,g_Bph); cudaGetSymbolAddress((void**)&Bpl,g_Bpl);
    cudaGetSymbolAddress((void**)&Bd1h,g_Bd1h); cudaGetSymbolAddress((void**)&Bd1l,g_Bd1l);
    cudaGetSymbolAddress((void**)&Bd2h,g_Bd2h); cudaGetSymbolAddress((void**)&Bd2l,g_Bd2l);
    cudaGetSymbolAddress((void**)&Bd3h,g_Bd3h); cudaGetSymbolAddress((void**)&Bd3l,g_Bd3l);
    cudaGetSymbolAddress((void**)&Bs1h,g_Bs1h); cudaGetSymbolAddress((void**)&Bs1l,g_Bs1l);
    cudaGetSymbolAddress((void**)&Bs2h,g_Bs2h); cudaGetSymbolAddress((void**)&Bs2l,g_Bs2l);
    cudaGetSymbolAddress((void**)&h1h,g_h1h); cudaGetSymbolAddress((void**)&h1l,g_h1l);
    cudaGetSymbolAddress((void**)&aoh,g_aoh); cudaGetSymbolAddress((void**)&aol,g_aol);
    cudaGetSymbolAddress((void**)&h2h,g_h2h); cudaGetSymbolAddress((void**)&h2l,g_h2l);
    cudaGetSymbolAddress((void**)&t1h,g_t1h); cudaGetSymbolAddress((void**)&t1l,g_t1l);
    cudaGetSymbolAddress((void**)&t2h,g_t2h); cudaGetSymbolAddress((void**)&t2l,g_t2l);
    cudaGetSymbolAddress((void**)&x2,g_x2); cudaGetSymbolAddress((void**)&h2,g_h2);
    cudaGetSymbolAddress((void**)&t3,g_t3);
    cudaGetSymbolAddress((void**)&tok,g_tok); cudaGetSymbolAddress((void**)&cnt,g_cnt);
    const size_t ZT1=(size_t)NT*FF, ZT3=(size_t)NT*CCH;

    dim3 wb(32,8);
    k_reset<<<1,32>>>();
    k_wsplit<<<dim3(2,24,12),wb>>>(wq, Bqh,           Bql,           CCH, HSZ);
    k_wsplit<<<dim3(2,24,12),wb>>>(wk, Bqh+CCH*CCH,   Bql+CCH*CCH,   CCH, HSZ);
    k_wsplit<<<dim3(2,24,12),wb>>>(wv, Bqh+2*CCH*CCH, Bql+2*CCH*CCH, CCH, HSZ);
    k_wsplit<<<dim3(24,24,1),wb>>>(w_proj, Bph, Bpl, CCH, CCH);
    k_wsplit<<<dim3(96,24,2),wb>>>(dw1, Bd1h, Bd1l, CCH, FF);
    k_wsplit<<<dim3(96,96,2),wb>>>(dw2, Bd2h, Bd2l, FF, FF);
    k_wsplit<<<dim3(24,96,2),wb>>>(dw3, Bd3h, Bd3l, FF, CCH);
    k_wsplit<<<dim3(96,24,6),wb>>>(sw1, Bs1h, Bs1l, CCH, FF);
    k_wsplit<<<dim3(24,96,6),wb>>>(sw2, Bs2h, Bs2l, FF, CCH);
    // attention
    k_ln<<<NT,256>>>(x, ln1g, ln1b, nullptr, h1h, h1l);
    k_mma<0><<<dim3(18,64,1),256,SMEMSZ>>>(h1h,h1l,0, Bqh,Bql,0, nullptr,0, nullptr,
        nullptr,nullptr,nullptr,0, NT,3*CCH,CCH, nullptr,nullptr);
    k_flash<<<dim3(16,BH),128,FSM>>>();
    k_mma<1><<<dim3(6,64,1),256,SMEMSZ>>>(aoh,aol,0, Bph,Bpl,0, b_proj,0, x,
        x2,nullptr,nullptr,0, NT,CCH,CCH, nullptr,nullptr);
    // router
    k_ln<<<NT,256>>>(x2, ln2g, ln2b, h2, h2h, h2l);
    k_router<<<NT/8,256>>>(wr,br,wn,bn,temp,rno);
    // experts, batched over z
    // L1 deep (z=0,1): h2 -> t1[z]
    k_mma<2><<<dim3(24,64,2),256,SMEMSZ>>>(h2h,h2l,0, Bd1h,Bd1l,(size_t)CCH*FF, db1,FF,
        nullptr, nullptr,t1h,t1l,ZT1, NT,FF,CCH, tok,cnt);
    // L1 simple (z=0..5 -> experts 2..7): h2 -> t1[2+z]
    k_mma<2><<<dim3(24,64,6),256,SMEMSZ>>>(h2h,h2l,0, Bs1h,Bs1l,(size_t)CCH*FF, sb1,FF,
        nullptr, nullptr,t1h+2*ZT1,t1l+2*ZT1,ZT1, NT,FF,CCH, tok+2*NT,cnt+2);
    // L2 deep: t1[z] -> t2[z]
    k_mma<2><<<dim3(24,64,2),256,SMEMSZ>>>(t1h,t1l,ZT1, Bd2h,Bd2l,(size_t)FF*FF, db2,FF,
        nullptr, nullptr,t2h,t2l,ZT1, NT,FF,FF, nullptr,cnt);
    // L3 deep: t2[z] -> t3[z]
    k_mma<3><<<dim3(6,64,2),256,SMEMSZ>>>(t2h,t2l,ZT1, Bd3h,Bd3l,(size_t)CCH*FF, db3,CCH,
        nullptr, t3,nullptr,nullptr,ZT3, NT,CCH,FF, nullptr,cnt);
    // L2 simple: t1[2+z] -> t3[2+z]
    k_mma<3><<<dim3(6,64,6),256,SMEMSZ>>>(t1h+2*ZT1,t1l+2*ZT1,ZT1, Bs2h,Bs2l,(size_t)CCH*FF, sb2,CCH,
        nullptr, t3+2*ZT3,nullptr,nullptr,ZT3, NT,CCH,FF, nullptr,cnt+2);
    // batched residual LN + combine
    k_resln<<<dim3(NT,EE),256>>>(t3, dlng, dlnb, slng, slnb);
    k_combine<<<NT,256>>>(out);
}

// round 7
// speedup vs baseline: 4.3417x; 1.3131x over previous
#include <cuda_runtime.h>
#include <cuda_bf16.h>
#include <cuda_fp16.h>
#include <stdint.h>
#include <math.h>

#define BN 8
#define TT 1024
#define CCH 768
#define HH 12
#define HSZ 64
#define EE 8
#define FF 3072
#define NT (BN*TT)
#define BH (BN*HH)
typedef __nv_bfloat16 bf16;
typedef __half f16;

// ---- static scratch ----
__device__ bf16  g_qh[BH*TT*HSZ], g_ql[BH*TT*HSZ];
__device__ bf16  g_kh[BH*TT*HSZ], g_kl[BH*TT*HSZ];
__device__ bf16  g_vh[BH*TT*HSZ], g_vl[BH*TT*HSZ];
__device__ bf16  g_h1h[NT*CCH], g_h1l[NT*CCH];
__device__ bf16  g_aoh[NT*CCH], g_aol[NT*CCH];
__device__ float g_x2[NT*CCH];
__device__ float g_h2[NT*CCH];
__device__ f16   g_h2f[NT*CCH];
__device__ float g_gw[NT*2];
__device__ int   g_pos[NT*2];
__device__ int   g_tok[EE*NT];
__device__ int   g_cnt[EE];
__device__ f16   g_t1f[(size_t)EE*NT*FF];
__device__ f16   g_t2f[(size_t)2*NT*FF];
__device__ float g_t3[(size_t)EE*NT*CCH];
__device__ bf16  g_Bqh[3*CCH*CCH], g_Bql[3*CCH*CCH];
__device__ bf16  g_Bph[CCH*CCH],  g_Bpl[CCH*CCH];
__device__ f16   g_Bd1h[2*CCH*FF], g_Bd1l[2*CCH*FF];
__device__ f16   g_Bd2h[(size_t)2*FF*FF], g_Bd2l[(size_t)2*FF*FF];
__device__ f16   g_Bd3h[2*CCH*FF], g_Bd3l[2*CCH*FF];
__device__ f16   g_Bs1h[(size_t)6*CCH*FF], g_Bs1l[(size_t)6*CCH*FF];
__device__ f16   g_Bs2h[(size_t)6*CCH*FF], g_Bs2l[(size_t)6*CCH*FF];

__device__ __forceinline__ float geluf(float v){
    return 0.5f*v*(1.f + erff(v*0.70710678118654752440f));
}
__device__ __forceinline__ uint32_t smem_u32(const void* p){
    uint32_t a;
    asm("{ .reg .u64 t; cvta.to.shared.u64 t, %1; cvt.u32.u64 %0, t; }" : "=r"(a) : "l"(p));
    return a;
}
__device__ __forceinline__ void cp16(uint32_t d, const void* s){
    asm volatile("cp.async.cg.shared.global [%0], [%1], 16;" :: "r"(d), "l"(s));
}
__device__ __forceinline__ void ldsm4(uint32_t a, uint32_t* r){
    asm volatile("ldmatrix.sync.aligned.m8n8.x4.shared.b16 {%0,%1,%2,%3}, [%4];"
        : "=r"(r[0]),"=r"(r[1]),"=r"(r[2]),"=r"(r[3]) : "r"(a));
}
__device__ __forceinline__ void mma16816(float* c, const uint32_t* a, const uint32_t* b){
    asm volatile("mma.sync.aligned.m16n8k16.row.col.f32.bf16.bf16.f32 "
        "{%0,%1,%2,%3},{%4,%5,%6,%7},{%8,%9},{%0,%1,%2,%3};"
        : "+f"(c[0]),"+f"(c[1]),"+f"(c[2]),"+f"(c[3])
        : "r"(a[0]),"r"(a[1]),"r"(a[2]),"r"(a[3]), "r"(b[0]),"r"(b[1]));
}
__device__ __forceinline__ void mmah16816(float* c, const uint32_t* a, const uint32_t* b){
    asm volatile("mma.sync.aligned.m16n8k16.row.col.f32.f16.f16.f32 "
        "{%0,%1,%2,%3},{%4,%5,%6,%7},{%8,%9},{%0,%1,%2,%3};"
        : "+f"(c[0]),"+f"(c[1]),"+f"(c[2]),"+f"(c[3])
        : "r"(a[0]),"r"(a[1]),"r"(a[2]),"r"(a[3]), "r"(b[0]),"r"(b[1]));
}
__device__ __forceinline__ uint32_t packbf(float a, float b){
    __nv_bfloat162 p; p.x=__float2bfloat16(a); p.y=__float2bfloat16(b);
    return *reinterpret_cast<uint32_t*>(&p);
}

__global__ void k_reset(){ if(threadIdx.x < EE) g_cnt[threadIdx.x] = 0; }

// W[K][N] -> out[N][K] hi/lo, vectorized transpose. grid(N/32, K/64, E), block(32,8)
template<typename T>
__global__ void k_wsplit2(const float* __restrict__ W, T* __restrict__ oh,
                          T* __restrict__ ol, int K, int N){
    int e = blockIdx.z;
    W += (size_t)e*K*N; oh += (size_t)e*K*N; ol += (size_t)e*K*N;
    __shared__ float s[64][33];
    int n0 = blockIdx.x*32, k0 = blockIdx.y*64;
    int tx = threadIdx.x, ty = threadIdx.y;
#pragma unroll
    for(int r=0;r<8;r++){ int kk=ty+r*8; s[kk][tx] = W[(size_t)(k0+kk)*N + n0+tx]; }
    __syncthreads();
#pragma unroll
    for(int r=0;r<4;r++){
        int n = ty + r*8;
        float v0 = s[2*tx][n], v1 = s[2*tx+1][n];
        T h0 = T(v0), h1 = T(v1);
        T hh[2] = {h0, h1};
        T ll[2] = {T(v0-float(h0)), T(v1-float(h1))};
        size_t o = (size_t)(n0+n)*K + k0 + 2*tx;
        *reinterpret_cast<uint32_t*>(&oh[o]) = *reinterpret_cast<uint32_t*>(hh);
        *reinterpret_cast<uint32_t*>(&ol[o]) = *reinterpret_cast<uint32_t*>(ll);
    }
}

__global__ void k_ln(const float* __restrict__ in, const float* __restrict__ gam,
                     const float* __restrict__ bet, float* __restrict__ out,
                     bf16* __restrict__ oh, bf16* __restrict__ ol, f16* __restrict__ of){
    int n = blockIdx.x, t = threadIdx.x;
    const float* row = in + (size_t)n*CCH;
    float v[3], s=0.f, s2=0.f;
#pragma unroll
    for(int i=0;i<3;i++){ v[i]=row[t+256*i]; s+=v[i]; s2+=v[i]*v[i]; }
    __shared__ float shs[8], shq[8];
#pragma unroll
    for(int o=16;o;o>>=1){ s+=__shfl_xor_sync(~0u,s,o); s2+=__shfl_xor_sync(~0u,s2,o); }
    if((t&31)==0){ shs[t>>5]=s; shq[t>>5]=s2; }
    __syncthreads();
    s=0.f; s2=0.f;
#pragma unroll
    for(int i=0;i<8;i++){ s+=shs[i]; s2+=shq[i]; }
    float mean=s*(1.f/768.f), var=s2*(1.f/768.f)-mean*mean, r=rsqrtf(var+1e-5f);
#pragma unroll
    for(int i=0;i<3;i++){
        int c=t+256*i;
        float o=(v[i]-mean)*r*gam[c]+bet[c];
        if(out) out[(size_t)n*CCH+c]=o;
        if(oh){
            bf16 hi=__float2bfloat16(o);
            oh[(size_t)n*CCH+c]=hi;
            ol[(size_t)n*CCH+c]=__float2bfloat16(o-__bfloat162float(hi));
        }
        if(of) of[(size_t)n*CCH+c]=__float2half(o);
    }
}

// ---- bf16 3-product GEMM (QKV + proj), 3-stage ----
#define PITCH 80
#define TILEB 10240
#define STAGEB 40960
#define SMEMSZ (3*STAGEB)
template<int EPI>
__global__ void __launch_bounds__(256,1)
k_mma(const bf16* __restrict__ Ah, const bf16* __restrict__ Al,
      const bf16* __restrict__ Bh, const bf16* __restrict__ Bl,
      const float* __restrict__ bias, const float* __restrict__ resid,
      float* __restrict__ out32, int M, int Nn, int K){
    int by = blockIdx.y, bx = blockIdx.x;
    extern __shared__ char smem[];
    uint32_t su = smem_u32(smem);
    int tid=threadIdx.x, lane=tid&31, wid=tid>>5;
    int wm=wid&3, wn=wid>>2;
    const int KT = K/32;
    float acc[2][8][4];
#pragma unroll
    for(int a=0;a<2;a++)
#pragma unroll
        for(int b=0;b<8;b++)
#pragma unroll
            for(int c=0;c<4;c++) acc[a][b][c]=0.f;
    auto load_stage = [&](int kt){
        uint32_t sb = su + (kt%3)*STAGEB;
#pragma unroll
        for(int i=0;i<8;i++){
            int c = tid + i*256;
            int tile=c>>9, w=c&511, row=w>>2, q=w&3;
            uint32_t d = sb + tile*TILEB + row*PITCH + q*16;
            const bf16* src;
            if(tile<2) src = (tile==0?Ah:Al) + (size_t)(by*128+row)*K + kt*32 + q*8;
            else       src = (tile==2?Bh:Bl) + (size_t)(bx*128+row)*K + kt*32 + q*8;
            cp16(d, src);
        }
        asm volatile("cp.async.commit_group;" ::: "memory");
    };
    load_stage(0);
    if(KT>1) load_stage(1);
    for(int kt=0; kt<KT; kt++){
        if(kt+2<KT) load_stage(kt+2);
        if(kt+2<KT)      asm volatile("cp.async.wait_group 2;" ::: "memory");
        else if(kt+1<KT) asm volatile("cp.async.wait_group 1;" ::: "memory");
        else             asm volatile("cp.async.wait_group 0;" ::: "memory");
        __syncthreads();
        uint32_t sb = su + (kt%3)*STAGEB;
#pragma unroll
        for(int kh=0; kh<2; kh++){
            uint32_t aH[2][4], aL[2][4];
            int arow = wm*32 + (lane&15);
            uint32_t ako = kh*32 + (lane>>4)*16;
#pragma unroll
            for(int mt=0;mt<2;mt++){
                uint32_t ad = sb + (arow+mt*16)*PITCH + ako;
                ldsm4(ad, aH[mt]); ldsm4(ad + TILEB, aL[mt]);
            }
            uint32_t bHf[4][4], bLf[4][4];
            int brow = wn*64 + ((lane&7) | ((lane&16)>>1));
            uint32_t bko = kh*32 + ((lane>>3)&1)*16;
#pragma unroll
            for(int nt=0;nt<4;nt++){
                uint32_t bd = sb + 2*TILEB + (brow+nt*16)*PITCH + bko;
                ldsm4(bd, bHf[nt]); ldsm4(bd + TILEB, bLf[nt]);
            }
#pragma unroll
            for(int mt=0;mt<2;mt++)
#pragma unroll
            for(int n8=0;n8<8;n8++){
                uint32_t* bh = &bHf[n8>>1][(n8&1)*2];
                uint32_t* bl = &bLf[n8>>1][(n8&1)*2];
                mma16816(acc[mt][n8], aH[mt], bh);
                mma16816(acc[mt][n8], aH[mt], bl);
                mma16816(acc[mt][n8], aL[mt], bh);
            }
        }
        __syncthreads();
    }
    int g = lane>>2, t4 = lane&3;
#pragma unroll
    for(int mt=0;mt<2;mt++)
#pragma unroll
    for(int n8=0;n8<8;n8++){
        int col = bx*128 + wn*64 + n8*8 + t4*2;
#pragma unroll
        for(int hf=0; hf<2; hf++){
            int row = by*128 + wm*32 + mt*16 + g + hf*8;
            float v0 = acc[mt][n8][hf*2+0];
            float v1 = acc[mt][n8][hf*2+1];
            if(EPI==0){
                int which = col/CCH, rem = col - which*CCH;
                int h = rem>>6, d0 = rem&63;
                int b = row>>10, t = row&1023;
                size_t o = ((size_t)(b*HH+h)*TT + t)*HSZ + d0;
                bf16* dh = which==0? g_qh : which==1? g_kh : g_vh;
                bf16* dl = which==0? g_ql : which==1? g_kl : g_vl;
                bf16 h0=__float2bfloat16(v0), h1=__float2bfloat16(v1);
                __nv_bfloat162 hp; hp.x=h0; hp.y=h1;
                __nv_bfloat162 lp;
                lp.x=__float2bfloat16(v0-__bfloat162float(h0));
                lp.y=__float2bfloat16(v1-__bfloat162float(h1));
                *reinterpret_cast<__nv_bfloat162*>(&dh[o]) = hp;
                *reinterpret_cast<__nv_bfloat162*>(&dl[o]) = lp;
            } else {
                size_t o=(size_t)row*Nn+col;
                out32[o]   = v0 + bias[col]   + resid[o];
                out32[o+1] = v1 + bias[col+1] + resid[o+1];
            }
        }
    }
}

// ---- fp16 2-product GEMM (experts), 4-stage, z-batched with pointer select ----
#define HSTG 30720
#define HSMEM (4*HSTG)
template<int EPI>
__global__ void __launch_bounds__(256,1)
k_mmah(const f16* __restrict__ A1, size_t zsA, const f16* __restrict__ A2, size_t zsA2,
       int zSplitA,
       const f16* __restrict__ B1h, const f16* __restrict__ B1l,
       const f16* __restrict__ B2h, const f16* __restrict__ B2l, size_t zsB, int zSplit,
       const float* __restrict__ b1, const float* __restrict__ b2,
       float* __restrict__ out32, f16* __restrict__ outH, size_t zsOut,
       int M, int Nn, int K,
       const int* __restrict__ tok, const int* __restrict__ cnt){
    int z = blockIdx.z;
    if(cnt) M = cnt[z];
    int by = blockIdx.y, bx = blockIdx.x;
    if(by*128 >= M) return;
    const f16* A = (z < zSplitA) ? A1 + (size_t)z*zsA : A2 + (size_t)z*zsA2;
    const f16 *Bh, *Bl; const float* bias;
    if(z < zSplit){ Bh=B1h+(size_t)z*zsB; Bl=B1l+(size_t)z*zsB; bias=b1+(size_t)z*Nn; }
    else { Bh=B2h+(size_t)(z-zSplit)*zsB; Bl=B2l+(size_t)(z-zSplit)*zsB; bias=b2+(size_t)(z-zSplit)*Nn; }
    if(out32) out32 += (size_t)z*zsOut;
    if(outH)  outH  += (size_t)z*zsOut;
    if(tok) tok += (size_t)z*NT;
    extern __shared__ char smem[];
    uint32_t su = smem_u32(smem);
    int tid=threadIdx.x, lane=tid&31, wid=tid>>5;
    int wm=wid&3, wn=wid>>2;
    const int KT = K/32;
    float acc[2][8][4];
#pragma unroll
    for(int a=0;a<2;a++)
#pragma unroll
        for(int b=0;b<8;b++)
#pragma unroll
            for(int c=0;c<4;c++) acc[a][b][c]=0.f;
    auto load_stage = [&](int kt){
        uint32_t sb = su + (kt&3)*HSTG;
#pragma unroll
        for(int i=0;i<6;i++){
            int c = tid + i*256;
            int tile=c>>9, w=c&511, row=w>>2, q=w&3;
            uint32_t d = sb + tile*TILEB + row*PITCH + q*16;
            const f16* src;
            if(tile==0){
                int rg=by*128+row; if(rg>=M) rg=M-1;
                int asrc = tok ? tok[rg] : rg;
                src = A + (size_t)asrc*K + kt*32 + q*8;
            } else {
                src = (tile==1?Bh:Bl) + (size_t)(bx*128+row)*K + kt*32 + q*8;
            }
            cp16(d, src);
        }
        asm volatile("cp.async.commit_group;" ::: "memory");
    };
    load_stage(0);
    if(KT>1) load_stage(1);
    if(KT>2) load_stage(2);
    for(int kt=0; kt<KT; kt++){
        if(kt+3<KT) load_stage(kt+3);
        if(kt+3<KT)      asm volatile("cp.async.wait_group 3;" ::: "memory");
        else if(kt+2<KT) asm volatile("cp.async.wait_group 2;" ::: "memory");
        else if(kt+1<KT) asm volatile("cp.async.wait_group 1;" ::: "memory");
        else             asm volatile("cp.async.wait_group 0;" ::: "memory");
        __syncthreads();
        uint32_t sb = su + (kt&3)*HSTG;
#pragma unroll
        for(int kh=0; kh<2; kh++){
            uint32_t aF[2][4];
            int arow = wm*32 + (lane&15);
            uint32_t ako = kh*32 + (lane>>4)*16;
#pragma unroll
            for(int mt=0;mt<2;mt++)
                ldsm4(sb + (arow+mt*16)*PITCH + ako, aF[mt]);
            uint32_t bHf[4][4], bLf[4][4];
            int brow = wn*64 + ((lane&7) | ((lane&16)>>1));
            uint32_t bko = kh*32 + ((lane>>3)&1)*16;
#pragma unroll
            for(int nt=0;nt<4;nt++){
                uint32_t bd = sb + TILEB + (brow+nt*16)*PITCH + bko;
                ldsm4(bd, bHf[nt]); ldsm4(bd + TILEB, bLf[nt]);
            }
#pragma unroll
            for(int mt=0;mt<2;mt++)
#pragma unroll
            for(int n8=0;n8<8;n8++){
                mmah16816(acc[mt][n8], aF[mt], &bHf[n8>>1][(n8&1)*2]);
                mmah16816(acc[mt][n8], aF[mt], &bLf[n8>>1][(n8&1)*2]);
            }
        }
        __syncthreads();
    }
    int g = lane>>2, t4 = lane&3;
#pragma unroll
    for(int mt=0;mt<2;mt++)
#pragma unroll
    for(int n8=0;n8<8;n8++){
        int col = bx*128 + wn*64 + n8*8 + t4*2;
#pragma unroll
        for(int hf=0; hf<2; hf++){
            int row = by*128 + wm*32 + mt*16 + g + hf*8;
            if(row >= M) continue;
            float v0 = acc[mt][n8][hf*2+0];
            float v1 = acc[mt][n8][hf*2+1];
            size_t o=(size_t)row*Nn+col;
            if(EPI==2){
                __half2 hp;
                hp.x = __float2half(geluf(v0 + bias[col]));
                hp.y = __float2half(geluf(v1 + bias[col+1]));
                *reinterpret_cast<__half2*>(&outH[o]) = hp;
            } else {
                out32[o]   = v0 + bias[col];
                out32[o+1] = v1 + bias[col+1];
            }
        }
    }
}

// ---- flash attention (bf16 3-product), heavy tiles first ----
#define FP 72
#define FT (64*FP*2)
#define FSM (6*FT)
__global__ void __launch_bounds__(128,1) k_flash(){
    int tb = 15 - blockIdx.x, bh = blockIdx.y;
    extern __shared__ char fsm[];
    uint32_t su = smem_u32(fsm);
    int tid=threadIdx.x, lane=tid&31, w=tid>>5;
    const size_t hb = (size_t)bh*TT*HSZ;
    for(int i=tid;i<2048;i+=128){
        int r=i>>5, c2=i&31;
        size_t go = hb + (size_t)(tb*64+r)*HSZ + c2*2;
        *(__nv_bfloat162*)((char*)fsm + 0*FT + (r*FP+c2*2)*2) = *(const __nv_bfloat162*)&g_qh[go];
        *(__nv_bfloat162*)((char*)fsm + 1*FT + (r*FP+c2*2)*2) = *(const __nv_bfloat162*)&g_ql[go];
    }
    float m0=-1e30f, m1=-1e30f, l0=0.f, l1=0.f;
    float O[8][4];
#pragma unroll
    for(int n8=0;n8<8;n8++)
#pragma unroll
        for(int c=0;c<4;c++) O[n8][c]=0.f;
    const float scale=0.036084391824351615f;
    int brow = (lane&7) | ((lane&16)>>1);
    int t4 = lane&3, g = lane>>2;
    for(int sb=0; sb<=tb; sb++){
        __syncthreads();
        for(int i=tid;i<2048;i+=128){
            int r=i>>5, c2=i&31;
            size_t go = hb + (size_t)(sb*64+r)*HSZ + c2*2;
            *(__nv_bfloat162*)((char*)fsm + 2*FT + (r*FP+c2*2)*2) = *(const __nv_bfloat162*)&g_kh[go];
            *(__nv_bfloat162*)((char*)fsm + 3*FT + (r*FP+c2*2)*2) = *(const __nv_bfloat162*)&g_kl[go];
            __nv_bfloat162 vh = *(const __nv_bfloat162*)&g_vh[go];
            __nv_bfloat162 vl = *(const __nv_bfloat162*)&g_vl[go];
            bf16* Vth = (bf16*)((char*)fsm + 4*FT);
            bf16* Vtl = (bf16*)((char*)fsm + 5*FT);
            Vth[(c2*2  )*FP + r] = vh.x;
            Vth[(c2*2+1)*FP + r] = vh.y;
            Vtl[(c2*2  )*FP + r] = vl.x;
            Vtl[(c2*2+1)*FP + r] = vl.y;
        }
        __syncthreads();
        float S[8][4];
#pragma unroll
        for(int n8=0;n8<8;n8++)
#pragma unroll
            for(int c=0;c<4;c++) S[n8][c]=0.f;
#pragma unroll
        for(int kc=0;kc<4;kc++){
            uint32_t aH[4], aL[4];
            uint32_t ad = su + (w*16+(lane&15))*144 + kc*32 + (lane>>4)*16;
            ldsm4(ad, aH); ldsm4(ad+FT, aL);
            uint32_t bHt[4][4], bLt[4][4];
#pragma unroll
            for(int nt=0;nt<4;nt++){
                uint32_t bd = su + 2*FT + ((nt*16+brow)*144) + kc*32 + ((lane>>3)&1)*16;
                ldsm4(bd, bHt[nt]); ldsm4(bd+FT, bLt[nt]);
            }
#pragma unroll
            for(int n8=0;n8<8;n8++){
                uint32_t* bh2=&bHt[n8>>1][(n8&1)*2];
                uint32_t* bl2=&bLt[n8>>1][(n8&1)*2];
                mma16816(S[n8], aH, bh2);
                mma16816(S[n8], aH, bl2);
                mma16816(S[n8], aL, bh2);
            }
        }
        int rg0 = tb*64 + w*16 + g;
#pragma unroll
        for(int n8=0;n8<8;n8++)
#pragma unroll
            for(int c=0;c<4;c++){
                S[n8][c] *= scale;
                if(sb==tb){
                    int sg = sb*64 + n8*8 + t4*2 + (c&1);
                    int rg = rg0 + ((c>=2)?8:0);
                    if(sg > rg) S[n8][c] = -1e30f;
                }
            }
        float mx0=-1e30f, mx1=-1e30f;
#pragma unroll
        for(int n8=0;n8<8;n8++){
            mx0=fmaxf(mx0,fmaxf(S[n8][0],S[n8][1]));
            mx1=fmaxf(mx1,fmaxf(S[n8][2],S[n8][3]));
        }
        mx0=fmaxf(mx0,__shfl_xor_sync(~0u,mx0,1)); mx0=fmaxf(mx0,__shfl_xor_sync(~0u,mx0,2));
        mx1=fmaxf(mx1,__shfl_xor_sync(~0u,mx1,1)); mx1=fmaxf(mx1,__shfl_xor_sync(~0u,mx1,2));
        float mn0=fmaxf(m0,mx0), mn1=fmaxf(m1,mx1);
        float f0=expf(m0-mn0), f1=expf(m1-mn1);
        m0=mn0; m1=mn1;
        float rs0=0.f, rs1=0.f;
#pragma unroll
        for(int n8=0;n8<8;n8++){
            S[n8][0]=expf(S[n8][0]-mn0); S[n8][1]=expf(S[n8][1]-mn0);
            S[n8][2]=expf(S[n8][2]-mn1); S[n8][3]=expf(S[n8][3]-mn1);
            rs0+=S[n8][0]+S[n8][1]; rs1+=S[n8][2]+S[n8][3];
        }
        rs0+=__shfl_xor_sync(~0u,rs0,1); rs0+=__shfl_xor_sync(~0u,rs0,2);
        rs1+=__shfl_xor_sync(~0u,rs1,1); rs1+=__shfl_xor_sync(~0u,rs1,2);
        l0=l0*f0+rs0; l1=l1*f1+rs1;
#pragma unroll
        for(int n8=0;n8<8;n8++){
            O[n8][0]*=f0; O[n8][1]*=f0; O[n8][2]*=f1; O[n8][3]*=f1;
        }
#pragma unroll
        for(int j=0;j<4;j++){
            float p00=S[2*j][0], p01=S[2*j][1], p02=S[2*j][2], p03=S[2*j][3];
            float p10=S[2*j+1][0], p11=S[2*j+1][1], p12=S[2*j+1][2], p13=S[2*j+1][3];
            uint32_t aPh[4], aPl[4];
            aPh[0]=packbf(p00,p01); aPh[1]=packbf(p02,p03);
            aPh[2]=packbf(p10,p11); aPh[3]=packbf(p12,p13);
            {
                __nv_bfloat162 t;
                t=*(__nv_bfloat162*)&aPh[0];
                aPl[0]=packbf(p00-__bfloat162float(t.x), p01-__bfloat162float(t.y));
                t=*(__nv_bfloat162*)&aPh[1];
                aPl[1]=packbf(p02-__bfloat162float(t.x), p03-__bfloat162float(t.y));
                t=*(__nv_bfloat162*)&aPh[2];
                aPl[2]=packbf(p10-__bfloat162float(t.x), p11-__bfloat162float(t.y));
                t=*(__nv_bfloat162*)&aPh[3];
                aPl[3]=packbf(p12-__bfloat162float(t.x), p13-__bfloat162float(t.y));
            }
            uint32_t bHt[4][4], bLt[4][4];
#pragma unroll
            for(int nt=0;nt<4;nt++){
                uint32_t bd = su + 4*FT + ((nt*16+brow)*144) + j*32 + ((lane>>3)&1)*16;
                ldsm4(bd, bHt[nt]); ldsm4(bd+FT, bLt[nt]);
            }
#pragma unroll
            for(int n8=0;n8<8;n8++){
                uint32_t* bh2=&bHt[n8>>1][(n8&1)*2];
                uint32_t* bl2=&bLt[n8>>1][(n8&1)*2];
                mma16816(O[n8], aPh, bh2);
                mma16816(O[n8], aPh, bl2);
                mma16816(O[n8], aPl, bh2);
            }
        }
    }
    float i0=1.f/l0, i1=1.f/l1;
    int b = bh/HH, h = bh%HH;
#pragma unroll
    for(int n8=0;n8<8;n8++){
        int col = h*64 + n8*8 + t4*2;
#pragma unroll
        for(int hf=0;hf<2;hf++){
            int tokr = b*1024 + tb*64 + w*16 + g + hf*8;
            float v0 = O[n8][hf*2+0]*(hf?i1:i0);
            float v1 = O[n8][hf*2+1]*(hf?i1:i0);
            size_t o=(size_t)tokr*CCH+col;
            bf16 h0=__float2bfloat16(v0), h1=__float2bfloat16(v1);
            __nv_bfloat162 hp2; hp2.x=h0; hp2.y=h1;
            __nv_bfloat162 lp;
            lp.x=__float2bfloat16(v0-__bfloat162float(h0));
            lp.y=__float2bfloat16(v1-__bfloat162float(h1));
            *reinterpret_cast<__nv_bfloat162*>(&g_aoh[o]) = hp2;
            *reinterpret_cast<__nv_bfloat162*>(&g_aol[o]) = lp;
        }
    }
}

__global__ void k_router(const float* __restrict__ wr, const float* __restrict__ br,
                         const float* __restrict__ wn, const float* __restrict__ bnn,
                         const float* __restrict__ temp, const float* __restrict__ noise){
    int warp=threadIdx.x>>5, lane=threadIdx.x&31;
    int n=blockIdx.x*8+warp;
    const float* hp = g_h2 + (size_t)n*CCH;
    float r[8]={}, q[8]={};
    for(int c=lane;c<CCH;c+=32){
        float hv=hp[c];
        const float* wrp=wr+c*EE; const float* wnp=wn+c*EE;
#pragma unroll
        for(int e=0;e<8;e++){ r[e]+=hv*wrp[e]; q[e]+=hv*wnp[e]; }
    }
#pragma unroll
    for(int e=0;e<8;e++)
#pragma unroll
        for(int o=16;o;o>>=1){
            r[e]+=__shfl_xor_sync(~0u,r[e],o);
            q[e]+=__shfl_xor_sync(~0u,q[e],o);
        }
    if(lane==0){
        float t=fminf(fmaxf(temp[0],0.5f),2.0f);
        float ny[8];
#pragma unroll
        for(int e=0;e<8;e++){
            float z=q[e]+bnn[e];
            float sp=(z>20.f)? z : log1pf(expf(z));
            ny[e]=r[e]+br[e] + t*noise[(size_t)n*EE+e]*sp;
        }
        int i1=0;
#pragma unroll
        for(int e=1;e<8;e++) if(ny[e]>ny[i1]) i1=e;
        int i2=-1;
#pragma unroll
        for(int e=0;e<8;e++){ if(e==i1) continue; if(i2<0||ny[e]>ny[i2]) i2=e; }
        float e2=expf(ny[i2]-ny[i1]);
        float gv[2]={1.f/(1.f+e2), e2/(1.f+e2)};
        int id[2]={i1,i2};
#pragma unroll
        for(int k2=0;k2<2;k2++){
            int e=id[k2];
            int row=atomicAdd(&g_cnt[e],1);
            g_tok[e*NT+row]=n;
            g_pos[n*2+k2]=e*NT+row;
            g_gw[n*2+k2]=gv[k2];
        }
    }
}

// fused dual residual-LN + gated combine
__global__ void k_fin(const float* __restrict__ t3,
                      const float* __restrict__ dg, const float* __restrict__ db_,
                      const float* __restrict__ sg, const float* __restrict__ sb_,
                      float* __restrict__ out){
    int n=blockIdx.x, t=threadIdx.x;
    int s0=g_pos[2*n], s1=g_pos[2*n+1];
    int e0=s0>>13, r0=s0&8191, e1=s1>>13, r1=s1&8191;
    const float* ta = t3 + (size_t)e0*NT*CCH + (size_t)r0*CCH;
    const float* tb = t3 + (size_t)e1*NT*CCH + (size_t)r1*CCH;
    float va[3], vb[3];
    float sa=0.f,qa=0.f,sb2=0.f,qb=0.f;
#pragma unroll
    for(int i=0;i<3;i++){
        int c=t+256*i;
        float h = g_h2[(size_t)n*CCH+c];
        va[i]=h+ta[c]; vb[i]=h+tb[c];
        sa+=va[i]; qa+=va[i]*va[i]; sb2+=vb[i]; qb+=vb[i]*vb[i];
    }
    __shared__ float sh[8][4];
#pragma unroll
    for(int o=16;o;o>>=1){
        sa+=__shfl_xor_sync(~0u,sa,o); qa+=__shfl_xor_sync(~0u,qa,o);
        sb2+=__shfl_xor_sync(~0u,sb2,o); qb+=__shfl_xor_sync(~0u,qb,o);
    }
    if((t&31)==0){ sh[t>>5][0]=sa; sh[t>>5][1]=qa; sh[t>>5][2]=sb2; sh[t>>5][3]=qb; }
    __syncthreads();
    sa=0.f; qa=0.f; sb2=0.f; qb=0.f;
#pragma unroll
    for(int i=0;i<8;i++){ sa+=sh[i][0]; qa+=sh[i][1]; sb2+=sh[i][2]; qb+=sh[i][3]; }
    float ma=sa*(1.f/768.f), ra=rsqrtf(qa*(1.f/768.f)-ma*ma+1e-5f);
    float mb=sb2*(1.f/768.f), rb=rsqrtf(qb*(1.f/768.f)-mb*mb+1e-5f);
    const float* g0p = (e0<2)? dg+e0*CCH : sg+(e0-2)*CCH;
    const float* b0p = (e0<2)? db_+e0*CCH : sb_+(e0-2)*CCH;
    const float* g1p = (e1<2)? dg+e1*CCH : sg+(e1-2)*CCH;
    const float* b1p = (e1<2)? db_+e1*CCH : sb_+(e1-2)*CCH;
    float gw0=g_gw[2*n], gw1=g_gw[2*n+1];
#pragma unroll
    for(int i=0;i<3;i++){
        int c=t+256*i;
        float o0=(va[i]-ma)*ra*g0p[c]+b0p[c];
        float o1=(vb[i]-mb)*rb*g1p[c]+b1p[c];
        out[(size_t)n*CCH+c]=g_x2[(size_t)n*CCH+c]+gw0*o0+gw1*o1;
    }
}

extern "C" void kernel_launch(void* const* d_in, const int* in_sizes, int n_in,
                              void* d_out, int out_size){
    const float *x=(const float*)d_in[0], *rno=(const float*)d_in[1];
    const float *wq=(const float*)d_in[2], *wk=(const float*)d_in[3], *wv=(const float*)d_in[4];
    const float *w_proj=(const float*)d_in[5], *b_proj=(const float*)d_in[6];
    const float *ln1g=(const float*)d_in[7], *ln1b=(const float*)d_in[8];
    const float *ln2g=(const float*)d_in[9], *ln2b=(const float*)d_in[10];
    const float *wr=(const float*)d_in[11], *br=(const float*)d_in[12];
    const float *wn=(const float*)d_in[13], *bn=(const float*)d_in[14];
    const float *temp=(const float*)d_in[15];
    const float *dw1=(const float*)d_in[16], *db1=(const float*)d_in[17];
    const float *dw2=(const float*)d_in[18], *db2=(const float*)d_in[19];
    const float *dw3=(const float*)d_in[20], *db3=(const float*)d_in[21];
    const float *dlng=(const float*)d_in[22], *dlnb=(const float*)d_in[23];
    const float *sw1=(const float*)d_in[24], *sb1=(const float*)d_in[25];
    const float *sw2=(const float*)d_in[26], *sb2=(const float*)d_in[27];
    const float *slng=(const float*)d_in[28], *slnb=(const float*)d_in[29];
    float* out=(float*)d_out;

    cudaFuncSetAttribute(k_mma<0>, cudaFuncAttributeMaxDynamicSharedMemorySize, SMEMSZ);
    cudaFuncSetAttribute(k_mma<1>, cudaFuncAttributeMaxDynamicSharedMemorySize, SMEMSZ);
    cudaFuncSetAttribute(k_mmah<2>, cudaFuncAttributeMaxDynamicSharedMemorySize, HSMEM);
    cudaFuncSetAttribute(k_mmah<3>, cudaFuncAttributeMaxDynamicSharedMemorySize, HSMEM);
    cudaFuncSetAttribute(k_flash, cudaFuncAttributeMaxDynamicSharedMemorySize, FSM);

    bf16 *Bqh,*Bql,*Bph,*Bpl,*h1h,*h1l,*aoh,*aol;
    f16 *Bd1h,*Bd1l,*Bd2h,*Bd2l,*Bd3h,*Bd3l,*Bs1h,*Bs1l,*Bs2h,*Bs2l,*h2f,*t1f,*t2f;
    float *x2,*h2,*t3; int *tok,*cnt;
    cudaGetSymbolAddress((void**)&Bqh,g_Bqh); cudaGetSymbolAddress((void**)&Bql,g_Bql);
    cudaGetSymbolAddress((void**)&Bph,g_Bph); cudaGetSymbolAddress((void**)&Bpl,g_Bpl);
    cudaGetSymbolAddress((void**)&Bd1h,g_Bd1h); cudaGetSymbolAddress((void**)&Bd1l,g_Bd1l);
    cudaGetSymbolAddress((void**)&Bd2h,g_Bd2h); cudaGetSymbolAddress((void**)&Bd2l,g_Bd2l);
    cudaGetSymbolAddress((void**)&Bd3h,g_Bd3h); cudaGetSymbolAddress((void**)&Bd3l,g_Bd3l);
    cudaGetSymbolAddress((void**)&Bs1h,g_Bs1h); cudaGetSymbolAddress((void**)&Bs1l,g_Bs1l);
    cudaGetSymbolAddress((void**)&Bs2h,g_Bs2h); cudaGetSymbolAddress((void**)&Bs2l,g_Bs2l);
    cudaGetSymbolAddress((void**)&h1h,g_h1h); cudaGetSymbolAddress((void**)&h1l,g_h1l);
    cudaGetSymbolAddress((void**)&aoh,g_aoh); cudaGetSymbolAddress((void**)&aol,g_aol);
    cudaGetSymbolAddress((void**)&h2f,g_h2f);
    cudaGetSymbolAddress((void**)&t1f,g_t1f); cudaGetSymbolAddress((void**)&t2f,g_t2f);
    cudaGetSymbolAddress((void**)&x2,g_x2); cudaGetSymbolAddress((void**)&h2,g_h2);
    cudaGetSymbolAddress((void**)&t3,g_t3);
    cudaGetSymbolAddress((void**)&tok,g_tok); cudaGetSymbolAddress((void**)&cnt,g_cnt);
    const size_t ZT1=(size_t)NT*FF, ZT3=(size_t)NT*CCH;

    dim3 wb(32,8);
    k_reset<<<1,32>>>();
    // weight transpose + split (bf16 for attn, fp16 for experts)
    k_wsplit2<bf16><<<dim3(2,12,12),wb>>>(wq, Bqh,           Bql,           CCH, HSZ);
    k_wsplit2<bf16><<<dim3(2,12,12),wb>>>(wk, Bqh+CCH*CCH,   Bql+CCH*CCH,   CCH, HSZ);
    k_wsplit2<bf16><<<dim3(2,12,12),wb>>>(wv, Bqh+2*CCH*CCH, Bql+2*CCH*CCH, CCH, HSZ);
    k_wsplit2<bf16><<<dim3(24,12,1),wb>>>(w_proj, Bph, Bpl, CCH, CCH);
    k_wsplit2<f16><<<dim3(96,12,2),wb>>>(dw1, Bd1h, Bd1l, CCH, FF);
    k_wsplit2<f16><<<dim3(96,48,2),wb>>>(dw2, Bd2h, Bd2l, FF, FF);
    k_wsplit2<f16><<<dim3(24,48,2),wb>>>(dw3, Bd3h, Bd3l, FF, CCH);
    k_wsplit2<f16><<<dim3(96,12,6),wb>>>(sw1, Bs1h, Bs1l, CCH, FF);
    k_wsplit2<f16><<<dim3(24,48,6),wb>>>(sw2, Bs2h, Bs2l, FF, CCH);
    // attention
    k_ln<<<NT,256>>>(x, ln1g, ln1b, nullptr, h1h, h1l, nullptr);
    k_mma<0><<<dim3(18,64),256,SMEMSZ>>>(h1h,h1l,Bqh,Bql,nullptr,nullptr,nullptr,
                                         NT,3*CCH,CCH);
    k_flash<<<dim3(16,BH),128,FSM>>>();
    k_mma<1><<<dim3(6,64),256,SMEMSZ>>>(aoh,aol,Bph,Bpl,b_proj,x,x2, NT,CCH,CCH);
    // router
    k_ln<<<NT,256>>>(x2, ln2g, ln2b, h2, nullptr, nullptr, h2f);
    k_router<<<NT/8,256>>>(wr,br,wn,bn,temp,rno);
    // experts: L1 (all 8), L2 deep, L3 deep + L2 simple fused
    k_mmah<2><<<dim3(24,64,8),256,HSMEM>>>(h2f,0, nullptr,0, 99,
        Bd1h,Bd1l, Bs1h,Bs1l,(size_t)CCH*FF, 2, db1,sb1,
        nullptr, t1f, ZT1, NT,FF,CCH, tok, cnt);
    k_mmah<2><<<dim3(24,64,2),256,HSMEM>>>(t1f,ZT1, nullptr,0, 99,
        Bd2h,Bd2l, nullptr,nullptr,(size_t)FF*FF, 99, db2,nullptr,
        nullptr, t2f, ZT1, NT,FF,FF, nullptr, cnt);
    k_mmah<3><<<dim3(6,64,8),256,HSMEM>>>(t2f,ZT1, t1f,ZT1, 2,
        Bd3h,Bd3l, Bs2h,Bs2l,(size_t)CCH*FF, 2, db3,sb2,
        t3, nullptr, ZT3, NT,CCH,FF, nullptr, cnt);
    // fused residual-LN + combine
    k_fin<<<NT,256>>>(t3, dlng, dlnb, slng, slnb, out);
}

// round 9
// speedup vs baseline: 4.5409x; 1.0459x over previous
#include <cuda_runtime.h>
#include <cuda_bf16.h>
#include <cuda_fp16.h>
#include <stdint.h>
#include <math.h>

#define BN 8
#define TT 1024
#define CCH 768
#define HH 12
#define HSZ 64
#define EE 8
#define FF 3072
#define NT (BN*TT)
#define BH (BN*HH)
typedef __nv_bfloat16 bf16;
typedef __half f16;

// ---- static scratch ----
__device__ bf16  g_qh[BH*TT*HSZ], g_ql[BH*TT*HSZ];
__device__ bf16  g_kh[BH*TT*HSZ], g_kl[BH*TT*HSZ];
__device__ bf16  g_vh[BH*TT*HSZ], g_vl[BH*TT*HSZ];
__device__ bf16  g_h1h[NT*CCH], g_h1l[NT*CCH];
__device__ bf16  g_aoh[NT*CCH], g_aol[NT*CCH];
__device__ float g_x2[NT*CCH];
__device__ float g_h2[NT*CCH];
__device__ f16   g_h2f[NT*CCH];
__device__ float g_gw[NT*2];
__device__ int   g_pos[NT*2];
__device__ int   g_tok[EE*NT];
__device__ int   g_cnt[EE];
__device__ f16   g_t1f[(size_t)EE*NT*FF];
__device__ f16   g_t2f[(size_t)2*NT*FF];
__device__ float g_t3[(size_t)EE*NT*CCH];
__device__ bf16  g_Bqh[3*CCH*CCH], g_Bql[3*CCH*CCH];
__device__ bf16  g_Bph[CCH*CCH],  g_Bpl[CCH*CCH];
__device__ f16   g_Bd1h[2*CCH*FF], g_Bd1l[2*CCH*FF];
__device__ f16   g_Bd2h[(size_t)2*FF*FF], g_Bd2l[(size_t)2*FF*FF];
__device__ f16   g_Bd3h[2*CCH*FF], g_Bd3l[2*CCH*FF];
__device__ f16   g_Bs1h[(size_t)6*CCH*FF], g_Bs1l[(size_t)6*CCH*FF];
__device__ f16   g_Bs2h[(size_t)6*CCH*FF], g_Bs2l[(size_t)6*CCH*FF];

__device__ __forceinline__ float geluf(float v){
    return 0.5f*v*(1.f + erff(v*0.70710678118654752440f));
}
__device__ __forceinline__ uint32_t smem_u32(const void* p){
    uint32_t a;
    asm("{ .reg .u64 t; cvta.to.shared.u64 t, %1; cvt.u32.u64 %0, t; }" : "=r"(a) : "l"(p));
    return a;
}
__device__ __forceinline__ void cp16(uint32_t d, const void* s){
    asm volatile("cp.async.cg.shared.global [%0], [%1], 16;" :: "r"(d), "l"(s));
}
__device__ __forceinline__ void ldsm4(uint32_t a, uint32_t* r){
    asm volatile("ldmatrix.sync.aligned.m8n8.x4.shared.b16 {%0,%1,%2,%3}, [%4];"
        : "=r"(r[0]),"=r"(r[1]),"=r"(r[2]),"=r"(r[3]) : "r"(a));
}
__device__ __forceinline__ void ldsm4t(uint32_t a, uint32_t* r){
    asm volatile("ldmatrix.sync.aligned.m8n8.x4.trans.shared.b16 {%0,%1,%2,%3}, [%4];"
        : "=r"(r[0]),"=r"(r[1]),"=r"(r[2]),"=r"(r[3]) : "r"(a));
}
__device__ __forceinline__ void mma16816(float* c, const uint32_t* a, const uint32_t* b){
    asm volatile("mma.sync.aligned.m16n8k16.row.col.f32.bf16.bf16.f32 "
        "{%0,%1,%2,%3},{%4,%5,%6,%7},{%8,%9},{%0,%1,%2,%3};"
        : "+f"(c[0]),"+f"(c[1]),"+f"(c[2]),"+f"(c[3])
        : "r"(a[0]),"r"(a[1]),"r"(a[2]),"r"(a[3]), "r"(b[0]),"r"(b[1]));
}
__device__ __forceinline__ void mmah16816(float* c, const uint32_t* a, const uint32_t* b){
    asm volatile("mma.sync.aligned.m16n8k16.row.col.f32.f16.f16.f32 "
        "{%0,%1,%2,%3},{%4,%5,%6,%7},{%8,%9},{%0,%1,%2,%3};"
        : "+f"(c[0]),"+f"(c[1]),"+f"(c[2]),"+f"(c[3])
        : "r"(a[0]),"r"(a[1]),"r"(a[2]),"r"(a[3]), "r"(b[0]),"r"(b[1]));
}
__device__ __forceinline__ uint32_t packbf(float a, float b){
    __nv_bfloat162 p; p.x=__float2bfloat16(a); p.y=__float2bfloat16(b);
    return *reinterpret_cast<uint32_t*>(&p);
}

__global__ void k_reset(){ if(threadIdx.x < EE) g_cnt[threadIdx.x] = 0; }

// W[K][N] -> out[N][K] hi/lo, vectorized transpose
template<typename T>
__global__ void k_wsplit2(const float* __restrict__ W, T* __restrict__ oh,
                          T* __restrict__ ol, int K, int N){
    int e = blockIdx.z;
    W += (size_t)e*K*N; oh += (size_t)e*K*N; ol += (size_t)e*K*N;
    __shared__ float s[64][33];
    int n0 = blockIdx.x*32, k0 = blockIdx.y*64;
    int tx = threadIdx.x, ty = threadIdx.y;
#pragma unroll
    for(int r=0;r<8;r++){ int kk=ty+r*8; s[kk][tx] = W[(size_t)(k0+kk)*N + n0+tx]; }
    __syncthreads();
#pragma unroll
    for(int r=0;r<4;r++){
        int n = ty + r*8;
        float v0 = s[2*tx][n], v1 = s[2*tx+1][n];
        T h0 = T(v0), h1 = T(v1);
        T hh[2] = {h0, h1};
        T ll[2] = {T(v0-float(h0)), T(v1-float(h1))};
        size_t o = (size_t)(n0+n)*K + k0 + 2*tx;
        *reinterpret_cast<uint32_t*>(&oh[o]) = *reinterpret_cast<uint32_t*>(hh);
        *reinterpret_cast<uint32_t*>(&ol[o]) = *reinterpret_cast<uint32_t*>(ll);
    }
}

__global__ void k_ln(const float* __restrict__ in, const float* __restrict__ gam,
                     const float* __restrict__ bet, float* __restrict__ out,
                     bf16* __restrict__ oh, bf16* __restrict__ ol, f16* __restrict__ of){
    int n = blockIdx.x, t = threadIdx.x;
    const float* row = in + (size_t)n*CCH;
    float v[3], s=0.f, s2=0.f;
#pragma unroll
    for(int i=0;i<3;i++){ v[i]=row[t+256*i]; s+=v[i]; s2+=v[i]*v[i]; }
    __shared__ float shs[8], shq[8];
#pragma unroll
    for(int o=16;o;o>>=1){ s+=__shfl_xor_sync(~0u,s,o); s2+=__shfl_xor_sync(~0u,s2,o); }
    if((t&31)==0){ shs[t>>5]=s; shq[t>>5]=s2; }
    __syncthreads();
    s=0.f; s2=0.f;
#pragma unroll
    for(int i=0;i<8;i++){ s+=shs[i]; s2+=shq[i]; }
    float mean=s*(1.f/768.f), var=s2*(1.f/768.f)-mean*mean, r=rsqrtf(var+1e-5f);
#pragma unroll
    for(int i=0;i<3;i++){
        int c=t+256*i;
        float o=(v[i]-mean)*r*gam[c]+bet[c];
        if(out) out[(size_t)n*CCH+c]=o;
        if(oh){
            bf16 hi=__float2bfloat16(o);
            oh[(size_t)n*CCH+c]=hi;
            ol[(size_t)n*CCH+c]=__float2bfloat16(o-__bfloat162float(hi));
        }
        if(of) of[(size_t)n*CCH+c]=__float2half(o);
    }
}

// ---- bf16 3-product GEMM (QKV + proj), 3-stage ----
#define PITCH 80
#define TILEB 10240
#define STAGEB 40960
#define SMEMSZ (3*STAGEB)
template<int EPI>
__global__ void __launch_bounds__(256,1)
k_mma(const bf16* __restrict__ Ah, const bf16* __restrict__ Al,
      const bf16* __restrict__ Bh, const bf16* __restrict__ Bl,
      const float* __restrict__ bias, const float* __restrict__ resid,
      float* __restrict__ out32, int M, int Nn, int K){
    int by = blockIdx.y, bx = blockIdx.x;
    extern __shared__ char smem[];
    uint32_t su = smem_u32(smem);
    int tid=threadIdx.x, lane=tid&31, wid=tid>>5;
    int wm=wid&3, wn=wid>>2;
    const int KT = K/32;
    float acc[2][8][4];
#pragma unroll
    for(int a=0;a<2;a++)
#pragma unroll
        for(int b=0;b<8;b++)
#pragma unroll
            for(int c=0;c<4;c++) acc[a][b][c]=0.f;
    auto load_stage = [&](int kt){
        uint32_t sb = su + (kt%3)*STAGEB;
#pragma unroll
        for(int i=0;i<8;i++){
            int c = tid + i*256;
            int tile=c>>9, w=c&511, row=w>>2, q=w&3;
            uint32_t d = sb + tile*TILEB + row*PITCH + q*16;
            const bf16* src;
            if(tile<2) src = (tile==0?Ah:Al) + (size_t)(by*128+row)*K + kt*32 + q*8;
            else       src = (tile==2?Bh:Bl) + (size_t)(bx*128+row)*K + kt*32 + q*8;
            cp16(d, src);
        }
        asm volatile("cp.async.commit_group;" ::: "memory");
    };
    load_stage(0);
    if(KT>1) load_stage(1);
    for(int kt=0; kt<KT; kt++){
        if(kt+2<KT) load_stage(kt+2);
        if(kt+2<KT)      asm volatile("cp.async.wait_group 2;" ::: "memory");
        else if(kt+1<KT) asm volatile("cp.async.wait_group 1;" ::: "memory");
        else             asm volatile("cp.async.wait_group 0;" ::: "memory");
        __syncthreads();
        uint32_t sb = su + (kt%3)*STAGEB;
#pragma unroll
        for(int kh=0; kh<2; kh++){
            uint32_t aH[2][4], aL[2][4];
            int arow = wm*32 + (lane&15);
            uint32_t ako = kh*32 + (lane>>4)*16;
#pragma unroll
            for(int mt=0;mt<2;mt++){
                uint32_t ad = sb + (arow+mt*16)*PITCH + ako;
                ldsm4(ad, aH[mt]); ldsm4(ad + TILEB, aL[mt]);
            }
            uint32_t bHf[4][4], bLf[4][4];
            int brow = wn*64 + ((lane&7) | ((lane&16)>>1));
            uint32_t bko = kh*32 + ((lane>>3)&1)*16;
#pragma unroll
            for(int nt=0;nt<4;nt++){
                uint32_t bd = sb + 2*TILEB + (brow+nt*16)*PITCH + bko;
                ldsm4(bd, bHf[nt]); ldsm4(bd + TILEB, bLf[nt]);
            }
#pragma unroll
            for(int mt=0;mt<2;mt++)
#pragma unroll
            for(int n8=0;n8<8;n8++){
                uint32_t* bh = &bHf[n8>>1][(n8&1)*2];
                uint32_t* bl = &bLf[n8>>1][(n8&1)*2];
                mma16816(acc[mt][n8], aH[mt], bh);
                mma16816(acc[mt][n8], aH[mt], bl);
                mma16816(acc[mt][n8], aL[mt], bh);
            }
        }
        __syncthreads();
    }
    int g = lane>>2, t4 = lane&3;
#pragma unroll
    for(int mt=0;mt<2;mt++)
#pragma unroll
    for(int n8=0;n8<8;n8++){
        int col = bx*128 + wn*64 + n8*8 + t4*2;
#pragma unroll
        for(int hf=0; hf<2; hf++){
            int row = by*128 + wm*32 + mt*16 + g + hf*8;
            float v0 = acc[mt][n8][hf*2+0];
            float v1 = acc[mt][n8][hf*2+1];
            if(EPI==0){
                int which = col/CCH, rem = col - which*CCH;
                int h = rem>>6, d0 = rem&63;
                int b = row>>10, t = row&1023;
                size_t o = ((size_t)(b*HH+h)*TT + t)*HSZ + d0;
                bf16* dh = which==0? g_qh : which==1? g_kh : g_vh;
                bf16* dl = which==0? g_ql : which==1? g_kl : g_vl;
                bf16 h0=__float2bfloat16(v0), h1=__float2bfloat16(v1);
                __nv_bfloat162 hp; hp.x=h0; hp.y=h1;
                __nv_bfloat162 lp;
                lp.x=__float2bfloat16(v0-__bfloat162float(h0));
                lp.y=__float2bfloat16(v1-__bfloat162float(h1));
                *reinterpret_cast<__nv_bfloat162*>(&dh[o]) = hp;
                *reinterpret_cast<__nv_bfloat162*>(&dl[o]) = lp;
            } else {
                size_t o=(size_t)row*Nn+col;
                out32[o]   = v0 + bias[col]   + resid[o];
                out32[o+1] = v1 + bias[col+1] + resid[o+1];
            }
        }
    }
}

// ---- fp16 2-product GEMM (experts), 4-stage, z-batched ----
#define HSTG 30720
#define HSMEM (4*HSTG)
template<int EPI>
__global__ void __launch_bounds__(256,1)
k_mmah(const f16* __restrict__ A1, size_t zsA, const f16* __restrict__ A2, size_t zsA2,
       int zSplitA,
       const f16* __restrict__ B1h, const f16* __restrict__ B1l,
       const f16* __restrict__ B2h, const f16* __restrict__ B2l, size_t zsB, int zSplit,
       const float* __restrict__ b1, const float* __restrict__ b2,
       float* __restrict__ out32, f16* __restrict__ outH, size_t zsOut,
       int M, int Nn, int K,
       const int* __restrict__ tok, const int* __restrict__ cnt){
    int z = blockIdx.z;
    if(cnt) M = cnt[z];
    int by = blockIdx.y, bx = blockIdx.x;
    if(by*128 >= M) return;
    const f16* A = (z < zSplitA) ? A1 + (size_t)z*zsA : A2 + (size_t)z*zsA2;
    const f16 *Bh, *Bl; const float* bias;
    if(z < zSplit){ Bh=B1h+(size_t)z*zsB; Bl=B1l+(size_t)z*zsB; bias=b1+(size_t)z*Nn; }
    else { Bh=B2h+(size_t)(z-zSplit)*zsB; Bl=B2l+(size_t)(z-zSplit)*zsB; bias=b2+(size_t)(z-zSplit)*Nn; }
    if(out32) out32 += (size_t)z*zsOut;
    if(outH)  outH  += (size_t)z*zsOut;
    if(tok) tok += (size_t)z*NT;
    extern __shared__ char smem[];
    uint32_t su = smem_u32(smem);
    int tid=threadIdx.x, lane=tid&31, wid=tid>>5;
    int wm=wid&3, wn=wid>>2;
    const int KT = K/32;
    float acc[2][8][4];
#pragma unroll
    for(int a=0;a<2;a++)
#pragma unroll
        for(int b=0;b<8;b++)
#pragma unroll
            for(int c=0;c<4;c++) acc[a][b][c]=0.f;
    auto load_stage = [&](int kt){
        uint32_t sb = su + (kt&3)*HSTG;
#pragma unroll
        for(int i=0;i<6;i++){
            int c = tid + i*256;
            int tile=c>>9, w=c&511, row=w>>2, q=w&3;
            uint32_t d = sb + tile*TILEB + row*PITCH + q*16;
            const f16* src;
            if(tile==0){
                int rg=by*128+row; if(rg>=M) rg=M-1;
                int asrc = tok ? tok[rg] : rg;
                src = A + (size_t)asrc*K + kt*32 + q*8;
            } else {
                src = (tile==1?Bh:Bl) + (size_t)(bx*128+row)*K + kt*32 + q*8;
            }
            cp16(d, src);
        }
        asm volatile("cp.async.commit_group;" ::: "memory");
    };
    load_stage(0);
    if(KT>1) load_stage(1);
    if(KT>2) load_stage(2);
    for(int kt=0; kt<KT; kt++){
        if(kt+3<KT) load_stage(kt+3);
        if(kt+3<KT)      asm volatile("cp.async.wait_group 3;" ::: "memory");
        else if(kt+2<KT) asm volatile("cp.async.wait_group 2;" ::: "memory");
        else if(kt+1<KT) asm volatile("cp.async.wait_group 1;" ::: "memory");
        else             asm volatile("cp.async.wait_group 0;" ::: "memory");
        __syncthreads();
        uint32_t sb = su + (kt&3)*HSTG;
#pragma unroll
        for(int kh=0; kh<2; kh++){
            uint32_t aF[2][4];
            int arow = wm*32 + (lane&15);
            uint32_t ako = kh*32 + (lane>>4)*16;
#pragma unroll
            for(int mt=0;mt<2;mt++)
                ldsm4(sb + (arow+mt*16)*PITCH + ako, aF[mt]);
            uint32_t bHf[4][4], bLf[4][4];
            int brow = wn*64 + ((lane&7) | ((lane&16)>>1));
            uint32_t bko = kh*32 + ((lane>>3)&1)*16;
#pragma unroll
            for(int nt=0;nt<4;nt++){
                uint32_t bd = sb + TILEB + (brow+nt*16)*PITCH + bko;
                ldsm4(bd, bHf[nt]); ldsm4(bd + TILEB, bLf[nt]);
            }
#pragma unroll
            for(int mt=0;mt<2;mt++)
#pragma unroll
            for(int n8=0;n8<8;n8++){
                mmah16816(acc[mt][n8], aF[mt], &bHf[n8>>1][(n8&1)*2]);
                mmah16816(acc[mt][n8], aF[mt], &bLf[n8>>1][(n8&1)*2]);
            }
        }
        __syncthreads();
    }
    int g = lane>>2, t4 = lane&3;
#pragma unroll
    for(int mt=0;mt<2;mt++)
#pragma unroll
    for(int n8=0;n8<8;n8++){
        int col = bx*128 + wn*64 + n8*8 + t4*2;
#pragma unroll
        for(int hf=0; hf<2; hf++){
            int row = by*128 + wm*32 + mt*16 + g + hf*8;
            if(row >= M) continue;
            float v0 = acc[mt][n8][hf*2+0];
            float v1 = acc[mt][n8][hf*2+1];
            size_t o=(size_t)row*Nn+col;
            if(EPI==2){
                __half2 hp;
                hp.x = __float2half(geluf(v0 + bias[col]));
                hp.y = __float2half(geluf(v1 + bias[col+1]));
                *reinterpret_cast<__half2*>(&outH[o]) = hp;
            } else {
                out32[o]   = v0 + bias[col];
                out32[o+1] = v1 + bias[col+1];
            }
        }
    }
}

// ---- flash attention v2 (fixed loads): 128-row q-tile, 256 thr,
//      cp.async double-buffered K/V, V row-major + ldmatrix.trans ----
#define FP2 144
#define QT (128*FP2)
#define KT2 (64*FP2)
#define STG2 (4*KT2)
#define FSM2 (2*QT + 2*STG2)
__global__ void __launch_bounds__(256,1) k_flash(){
    int tb = 7 - blockIdx.x, bh = blockIdx.y;
    extern __shared__ char fsm[];
    uint32_t su = smem_u32(fsm);
    uint32_t qb = su, kvb = su + 2*QT;
    int tid=threadIdx.x, lane=tid&31, w=tid>>5;
    const size_t hb = (size_t)bh*TT*HSZ;
    // Q: 2 halves x 128 rows x 8 chunks(16B) = 2048 cp16
#pragma unroll
    for(int i=0;i<8;i++){
        int c = tid + i*256;
        int half = c>>10, w2 = c&1023, row = w2>>3, q = w2&7;
        cp16(qb + half*QT + row*FP2 + q*16,
             (half? g_ql : g_qh) + hb + (size_t)(tb*128+row)*HSZ + q*8);
    }
    auto loadKV = [&](int sb){
        uint32_t base = kvb + (sb&1)*STG2;
        // 4 arrays x 64 rows x 8 chunks = 2048 cp16
#pragma unroll
        for(int i=0;i<8;i++){
            int c = tid + i*256;
            int arr = c>>9, w2 = c&511, row = w2>>3, q = w2&7;
            const bf16* src = (arr==0? g_kh : arr==1? g_kl : arr==2? g_vh : g_vl)
                            + hb + (size_t)(sb*64+row)*HSZ + q*8;
            cp16(base + arr*KT2 + row*FP2 + q*16, src);
        }
        asm volatile("cp.async.commit_group;" ::: "memory");
    };
    loadKV(0);
    float m0=-1e30f, m1=-1e30f, l0=0.f, l1=0.f;
    float O[8][4];
#pragma unroll
    for(int n8=0;n8<8;n8++)
#pragma unroll
        for(int c=0;c<4;c++) O[n8][c]=0.f;
    const float scale=0.036084391824351615f;
    int brow = (lane&7) | ((lane&16)>>1);
    int t4 = lane&3, g = lane>>2;
    int smax = 2*tb+1;
    for(int sb=0; sb<=smax; sb++){
        if(sb<smax) loadKV(sb+1);
        if(sb<smax) asm volatile("cp.async.wait_group 1;" ::: "memory");
        else        asm volatile("cp.async.wait_group 0;" ::: "memory");
        __syncthreads();
        uint32_t kb = kvb + (sb&1)*STG2;
        uint32_t vb = kb + 2*KT2;
        float S[8][4];
#pragma unroll
        for(int n8=0;n8<8;n8++)
#pragma unroll
            for(int c=0;c<4;c++) S[n8][c]=0.f;
#pragma unroll
        for(int kc=0;kc<4;kc++){
            uint32_t aH[4], aL[4];
            uint32_t ad = qb + (w*16+(lane&15))*FP2 + kc*32 + (lane>>4)*16;
            ldsm4(ad, aH); ldsm4(ad+QT, aL);
            uint32_t bHt[4][4], bLt[4][4];
#pragma unroll
            for(int nt=0;nt<4;nt++){
                uint32_t bd = kb + (nt*16+brow)*FP2 + kc*32 + ((lane>>3)&1)*16;
                ldsm4(bd, bHt[nt]); ldsm4(bd+KT2, bLt[nt]);
            }
#pragma unroll
            for(int n8=0;n8<8;n8++){
                uint32_t* bh2=&bHt[n8>>1][(n8&1)*2];
                uint32_t* bl2=&bLt[n8>>1][(n8&1)*2];
                mma16816(S[n8], aH, bh2);
                mma16816(S[n8], aH, bl2);
                mma16816(S[n8], aL, bh2);
            }
        }
        int rg0 = tb*128 + w*16 + g;
#pragma unroll
        for(int n8=0;n8<8;n8++)
#pragma unroll
            for(int c=0;c<4;c++){
                S[n8][c] *= scale;
                if(sb >= 2*tb){
                    int sg = sb*64 + n8*8 + t4*2 + (c&1);
                    int rg = rg0 + ((c>=2)?8:0);
                    if(sg > rg) S[n8][c] = -1e30f;
                }
            }
        float mx0=-1e30f, mx1=-1e30f;
#pragma unroll
        for(int n8=0;n8<8;n8++){
            mx0=fmaxf(mx0,fmaxf(S[n8][0],S[n8][1]));
            mx1=fmaxf(mx1,fmaxf(S[n8][2],S[n8][3]));
        }
        mx0=fmaxf(mx0,__shfl_xor_sync(~0u,mx0,1)); mx0=fmaxf(mx0,__shfl_xor_sync(~0u,mx0,2));
        mx1=fmaxf(mx1,__shfl_xor_sync(~0u,mx1,1)); mx1=fmaxf(mx1,__shfl_xor_sync(~0u,mx1,2));
        float mn0=fmaxf(m0,mx0), mn1=fmaxf(m1,mx1);
        float f0=expf(m0-mn0), f1=expf(m1-mn1);
        m0=mn0; m1=mn1;
        float rs0=0.f, rs1=0.f;
#pragma unroll
        for(int n8=0;n8<8;n8++){
            S[n8][0]=expf(S[n8][0]-mn0); S[n8][1]=expf(S[n8][1]-mn0);
            S[n8][2]=expf(S[n8][2]-mn1); S[n8][3]=expf(S[n8][3]-mn1);
            rs0+=S[n8][0]+S[n8][1]; rs1+=S[n8][2]+S[n8][3];
        }
        rs0+=__shfl_xor_sync(~0u,rs0,1); rs0+=__shfl_xor_sync(~0u,rs0,2);
        rs1+=__shfl_xor_sync(~0u,rs1,1); rs1+=__shfl_xor_sync(~0u,rs1,2);
        l0=l0*f0+rs0; l1=l1*f1+rs1;
#pragma unroll
        for(int n8=0;n8<8;n8++){
            O[n8][0]*=f0; O[n8][1]*=f0; O[n8][2]*=f1; O[n8][3]*=f1;
        }
#pragma unroll
        for(int j=0;j<4;j++){
            float p00=S[2*j][0], p01=S[2*j][1], p02=S[2*j][2], p03=S[2*j][3];
            float p10=S[2*j+1][0], p11=S[2*j+1][1], p12=S[2*j+1][2], p13=S[2*j+1][3];
            uint32_t aPh[4], aPl[4];
            aPh[0]=packbf(p00,p01); aPh[1]=packbf(p02,p03);
            aPh[2]=packbf(p10,p11); aPh[3]=packbf(p12,p13);
            {
                __nv_bfloat162 t;
                t=*(__nv_bfloat162*)&aPh[0];
                aPl[0]=packbf(p00-__bfloat162float(t.x), p01-__bfloat162float(t.y));
                t=*(__nv_bfloat162*)&aPh[1];
                aPl[1]=packbf(p02-__bfloat162float(t.x), p03-__bfloat162float(t.y));
                t=*(__nv_bfloat162*)&aPh[2];
                aPl[2]=packbf(p10-__bfloat162float(t.x), p11-__bfloat162float(t.y));
                t=*(__nv_bfloat162*)&aPh[3];
                aPl[3]=packbf(p12-__bfloat162float(t.x), p13-__bfloat162float(t.y));
            }
            uint32_t bHt[4][4], bLt[4][4];
            uint32_t vrow = (j*16 + (lane&15))*FP2 + (lane>>4)*16;
#pragma unroll
            for(int nt=0;nt<4;nt++){
                uint32_t bd = vb + vrow + nt*32;
                ldsm4t(bd, bHt[nt]); ldsm4t(bd+KT2, bLt[nt]);
            }
#pragma unroll
            for(int n8=0;n8<8;n8++){
                uint32_t* bh2=&bHt[n8>>1][(n8&1)*2];
                uint32_t* bl2=&bLt[n8>>1][(n8&1)*2];
                mma16816(O[n8], aPh, bh2);
                mma16816(O[n8], aPh, bl2);
                mma16816(O[n8], aPl, bh2);
            }
        }
        __syncthreads();
    }
    float i0=1.f/l0, i1=1.f/l1;
    int b = bh/HH, h = bh%HH;
#pragma unroll
    for(int n8=0;n8<8;n8++){
        int col = h*64 + n8*8 + t4*2;
#pragma unroll
        for(int hf=0;hf<2;hf++){
            int tokr = b*1024 + tb*128 + w*16 + g + hf*8;
            float v0 = O[n8][hf*2+0]*(hf?i1:i0);
            float v1 = O[n8][hf*2+1]*(hf?i1:i0);
            size_t o=(size_t)tokr*CCH+col;
            bf16 h0=__float2bfloat16(v0), h1=__float2bfloat16(v1);
            __nv_bfloat162 hp2; hp2.x=h0; hp2.y=h1;
            __nv_bfloat162 lp;
            lp.x=__float2bfloat16(v0-__bfloat162float(h0));
            lp.y=__float2bfloat16(v1-__bfloat162float(h1));
            *reinterpret_cast<__nv_bfloat162*>(&g_aoh[o]) = hp2;
            *reinterpret_cast<__nv_bfloat162*>(&g_aol[o]) = lp;
        }
    }
}

__global__ void k_router(const float* __restrict__ wr, const float* __restrict__ br,
                         const float* __restrict__ wn, const float* __restrict__ bnn,
                         const float* __restrict__ temp, const float* __restrict__ noise){
    int warp=threadIdx.x>>5, lane=threadIdx.x&31;
    int n=blockIdx.x*8+warp;
    const float* hp = g_h2 + (size_t)n*CCH;
    float r[8]={}, q[8]={};
    for(int c=lane;c<CCH;c+=32){
        float hv=hp[c];
        const float* wrp=wr+c*EE; const float* wnp=wn+c*EE;
#pragma unroll
        for(int e=0;e<8;e++){ r[e]+=hv*wrp[e]; q[e]+=hv*wnp[e]; }
    }
#pragma unroll
    for(int e=0;e<8;e++)
#pragma unroll
        for(int o=16;o;o>>=1){
            r[e]+=__shfl_xor_sync(~0u,r[e],o);
            q[e]+=__shfl_xor_sync(~0u,q[e],o);
        }
    if(lane==0){
        float t=fminf(fmaxf(temp[0],0.5f),2.0f);
        float ny[8];
#pragma unroll
        for(int e=0;e<8;e++){
            float z=q[e]+bnn[e];
            float sp=(z>20.f)? z : log1pf(expf(z));
            ny[e]=r[e]+br[e] + t*noise[(size_t)n*EE+e]*sp;
        }
        int i1=0;
#pragma unroll
        for(int e=1;e<8;e++) if(ny[e]>ny[i1]) i1=e;
        int i2=-1;
#pragma unroll
        for(int e=0;e<8;e++){ if(e==i1) continue; if(i2<0||ny[e]>ny[i2]) i2=e; }
        float e2=expf(ny[i2]-ny[i1]);
        float gv[2]={1.f/(1.f+e2), e2/(1.f+e2)};
        int id[2]={i1,i2};
#pragma unroll
        for(int k2=0;k2<2;k2++){
            int e=id[k2];
            int row=atomicAdd(&g_cnt[e],1);
            g_tok[e*NT+row]=n;
            g_pos[n*2+k2]=e*NT+row;
            g_gw[n*2+k2]=gv[k2];
        }
    }
}

// fused dual residual-LN + gated combine
__global__ void k_fin(const float* __restrict__ t3,
                      const float* __restrict__ dg, const float* __restrict__ db_,
                      const float* __restrict__ sg, const float* __restrict__ sb_,
                      float* __restrict__ out){
    int n=blockIdx.x, t=threadIdx.x;
    int s0=g_pos[2*n], s1=g_pos[2*n+1];
    int e0=s0>>13, r0=s0&8191, e1=s1>>13, r1=s1&8191;
    const float* ta = t3 + (size_t)e0*NT*CCH + (size_t)r0*CCH;
    const float* tb = t3 + (size_t)e1*NT*CCH + (size_t)r1*CCH;
    float va[3], vb[3];
    float sa=0.f,qa=0.f,sb2=0.f,qb=0.f;
#pragma unroll
    for(int i=0;i<3;i++){
        int c=t+256*i;
        float h = g_h2[(size_t)n*CCH+c];
        va[i]=h+ta[c]; vb[i]=h+tb[c];
        sa+=va[i]; qa+=va[i]*va[i]; sb2+=vb[i]; qb+=vb[i]*vb[i];
    }
    __shared__ float sh[8][4];
#pragma unroll
    for(int o=16;o;o>>=1){
        sa+=__shfl_xor_sync(~0u,sa,o); qa+=__shfl_xor_sync(~0u,qa,o);
        sb2+=__shfl_xor_sync(~0u,sb2,o); qb+=__shfl_xor_sync(~0u,qb,o);
    }
    if((t&31)==0){ sh[t>>5][0]=sa; sh[t>>5][1]=qa; sh[t>>5][2]=sb2; sh[t>>5][3]=qb; }
    __syncthreads();
    sa=0.f; qa=0.f; sb2=0.f; qb=0.f;
#pragma unroll
    for(int i=0;i<8;i++){ sa+=sh[i][0]; qa+=sh[i][1]; sb2+=sh[i][2]; qb+=sh[i][3]; }
    float ma=sa*(1.f/768.f), ra=rsqrtf(qa*(1.f/768.f)-ma*ma+1e-5f);
    float mb=sb2*(1.f/768.f), rb=rsqrtf(qb*(1.f/768.f)-mb*mb+1e-5f);
    const float* g0p = (e0<2)? dg+e0*CCH : sg+(e0-2)*CCH;
    const float* b0p = (e0<2)? db_+e0*CCH : sb_+(e0-2)*CCH;
    const float* g1p = (e1<2)? dg+e1*CCH : sg+(e1-2)*CCH;
    const float* b1p = (e1<2)? db_+e1*CCH : sb_+(e1-2)*CCH;
    float gw0=g_gw[2*n], gw1=g_gw[2*n+1];
#pragma unroll
    for(int i=0;i<3;i++){
        int c=t+256*i;
        float o0=(va[i]-ma)*ra*g0p[c]+b0p[c];
        float o1=(vb[i]-mb)*rb*g1p[c]+b1p[c];
        out[(size_t)n*CCH+c]=g_x2[(size_t)n*CCH+c]+gw0*o0+gw1*o1;
    }
}

extern "C" void kernel_launch(void* const* d_in, const int* in_sizes, int n_in,
                              void* d_out, int out_size){
    const float *x=(const float*)d_in[0], *rno=(const float*)d_in[1];
    const float *wq=(const float*)d_in[2], *wk=(const float*)d_in[3], *wv=(const float*)d_in[4];
    const float *w_proj=(const float*)d_in[5], *b_proj=(const float*)d_in[6];
    const float *ln1g=(const float*)d_in[7], *ln1b=(const float*)d_in[8];
    const float *ln2g=(const float*)d_in[9], *ln2b=(const float*)d_in[10];
    const float *wr=(const float*)d_in[11], *br=(const float*)d_in[12];
    const float *wn=(const float*)d_in[13], *bn=(const float*)d_in[14];
    const float *temp=(const float*)d_in[15];
    const float *dw1=(const float*)d_in[16], *db1=(const float*)d_in[17];
    const float *dw2=(const float*)d_in[18], *db2=(const float*)d_in[19];
    const float *dw3=(const float*)d_in[20], *db3=(const float*)d_in[21];
    const float *dlng=(const float*)d_in[22], *dlnb=(const float*)d_in[23];
    const float *sw1=(const float*)d_in[24], *sb1=(const float*)d_in[25];
    const float *sw2=(const float*)d_in[26], *sb2=(const float*)d_in[27];
    const float *slng=(const float*)d_in[28], *slnb=(const float*)d_in[29];
    float* out=(float*)d_out;

    cudaFuncSetAttribute(k_mma<0>, cudaFuncAttributeMaxDynamicSharedMemorySize, SMEMSZ);
    cudaFuncSetAttribute(k_mma<1>, cudaFuncAttributeMaxDynamicSharedMemorySize, SMEMSZ);
    cudaFuncSetAttribute(k_mmah<2>, cudaFuncAttributeMaxDynamicSharedMemorySize, HSMEM);
    cudaFuncSetAttribute(k_mmah<3>, cudaFuncAttributeMaxDynamicSharedMemorySize, HSMEM);
    cudaFuncSetAttribute(k_flash, cudaFuncAttributeMaxDynamicSharedMemorySize, FSM2);

    bf16 *Bqh,*Bql,*Bph,*Bpl,*h1h,*h1l,*aoh,*aol;
    f16 *Bd1h,*Bd1l,*Bd2h,*Bd2l,*Bd3h,*Bd3l,*Bs1h,*Bs1l,*Bs2h,*Bs2l,*h2f,*t1f,*t2f;
    float *x2,*h2,*t3; int *tok,*cnt;
    cudaGetSymbolAddress((void**)&Bqh,g_Bqh); cudaGetSymbolAddress((void**)&Bql,g_Bql);
    cudaGetSymbolAddress((void**)&Bph,g_Bph); cudaGetSymbolAddress((void**)&Bpl,g_Bpl);
    cudaGetSymbolAddress((void**)&Bd1h,g_Bd1h); cudaGetSymbolAddress((void**)&Bd1l,g_Bd1l);
    cudaGetSymbolAddress((void**)&Bd2h,g_Bd2h); cudaGetSymbolAddress((void**)&Bd2l,g_Bd2l);
    cudaGetSymbolAddress((void**)&Bd3h,g_Bd3h); cudaGetSymbolAddress((void**)&Bd3l,g_Bd3l);
    cudaGetSymbolAddress((void**)&Bs1h,g_Bs1h); cudaGetSymbolAddress((void**)&Bs1l,g_Bs1l);
    cudaGetSymbolAddress((void**)&Bs2h,g_Bs2h); cudaGetSymbolAddress((void**)&Bs2l,g_Bs2l);
    cudaGetSymbolAddress((void**)&h1h,g_h1h); cudaGetSymbolAddress((void**)&h1l,g_h1l);
    cudaGetSymbolAddress((void**)&aoh,g_aoh); cudaGetSymbolAddress((void**)&aol,g_aol);
    cudaGetSymbolAddress((void**)&h2f,g_h2f);
    cudaGetSymbolAddress((void**)&t1f,g_t1f); cudaGetSymbolAddress((void**)&t2f,g_t2f);
    cudaGetSymbolAddress((void**)&x2,g_x2); cudaGetSymbolAddress((void**)&h2,g_h2);
    cudaGetSymbolAddress((void**)&t3,g_t3);
    cudaGetSymbolAddress((void**)&tok,g_tok); cudaGetSymbolAddress((void**)&cnt,g_cnt);
    const size_t ZT1=(size_t)NT*FF, ZT3=(size_t)NT*CCH;

    dim3 wb(32,8);
    k_reset<<<1,32>>>();
    k_wsplit2<bf16><<<dim3(2,12,12),wb>>>(wq, Bqh,           Bql,           CCH, HSZ);
    k_wsplit2<bf16><<<dim3(2,12,12),wb>>>(wk, Bqh+CCH*CCH,   Bql+CCH*CCH,   CCH, HSZ);
    k_wsplit2<bf16><<<dim3(2,12,12),wb>>>(wv, Bqh+2*CCH*CCH, Bql+2*CCH*CCH, CCH, HSZ);
    k_wsplit2<bf16><<<dim3(24,12,1),wb>>>(w_proj, Bph, Bpl, CCH, CCH);
    k_wsplit2<f16><<<dim3(96,12,2),wb>>>(dw1, Bd1h, Bd1l, CCH, FF);
    k_wsplit2<f16><<<dim3(96,48,2),wb>>>(dw2, Bd2h, Bd2l, FF, FF);
    k_wsplit2<f16><<<dim3(24,48,2),wb>>>(dw3, Bd3h, Bd3l, FF, CCH);
    k_wsplit2<f16><<<dim3(96,12,6),wb>>>(sw1, Bs1h, Bs1l, CCH, FF);
    k_wsplit2<f16><<<dim3(24,48,6),wb>>>(sw2, Bs2h, Bs2l, FF, CCH);
    // attention
    k_ln<<<NT,256>>>(x, ln1g, ln1b, nullptr, h1h, h1l, nullptr);
    k_mma<0><<<dim3(18,64),256,SMEMSZ>>>(h1h,h1l,Bqh,Bql,nullptr,nullptr,nullptr,
                                         NT,3*CCH,CCH);
    k_flash<<<dim3(8,BH),256,FSM2>>>();
    k_mma<1><<<dim3(6,64),256,SMEMSZ>>>(aoh,aol,Bph,Bpl,b_proj,x,x2, NT,CCH,CCH);
    // router
    k_ln<<<NT,256>>>(x2, ln2g, ln2b, h2, nullptr, nullptr, h2f);
    k_router<<<NT/8,256>>>(wr,br,wn,bn,temp,rno);
    // experts
    k_mmah<2><<<dim3(24,64,8),256,HSMEM>>>(h2f,0, nullptr,0, 99,
        Bd1h,Bd1l, Bs1h,Bs1l,(size_t)CCH*FF, 2, db1,sb1,
        nullptr, t1f, ZT1, NT,FF,CCH, tok, cnt);
    k_mmah<2><<<dim3(24,64,2),256,HSMEM>>>(t1f,ZT1, nullptr,0, 99,
        Bd2h,Bd2l, nullptr,nullptr,(size_t)FF*FF, 99, db2,nullptr,
        nullptr, t2f, ZT1, NT,FF,FF, nullptr, cnt);
    k_mmah<3><<<dim3(6,64,8),256,HSMEM>>>(t2f,ZT1, t1f,ZT1, 2,
        Bd3h,Bd3l, Bs2h,Bs2l,(size_t)CCH*FF, 2, db3,sb2,
        t3, nullptr, ZT3, NT,CCH,FF, nullptr, cnt);
    k_fin<<<NT,256>>>(t3, dlng, dlnb, slng, slnb, out);
}

// round 10
// speedup vs baseline: 5.7146x; 1.2585x over previous
#include <cuda_runtime.h>
#include <cuda_bf16.h>
#include <cuda_fp16.h>
#include <stdint.h>
#include <math.h>

#define BN 8
#define TT 1024
#define CCH 768
#define HH 12
#define HSZ 64
#define EE 8
#define FF 3072
#define NT (BN*TT)
#define BH (BN*HH)
typedef __nv_bfloat16 bf16;
typedef __half f16;

// ---- static scratch ----
__device__ bf16  g_qh[BH*TT*HSZ], g_ql[BH*TT*HSZ];
__device__ bf16  g_kh[BH*TT*HSZ], g_kl[BH*TT*HSZ];
__device__ bf16  g_vh[BH*TT*HSZ], g_vl[BH*TT*HSZ];
__device__ bf16  g_h1h[NT*CCH], g_h1l[NT*CCH];
__device__ bf16  g_aoh[NT*CCH], g_aol[NT*CCH];
__device__ float g_x2[NT*CCH];
__device__ float g_h2[NT*CCH];
__device__ f16   g_h2f[NT*CCH];
__device__ float g_gw[NT*2];
__device__ int   g_pos[NT*2];
__device__ int   g_tok[EE*NT];
__device__ int   g_cnt[EE];
__device__ f16   g_t1f[(size_t)EE*NT*FF];
__device__ f16   g_t2f[(size_t)2*NT*FF];
__device__ float g_t3[(size_t)EE*NT*CCH];
__device__ bf16  g_Bqh[3*CCH*CCH], g_Bql[3*CCH*CCH];
__device__ bf16  g_Bph[CCH*CCH],  g_Bpl[CCH*CCH];
__device__ f16   g_Bd1[2*CCH*FF];
__device__ f16   g_Bd2[(size_t)2*FF*FF];
__device__ f16   g_Bd3[2*CCH*FF];
__device__ f16   g_Bs1[(size_t)6*CCH*FF];
__device__ f16   g_Bs2[(size_t)6*CCH*FF];

__device__ __forceinline__ float geluf(float v){
    return 0.5f*v*(1.f + erff(v*0.70710678118654752440f));
}
__device__ __forceinline__ uint32_t smem_u32(const void* p){
    uint32_t a;
    asm("{ .reg .u64 t; cvta.to.shared.u64 t, %1; cvt.u32.u64 %0, t; }" : "=r"(a) : "l"(p));
    return a;
}
__device__ __forceinline__ void cp16(uint32_t d, const void* s){
    asm volatile("cp.async.cg.shared.global [%0], [%1], 16;" :: "r"(d), "l"(s));
}
__device__ __forceinline__ void ldsm4(uint32_t a, uint32_t* r){
    asm volatile("ldmatrix.sync.aligned.m8n8.x4.shared.b16 {%0,%1,%2,%3}, [%4];"
        : "=r"(r[0]),"=r"(r[1]),"=r"(r[2]),"=r"(r[3]) : "r"(a));
}
__device__ __forceinline__ void ldsm4t(uint32_t a, uint32_t* r){
    asm volatile("ldmatrix.sync.aligned.m8n8.x4.trans.shared.b16 {%0,%1,%2,%3}, [%4];"
        : "=r"(r[0]),"=r"(r[1]),"=r"(r[2]),"=r"(r[3]) : "r"(a));
}
__device__ __forceinline__ void mma16816(float* c, const uint32_t* a, const uint32_t* b){
    asm volatile("mma.sync.aligned.m16n8k16.row.col.f32.bf16.bf16.f32 "
        "{%0,%1,%2,%3},{%4,%5,%6,%7},{%8,%9},{%0,%1,%2,%3};"
        : "+f"(c[0]),"+f"(c[1]),"+f"(c[2]),"+f"(c[3])
        : "r"(a[0]),"r"(a[1]),"r"(a[2]),"r"(a[3]), "r"(b[0]),"r"(b[1]));
}
__device__ __forceinline__ void mmah16816(float* c, const uint32_t* a, const uint32_t* b){
    asm volatile("mma.sync.aligned.m16n8k16.row.col.f32.f16.f16.f32 "
        "{%0,%1,%2,%3},{%4,%5,%6,%7},{%8,%9},{%0,%1,%2,%3};"
        : "+f"(c[0]),"+f"(c[1]),"+f"(c[2]),"+f"(c[3])
        : "r"(a[0]),"r"(a[1]),"r"(a[2]),"r"(a[3]), "r"(b[0]),"r"(b[1]));
}
__device__ __forceinline__ uint32_t packbf(float a, float b){
    __nv_bfloat162 p; p.x=__float2bfloat16(a); p.y=__float2bfloat16(b);
    return *reinterpret_cast<uint32_t*>(&p);
}

__global__ void k_reset(){ if(threadIdx.x < EE) g_cnt[threadIdx.x] = 0; }

// W[K][N] -> out[N][K] hi/lo bf16 (attention weights)
__global__ void k_wsplit2(const float* __restrict__ W, bf16* __restrict__ oh,
                          bf16* __restrict__ ol, int K, int N){
    int e = blockIdx.z;
    W += (size_t)e*K*N; oh += (size_t)e*K*N; ol += (size_t)e*K*N;
    __shared__ float s[64][33];
    int n0 = blockIdx.x*32, k0 = blockIdx.y*64;
    int tx = threadIdx.x, ty = threadIdx.y;
#pragma unroll
    for(int r=0;r<8;r++){ int kk=ty+r*8; s[kk][tx] = W[(size_t)(k0+kk)*N + n0+tx]; }
    __syncthreads();
#pragma unroll
    for(int r=0;r<4;r++){
        int n = ty + r*8;
        float v0 = s[2*tx][n], v1 = s[2*tx+1][n];
        bf16 h0 = __float2bfloat16(v0), h1 = __float2bfloat16(v1);
        bf16 hh[2] = {h0, h1};
        bf16 ll[2] = {__float2bfloat16(v0-__bfloat162float(h0)),
                      __float2bfloat16(v1-__bfloat162float(h1))};
        size_t o = (size_t)(n0+n)*K + k0 + 2*tx;
        *reinterpret_cast<uint32_t*>(&oh[o]) = *reinterpret_cast<uint32_t*>(hh);
        *reinterpret_cast<uint32_t*>(&ol[o]) = *reinterpret_cast<uint32_t*>(ll);
    }
}

// W[K][N] -> out[N][K] single fp16 (expert weights)
__global__ void k_wcvt(const float* __restrict__ W, f16* __restrict__ oh, int K, int N){
    int e = blockIdx.z;
    W += (size_t)e*K*N; oh += (size_t)e*K*N;
    __shared__ float s[64][33];
    int n0 = blockIdx.x*32, k0 = blockIdx.y*64;
    int tx = threadIdx.x, ty = threadIdx.y;
#pragma unroll
    for(int r=0;r<8;r++){ int kk=ty+r*8; s[kk][tx] = W[(size_t)(k0+kk)*N + n0+tx]; }
    __syncthreads();
#pragma unroll
    for(int r=0;r<4;r++){
        int n = ty + r*8;
        __half2 hp; hp.x=__float2half(s[2*tx][n]); hp.y=__float2half(s[2*tx+1][n]);
        size_t o = (size_t)(n0+n)*K + k0 + 2*tx;
        *reinterpret_cast<__half2*>(&oh[o]) = hp;
    }
}

__global__ void k_ln(const float* __restrict__ in, const float* __restrict__ gam,
                     const float* __restrict__ bet, float* __restrict__ out,
                     bf16* __restrict__ oh, bf16* __restrict__ ol, f16* __restrict__ of){
    int n = blockIdx.x, t = threadIdx.x;
    const float* row = in + (size_t)n*CCH;
    float v[3], s=0.f, s2=0.f;
#pragma unroll
    for(int i=0;i<3;i++){ v[i]=row[t+256*i]; s+=v[i]; s2+=v[i]*v[i]; }
    __shared__ float shs[8], shq[8];
#pragma unroll
    for(int o=16;o;o>>=1){ s+=__shfl_xor_sync(~0u,s,o); s2+=__shfl_xor_sync(~0u,s2,o); }
    if((t&31)==0){ shs[t>>5]=s; shq[t>>5]=s2; }
    __syncthreads();
    s=0.f; s2=0.f;
#pragma unroll
    for(int i=0;i<8;i++){ s+=shs[i]; s2+=shq[i]; }
    float mean=s*(1.f/768.f), var=s2*(1.f/768.f)-mean*mean, r=rsqrtf(var+1e-5f);
#pragma unroll
    for(int i=0;i<3;i++){
        int c=t+256*i;
        float o=(v[i]-mean)*r*gam[c]+bet[c];
        if(out) out[(size_t)n*CCH+c]=o;
        if(oh){
            bf16 hi=__float2bfloat16(o);
            oh[(size_t)n*CCH+c]=hi;
            ol[(size_t)n*CCH+c]=__float2bfloat16(o-__bfloat162float(hi));
        }
        if(of) of[(size_t)n*CCH+c]=__float2half(o);
    }
}

// ---- bf16 3-product GEMM (QKV + proj), 3-stage ----
#define PITCH 80
#define TILEB 10240
#define STAGEB 40960
#define SMEMSZ (3*STAGEB)
template<int EPI>
__global__ void __launch_bounds__(256,1)
k_mma(const bf16* __restrict__ Ah, const bf16* __restrict__ Al,
      const bf16* __restrict__ Bh, const bf16* __restrict__ Bl,
      const float* __restrict__ bias, const float* __restrict__ resid,
      float* __restrict__ out32, int M, int Nn, int K){
    int by = blockIdx.y, bx = blockIdx.x;
    extern __shared__ char smem[];
    uint32_t su = smem_u32(smem);
    int tid=threadIdx.x, lane=tid&31, wid=tid>>5;
    int wm=wid&3, wn=wid>>2;
    const int KT = K/32;
    float acc[2][8][4];
#pragma unroll
    for(int a=0;a<2;a++)
#pragma unroll
        for(int b=0;b<8;b++)
#pragma unroll
            for(int c=0;c<4;c++) acc[a][b][c]=0.f;
    auto load_stage = [&](int kt){
        uint32_t sb = su + (kt%3)*STAGEB;
#pragma unroll
        for(int i=0;i<8;i++){
            int c = tid + i*256;
            int tile=c>>9, w=c&511, row=w>>2, q=w&3;
            uint32_t d = sb + tile*TILEB + row*PITCH + q*16;
            const bf16* src;
            if(tile<2) src = (tile==0?Ah:Al) + (size_t)(by*128+row)*K + kt*32 + q*8;
            else       src = (tile==2?Bh:Bl) + (size_t)(bx*128+row)*K + kt*32 + q*8;
            cp16(d, src);
        }
        asm volatile("cp.async.commit_group;" ::: "memory");
    };
    load_stage(0);
    if(KT>1) load_stage(1);
    for(int kt=0; kt<KT; kt++){
        if(kt+2<KT) load_stage(kt+2);
        if(kt+2<KT)      asm volatile("cp.async.wait_group 2;" ::: "memory");
        else if(kt+1<KT) asm volatile("cp.async.wait_group 1;" ::: "memory");
        else             asm volatile("cp.async.wait_group 0;" ::: "memory");
        __syncthreads();
        uint32_t sb = su + (kt%3)*STAGEB;
#pragma unroll
        for(int kh=0; kh<2; kh++){
            uint32_t aH[2][4], aL[2][4];
            int arow = wm*32 + (lane&15);
            uint32_t ako = kh*32 + (lane>>4)*16;
#pragma unroll
            for(int mt=0;mt<2;mt++){
                uint32_t ad = sb + (arow+mt*16)*PITCH + ako;
                ldsm4(ad, aH[mt]); ldsm4(ad + TILEB, aL[mt]);
            }
            uint32_t bHf[4][4], bLf[4][4];
            int brow = wn*64 + ((lane&7) | ((lane&16)>>1));
            uint32_t bko = kh*32 + ((lane>>3)&1)*16;
#pragma unroll
            for(int nt=0;nt<4;nt++){
                uint32_t bd = sb + 2*TILEB + (brow+nt*16)*PITCH + bko;
                ldsm4(bd, bHf[nt]); ldsm4(bd + TILEB, bLf[nt]);
            }
#pragma unroll
            for(int mt=0;mt<2;mt++)
#pragma unroll
            for(int n8=0;n8<8;n8++){
                uint32_t* bh = &bHf[n8>>1][(n8&1)*2];
                uint32_t* bl = &bLf[n8>>1][(n8&1)*2];
                mma16816(acc[mt][n8], aH[mt], bh);
                mma16816(acc[mt][n8], aH[mt], bl);
                mma16816(acc[mt][n8], aL[mt], bh);
            }
        }
        __syncthreads();
    }
    int g = lane>>2, t4 = lane&3;
#pragma unroll
    for(int mt=0;mt<2;mt++)
#pragma unroll
    for(int n8=0;n8<8;n8++){
        int col = bx*128 + wn*64 + n8*8 + t4*2;
#pragma unroll
        for(int hf=0; hf<2; hf++){
            int row = by*128 + wm*32 + mt*16 + g + hf*8;
            float v0 = acc[mt][n8][hf*2+0];
            float v1 = acc[mt][n8][hf*2+1];
            if(EPI==0){
                int which = col/CCH, rem = col - which*CCH;
                int h = rem>>6, d0 = rem&63;
                int b = row>>10, t = row&1023;
                size_t o = ((size_t)(b*HH+h)*TT + t)*HSZ + d0;
                bf16* dh = which==0? g_qh : which==1? g_kh : g_vh;
                bf16* dl = which==0? g_ql : which==1? g_kl : g_vl;
                bf16 h0=__float2bfloat16(v0), h1=__float2bfloat16(v1);
                __nv_bfloat162 hp; hp.x=h0; hp.y=h1;
                __nv_bfloat162 lp;
                lp.x=__float2bfloat16(v0-__bfloat162float(h0));
                lp.y=__float2bfloat16(v1-__bfloat162float(h1));
                *reinterpret_cast<__nv_bfloat162*>(&dh[o]) = hp;
                *reinterpret_cast<__nv_bfloat162*>(&dl[o]) = lp;
            } else {
                size_t o=(size_t)row*Nn+col;
                out32[o]   = v0 + bias[col]   + resid[o];
                out32[o+1] = v1 + bias[col+1] + resid[o+1];
            }
        }
    }
}

// ---- fp16 single-product GEMM (experts), 4-stage, z-batched ----
#define HSTG (2*TILEB)
#define HSMEM (4*HSTG)
template<int EPI>
__global__ void __launch_bounds__(256,1)
k_mmah(const f16* __restrict__ A1, size_t zsA, const f16* __restrict__ A2, size_t zsA2,
       int zSplitA,
       const f16* __restrict__ B1, const f16* __restrict__ B2, size_t zsB, int zSplit,
       const float* __restrict__ b1, const float* __restrict__ b2,
       float* __restrict__ out32, f16* __restrict__ outH, size_t zsOut,
       int M, int Nn, int K,
       const int* __restrict__ tok, const int* __restrict__ cnt){
    int z = blockIdx.z;
    if(cnt) M = cnt[z];
    int by = blockIdx.y, bx = blockIdx.x;
    if(by*128 >= M) return;
    const f16* A = (z < zSplitA) ? A1 + (size_t)z*zsA : A2 + (size_t)z*zsA2;
    const f16* Bp; const float* bias;
    if(z < zSplit){ Bp=B1+(size_t)z*zsB; bias=b1+(size_t)z*Nn; }
    else { Bp=B2+(size_t)(z-zSplit)*zsB; bias=b2+(size_t)(z-zSplit)*Nn; }
    if(out32) out32 += (size_t)z*zsOut;
    if(outH)  outH  += (size_t)z*zsOut;
    if(tok) tok += (size_t)z*NT;
    extern __shared__ char smem[];
    uint32_t su = smem_u32(smem);
    int tid=threadIdx.x, lane=tid&31, wid=tid>>5;
    int wm=wid&3, wn=wid>>2;
    const int KT = K/32;
    float acc[2][8][4];
#pragma unroll
    for(int a=0;a<2;a++)
#pragma unroll
        for(int b=0;b<8;b++)
#pragma unroll
            for(int c=0;c<4;c++) acc[a][b][c]=0.f;
    auto load_stage = [&](int kt){
        uint32_t sb = su + (kt&3)*HSTG;
#pragma unroll
        for(int i=0;i<4;i++){
            int c = tid + i*256;
            int tile=c>>9, w=c&511, row=w>>2, q=w&3;
            uint32_t d = sb + tile*TILEB + row*PITCH + q*16;
            const f16* src;
            if(tile==0){
                int rg=by*128+row; if(rg>=M) rg=M-1;
                int asrc = tok ? tok[rg] : rg;
                src = A + (size_t)asrc*K + kt*32 + q*8;
            } else {
                src = Bp + (size_t)(bx*128+row)*K + kt*32 + q*8;
            }
            cp16(d, src);
        }
        asm volatile("cp.async.commit_group;" ::: "memory");
    };
    load_stage(0);
    if(KT>1) load_stage(1);
    if(KT>2) load_stage(2);
    for(int kt=0; kt<KT; kt++){
        if(kt+3<KT) load_stage(kt+3);
        if(kt+3<KT)      asm volatile("cp.async.wait_group 3;" ::: "memory");
        else if(kt+2<KT) asm volatile("cp.async.wait_group 2;" ::: "memory");
        else if(kt+1<KT) asm volatile("cp.async.wait_group 1;" ::: "memory");
        else             asm volatile("cp.async.wait_group 0;" ::: "memory");
        __syncthreads();
        uint32_t sb = su + (kt&3)*HSTG;
#pragma unroll
        for(int kh=0; kh<2; kh++){
            uint32_t aF[2][4];
            int arow = wm*32 + (lane&15);
            uint32_t ako = kh*32 + (lane>>4)*16;
#pragma unroll
            for(int mt=0;mt<2;mt++)
                ldsm4(sb + (arow+mt*16)*PITCH + ako, aF[mt]);
            uint32_t bF[4][4];
            int brow = wn*64 + ((lane&7) | ((lane&16)>>1));
            uint32_t bko = kh*32 + ((lane>>3)&1)*16;
#pragma unroll
            for(int nt=0;nt<4;nt++)
                ldsm4(sb + TILEB + (brow+nt*16)*PITCH + bko, bF[nt]);
#pragma unroll
            for(int mt=0;mt<2;mt++)
#pragma unroll
            for(int n8=0;n8<8;n8++)
                mmah16816(acc[mt][n8], aF[mt], &bF[n8>>1][(n8&1)*2]);
        }
        __syncthreads();
    }
    int g = lane>>2, t4 = lane&3;
#pragma unroll
    for(int mt=0;mt<2;mt++)
#pragma unroll
    for(int n8=0;n8<8;n8++){
        int col = bx*128 + wn*64 + n8*8 + t4*2;
#pragma unroll
        for(int hf=0; hf<2; hf++){
            int row = by*128 + wm*32 + mt*16 + g + hf*8;
            if(row >= M) continue;
            float v0 = acc[mt][n8][hf*2+0];
            float v1 = acc[mt][n8][hf*2+1];
            size_t o=(size_t)row*Nn+col;
            if(EPI==2){
                __half2 hp;
                hp.x = __float2half(geluf(v0 + bias[col]));
                hp.y = __float2half(geluf(v1 + bias[col+1]));
                *reinterpret_cast<__half2*>(&outH[o]) = hp;
            } else {
                out32[o]   = v0 + bias[col];
                out32[o+1] = v1 + bias[col+1];
            }
        }
    }
}

// ---- flash attention v2 ----
#define FP2 144
#define QT (128*FP2)
#define KT2 (64*FP2)
#define STG2 (4*KT2)
#define FSM2 (2*QT + 2*STG2)
__global__ void __launch_bounds__(256,1) k_flash(){
    int tb = 7 - blockIdx.x, bh = blockIdx.y;
    extern __shared__ char fsm[];
    uint32_t su = smem_u32(fsm);
    uint32_t qb = su, kvb = su + 2*QT;
    int tid=threadIdx.x, lane=tid&31, w=tid>>5;
    const size_t hb = (size_t)bh*TT*HSZ;
#pragma unroll
    for(int i=0;i<8;i++){
        int c = tid + i*256;
        int half = c>>10, w2 = c&1023, row = w2>>3, q = w2&7;
        cp16(qb + half*QT + row*FP2 + q*16,
             (half? g_ql : g_qh) + hb + (size_t)(tb*128+row)*HSZ + q*8);
    }
    auto loadKV = [&](int sb){
        uint32_t base = kvb + (sb&1)*STG2;
#pragma unroll
        for(int i=0;i<8;i++){
            int c = tid + i*256;
            int arr = c>>9, w2 = c&511, row = w2>>3, q = w2&7;
            const bf16* src = (arr==0? g_kh : arr==1? g_kl : arr==2? g_vh : g_vl)
                            + hb + (size_t)(sb*64+row)*HSZ + q*8;
            cp16(base + arr*KT2 + row*FP2 + q*16, src);
        }
        asm volatile("cp.async.commit_group;" ::: "memory");
    };
    loadKV(0);
    float m0=-1e30f, m1=-1e30f, l0=0.f, l1=0.f;
    float O[8][4];
#pragma unroll
    for(int n8=0;n8<8;n8++)
#pragma unroll
        for(int c=0;c<4;c++) O[n8][c]=0.f;
    const float scale=0.036084391824351615f;
    int brow = (lane&7) | ((lane&16)>>1);
    int t4 = lane&3, g = lane>>2;
    int smax = 2*tb+1;
    for(int sb=0; sb<=smax; sb++){
        if(sb<smax) loadKV(sb+1);
        if(sb<smax) asm volatile("cp.async.wait_group 1;" ::: "memory");
        else        asm volatile("cp.async.wait_group 0;" ::: "memory");
        __syncthreads();
        uint32_t kb = kvb + (sb&1)*STG2;
        uint32_t vb = kb + 2*KT2;
        float S[8][4];
#pragma unroll
        for(int n8=0;n8<8;n8++)
#pragma unroll
            for(int c=0;c<4;c++) S[n8][c]=0.f;
#pragma unroll
        for(int kc=0;kc<4;kc++){
            uint32_t aH[4], aL[4];
            uint32_t ad = qb + (w*16+(lane&15))*FP2 + kc*32 + (lane>>4)*16;
            ldsm4(ad, aH); ldsm4(ad+QT, aL);
            uint32_t bHt[4][4], bLt[4][4];
#pragma unroll
            for(int nt=0;nt<4;nt++){
                uint32_t bd = kb + (nt*16+brow)*FP2 + kc*32 + ((lane>>3)&1)*16;
                ldsm4(bd, bHt[nt]); ldsm4(bd+KT2, bLt[nt]);
            }
#pragma unroll
            for(int n8=0;n8<8;n8++){
                uint32_t* bh2=&bHt[n8>>1][(n8&1)*2];
                uint32_t* bl2=&bLt[n8>>1][(n8&1)*2];
                mma16816(S[n8], aH, bh2);
                mma16816(S[n8], aH, bl2);
                mma16816(S[n8], aL, bh2);
            }
        }
        int rg0 = tb*128 + w*16 + g;
#pragma unroll
        for(int n8=0;n8<8;n8++)
#pragma unroll
            for(int c=0;c<4;c++){
                S[n8][c] *= scale;
                if(sb >= 2*tb){
                    int sg = sb*64 + n8*8 + t4*2 + (c&1);
                    int rg = rg0 + ((c>=2)?8:0);
                    if(sg > rg) S[n8][c] = -1e30f;
                }
            }
        float mx0=-1e30f, mx1=-1e30f;
#pragma unroll
        for(int n8=0;n8<8;n8++){
            mx0=fmaxf(mx0,fmaxf(S[n8][0],S[n8][1]));
            mx1=fmaxf(mx1,fmaxf(S[n8][2],S[n8][3]));
        }
        mx0=fmaxf(mx0,__shfl_xor_sync(~0u,mx0,1)); mx0=fmaxf(mx0,__shfl_xor_sync(~0u,mx0,2));
        mx1=fmaxf(mx1,__shfl_xor_sync(~0u,mx1,1)); mx1=fmaxf(mx1,__shfl_xor_sync(~0u,mx1,2));
        float mn0=fmaxf(m0,mx0), mn1=fmaxf(m1,mx1);
        float f0=expf(m0-mn0), f1=expf(m1-mn1);
        m0=mn0; m1=mn1;
        float rs0=0.f, rs1=0.f;
#pragma unroll
        for(int n8=0;n8<8;n8++){
            S[n8][0]=expf(S[n8][0]-mn0); S[n8][1]=expf(S[n8][1]-mn0);
            S[n8][2]=expf(S[n8][2]-mn1); S[n8][3]=expf(S[n8][3]-mn1);
            rs0+=S[n8][0]+S[n8][1]; rs1+=S[n8][2]+S[n8][3];
        }
        rs0+=__shfl_xor_sync(~0u,rs0,1); rs0+=__shfl_xor_sync(~0u,rs0,2);
        rs1+=__shfl_xor_sync(~0u,rs1,1); rs1+=__shfl_xor_sync(~0u,rs1,2);
        l0=l0*f0+rs0; l1=l1*f1+rs1;
#pragma unroll
        for(int n8=0;n8<8;n8++){
            O[n8][0]*=f0; O[n8][1]*=f0; O[n8][2]*=f1; O[n8][3]*=f1;
        }
#pragma unroll
        for(int j=0;j<4;j++){
            float p00=S[2*j][0], p01=S[2*j][1], p02=S[2*j][2], p03=S[2*j][3];
            float p10=S[2*j+1][0], p11=S[2*j+1][1], p12=S[2*j+1][2], p13=S[2*j+1][3];
            uint32_t aPh[4], aPl[4];
            aPh[0]=packbf(p00,p01); aPh[1]=packbf(p02,p03);
            aPh[2]=packbf(p10,p11); aPh[3]=packbf(p12,p13);
            {
                __nv_bfloat162 t;
                t=*(__nv_bfloat162*)&aPh[0];
                aPl[0]=packbf(p00-__bfloat162float(t.x), p01-__bfloat162float(t.y));
                t=*(__nv_bfloat162*)&aPh[1];
                aPl[1]=packbf(p02-__bfloat162float(t.x), p03-__bfloat162float(t.y));
                t=*(__nv_bfloat162*)&aPh[2];
                aPl[2]=packbf(p10-__bfloat162float(t.x), p11-__bfloat162float(t.y));
                t=*(__nv_bfloat162*)&aPh[3];
                aPl[3]=packbf(p12-__bfloat162float(t.x), p13-__bfloat162float(t.y));
            }
            uint32_t bHt[4][4], bLt[4][4];
            uint32_t vrow = (j*16 + (lane&15))*FP2 + (lane>>4)*16;
#pragma unroll
            for(int nt=0;nt<4;nt++){
                uint32_t bd = vb + vrow + nt*32;
                ldsm4t(bd, bHt[nt]); ldsm4t(bd+KT2, bLt[nt]);
            }
#pragma unroll
            for(int n8=0;n8<8;n8++){
                uint32_t* bh2=&bHt[n8>>1][(n8&1)*2];
                uint32_t* bl2=&bLt[n8>>1][(n8&1)*2];
                mma16816(O[n8], aPh, bh2);
                mma16816(O[n8], aPh, bl2);
                mma16816(O[n8], aPl, bh2);
            }
        }
        __syncthreads();
    }
    float i0=1.f/l0, i1=1.f/l1;
    int b = bh/HH, h = bh%HH;
#pragma unroll
    for(int n8=0;n8<8;n8++){
        int col = h*64 + n8*8 + t4*2;
#pragma unroll
        for(int hf=0;hf<2;hf++){
            int tokr = b*1024 + tb*128 + w*16 + g + hf*8;
            float v0 = O[n8][hf*2+0]*(hf?i1:i0);
            float v1 = O[n8][hf*2+1]*(hf?i1:i0);
            size_t o=(size_t)tokr*CCH+col;
            bf16 h0=__float2bfloat16(v0), h1=__float2bfloat16(v1);
            __nv_bfloat162 hp2; hp2.x=h0; hp2.y=h1;
            __nv_bfloat162 lp;
            lp.x=__float2bfloat16(v0-__bfloat162float(h0));
            lp.y=__float2bfloat16(v1-__bfloat162float(h1));
            *reinterpret_cast<__nv_bfloat162*>(&g_aoh[o]) = hp2;
            *reinterpret_cast<__nv_bfloat162*>(&g_aol[o]) = lp;
        }
    }
}

__global__ void k_router(const float* __restrict__ wr, const float* __restrict__ br,
                         const float* __restrict__ wn, const float* __restrict__ bnn,
                         const float* __restrict__ temp, const float* __restrict__ noise){
    int warp=threadIdx.x>>5, lane=threadIdx.x&31;
    int n=blockIdx.x*8+warp;
    const float* hp = g_h2 + (size_t)n*CCH;
    float r[8]={}, q[8]={};
    for(int c=lane;c<CCH;c+=32){
        float hv=hp[c];
        const float* wrp=wr+c*EE; const float* wnp=wn+c*EE;
#pragma unroll
        for(int e=0;e<8;e++){ r[e]+=hv*wrp[e]; q[e]+=hv*wnp[e]; }
    }
#pragma unroll
    for(int e=0;e<8;e++)
#pragma unroll
        for(int o=16;o;o>>=1){
            r[e]+=__shfl_xor_sync(~0u,r[e],o);
            q[e]+=__shfl_xor_sync(~0u,q[e],o);
        }
    if(lane==0){
        float t=fminf(fmaxf(temp[0],0.5f),2.0f);
        float ny[8];
#pragma unroll
        for(int e=0;e<8;e++){
            float z=q[e]+bnn[e];
            float sp=(z>20.f)? z : log1pf(expf(z));
            ny[e]=r[e]+br[e] + t*noise[(size_t)n*EE+e]*sp;
        }
        int i1=0;
#pragma unroll
        for(int e=1;e<8;e++) if(ny[e]>ny[i1]) i1=e;
        int i2=-1;
#pragma unroll
        for(int e=0;e<8;e++){ if(e==i1) continue; if(i2<0||ny[e]>ny[i2]) i2=e; }
        float e2=expf(ny[i2]-ny[i1]);
        float gv[2]={1.f/(1.f+e2), e2/(1.f+e2)};
        int id[2]={i1,i2};
#pragma unroll
        for(int k2=0;k2<2;k2++){
            int e=id[k2];
            int row=atomicAdd(&g_cnt[e],1);
            g_tok[e*NT+row]=n;
            g_pos[n*2+k2]=e*NT+row;
            g_gw[n*2+k2]=gv[k2];
        }
    }
}

// fused dual residual-LN + gated combine
__global__ void k_fin(const float* __restrict__ t3,
                      const float* __restrict__ dg, const float* __restrict__ db_,
                      const float* __restrict__ sg, const float* __restrict__ sb_,
                      float* __restrict__ out){
    int n=blockIdx.x, t=threadIdx.x;
    int s0=g_pos[2*n], s1=g_pos[2*n+1];
    int e0=s0>>13, r0=s0&8191, e1=s1>>13, r1=s1&8191;
    const float* ta = t3 + (size_t)e0*NT*CCH + (size_t)r0*CCH;
    const float* tb = t3 + (size_t)e1*NT*CCH + (size_t)r1*CCH;
    float va[3], vb[3];
    float sa=0.f,qa=0.f,sb2=0.f,qb=0.f;
#pragma unroll
    for(int i=0;i<3;i++){
        int c=t+256*i;
        float h = g_h2[(size_t)n*CCH+c];
        va[i]=h+ta[c]; vb[i]=h+tb[c];
        sa+=va[i]; qa+=va[i]*va[i]; sb2+=vb[i]; qb+=vb[i]*vb[i];
    }
    __shared__ float sh[8][4];
#pragma unroll
    for(int o=16;o;o>>=1){
        sa+=__shfl_xor_sync(~0u,sa,o); qa+=__shfl_xor_sync(~0u,qa,o);
        sb2+=__shfl_xor_sync(~0u,sb2,o); qb+=__shfl_xor_sync(~0u,qb,o);
    }
    if((t&31)==0){ sh[t>>5][0]=sa; sh[t>>5][1]=qa; sh[t>>5][2]=sb2; sh[t>>5][3]=qb; }
    __syncthreads();
    sa=0.f; qa=0.f; sb2=0.f; qb=0.f;
#pragma unroll
    for(int i=0;i<8;i++){ sa+=sh[i][0]; qa+=sh[i][1]; sb2+=sh[i][2]; qb+=sh[i][3]; }
    float ma=sa*(1.f/768.f), ra=rsqrtf(qa*(1.f/768.f)-ma*ma+1e-5f);
    float mb=sb2*(1.f/768.f), rb=rsqrtf(qb*(1.f/768.f)-mb*mb+1e-5f);
    const float* g0p = (e0<2)? dg+e0*CCH : sg+(e0-2)*CCH;
    const float* b0p = (e0<2)? db_+e0*CCH : sb_+(e0-2)*CCH;
    const float* g1p = (e1<2)? dg+e1*CCH : sg+(e1-2)*CCH;
    const float* b1p = (e1<2)? db_+e1*CCH : sb_+(e1-2)*CCH;
    float gw0=g_gw[2*n], gw1=g_gw[2*n+1];
#pragma unroll
    for(int i=0;i<3;i++){
        int c=t+256*i;
        float o0=(va[i]-ma)*ra*g0p[c]+b0p[c];
        float o1=(vb[i]-mb)*rb*g1p[c]+b1p[c];
        out[(size_t)n*CCH+c]=g_x2[(size_t)n*CCH+c]+gw0*o0+gw1*o1;
    }
}

extern "C" void kernel_launch(void* const* d_in, const int* in_sizes, int n_in,
                              void* d_out, int out_size){
    const float *x=(const float*)d_in[0], *rno=(const float*)d_in[1];
    const float *wq=(const float*)d_in[2], *wk=(const float*)d_in[3], *wv=(const float*)d_in[4];
    const float *w_proj=(const float*)d_in[5], *b_proj=(const float*)d_in[6];
    const float *ln1g=(const float*)d_in[7], *ln1b=(const float*)d_in[8];
    const float *ln2g=(const float*)d_in[9], *ln2b=(const float*)d_in[10];
    const float *wr=(const float*)d_in[11], *br=(const float*)d_in[12];
    const float *wn=(const float*)d_in[13], *bn=(const float*)d_in[14];
    const float *temp=(const float*)d_in[15];
    const float *dw1=(const float*)d_in[16], *db1=(const float*)d_in[17];
    const float *dw2=(const float*)d_in[18], *db2=(const float*)d_in[19];
    const float *dw3=(const float*)d_in[20], *db3=(const float*)d_in[21];
    const float *dlng=(const float*)d_in[22], *dlnb=(const float*)d_in[23];
    const float *sw1=(const float*)d_in[24], *sb1=(const float*)d_in[25];
    const float *sw2=(const float*)d_in[26], *sb2=(const float*)d_in[27];
    const float *slng=(const float*)d_in[28], *slnb=(const float*)d_in[29];
    float* out=(float*)d_out;

    cudaFuncSetAttribute(k_mma<0>, cudaFuncAttributeMaxDynamicSharedMemorySize, SMEMSZ);
    cudaFuncSetAttribute(k_mma<1>, cudaFuncAttributeMaxDynamicSharedMemorySize, SMEMSZ);
    cudaFuncSetAttribute(k_mmah<2>, cudaFuncAttributeMaxDynamicSharedMemorySize, HSMEM);
    cudaFuncSetAttribute(k_mmah<3>, cudaFuncAttributeMaxDynamicSharedMemorySize, HSMEM);
    cudaFuncSetAttribute(k_flash, cudaFuncAttributeMaxDynamicSharedMemorySize, FSM2);

    bf16 *Bqh,*Bql,*Bph,*Bpl,*h1h,*h1l,*aoh,*aol;
    f16 *Bd1,*Bd2,*Bd3,*Bs1,*Bs2,*h2f,*t1f,*t2f;
    float *x2,*h2,*t3; int *tok,*cnt;
    cudaGetSymbolAddress((void**)&Bqh,g_Bqh); cudaGetSymbolAddress((void**)&Bql,g_Bql);
    cudaGetSymbolAddress((void**)&Bph,g_Bph); cudaGetSymbolAddress((void**)&Bpl,g_Bpl);
    cudaGetSymbolAddress((void**)&Bd1,g_Bd1);
    cudaGetSymbolAddress((void**)&Bd2,g_Bd2);
    cudaGetSymbolAddress((void**)&Bd3,g_Bd3);
    cudaGetSymbolAddress((void**)&Bs1,g_Bs1);
    cudaGetSymbolAddress((void**)&Bs2,g_Bs2);
    cudaGetSymbolAddress((void**)&h1h,g_h1h); cudaGetSymbolAddress((void**)&h1l,g_h1l);
    cudaGetSymbolAddress((void**)&aoh,g_aoh); cudaGetSymbolAddress((void**)&aol,g_aol);
    cudaGetSymbolAddress((void**)&h2f,g_h2f);
    cudaGetSymbolAddress((void**)&t1f,g_t1f); cudaGetSymbolAddress((void**)&t2f,g_t2f);
    cudaGetSymbolAddress((void**)&x2,g_x2); cudaGetSymbolAddress((void**)&h2,g_h2);
    cudaGetSymbolAddress((void**)&t3,g_t3);
    cudaGetSymbolAddress((void**)&tok,g_tok); cudaGetSymbolAddress((void**)&cnt,g_cnt);
    const size_t ZT1=(size_t)NT*FF, ZT3=(size_t)NT*CCH;

    dim3 wb(32,8);
    k_reset<<<1,32>>>();
    k_wsplit2<<<dim3(2,12,12),wb>>>(wq, Bqh,           Bql,           CCH, HSZ);
    k_wsplit2<<<dim3(2,12,12),wb>>>(wk, Bqh+CCH*CCH,   Bql+CCH*CCH,   CCH, HSZ);
    k_wsplit2<<<dim3(2,12,12),wb>>>(wv, Bqh+2*CCH*CCH, Bql+2*CCH*CCH, CCH, HSZ);
    k_wsplit2<<<dim3(24,12,1),wb>>>(w_proj, Bph, Bpl, CCH, CCH);
    k_wcvt<<<dim3(96,12,2),wb>>>(dw1, Bd1, CCH, FF);
    k_wcvt<<<dim3(96,48,2),wb>>>(dw2, Bd2, FF, FF);
    k_wcvt<<<dim3(24,48,2),wb>>>(dw3, Bd3, FF, CCH);
    k_wcvt<<<dim3(96,12,6),wb>>>(sw1, Bs1, CCH, FF);
    k_wcvt<<<dim3(24,48,6),wb>>>(sw2, Bs2, FF, CCH);
    // attention
    k_ln<<<NT,256>>>(x, ln1g, ln1b, nullptr, h1h, h1l, nullptr);
    k_mma<0><<<dim3(18,64),256,SMEMSZ>>>(h1h,h1l,Bqh,Bql,nullptr,nullptr,nullptr,
                                         NT,3*CCH,CCH);
    k_flash<<<dim3(8,BH),256,FSM2>>>();
    k_mma<1><<<dim3(6,64),256,SMEMSZ>>>(aoh,aol,Bph,Bpl,b_proj,x,x2, NT,CCH,CCH);
    // router
    k_ln<<<NT,256>>>(x2, ln2g, ln2b, h2, nullptr, nullptr, h2f);
    k_router<<<NT/8,256>>>(wr,br,wn,bn,temp,rno);
    // experts
    k_mmah<2><<<dim3(24,64,8),256,HSMEM>>>(h2f,0, nullptr,0, 99,
        Bd1, Bs1,(size_t)CCH*FF, 2, db1,sb1,
        nullptr, t1f, ZT1, NT,FF,CCH, tok, cnt);
    k_mmah<2><<<dim3(24,64,2),256,HSMEM>>>(t1f,ZT1, nullptr,0, 99,
        Bd2, nullptr,(size_t)FF*FF, 99, db2,nullptr,
        nullptr, t2f, ZT1, NT,FF,FF, nullptr, cnt);
    k_mmah<3><<<dim3(6,64,8),256,HSMEM>>>(t2f,ZT1, t1f,ZT1, 2,
        Bd3, Bs2,(size_t)CCH*FF, 2, db3,sb2,
        t3, nullptr, ZT3, NT,CCH,FF, nullptr, cnt);
    k_fin<<<NT,256>>>(t3, dlng, dlnb, slng, slnb, out);
}

// round 11
// speedup vs baseline: 7.0060x; 1.2260x over previous
#include <cuda_runtime.h>
#include <cuda_bf16.h>
#include <cuda_fp16.h>
#include <stdint.h>
#include <math.h>

#define BN 8
#define TT 1024
#define CCH 768
#define HH 12
#define HSZ 64
#define EE 8
#define FF 3072
#define NT (BN*TT)
#define BH (BN*HH)
typedef __nv_bfloat16 bf16;
typedef __half f16;

// ---- static scratch ----
__device__ bf16  g_qh[BH*TT*HSZ], g_ql[BH*TT*HSZ];
__device__ bf16  g_kh[BH*TT*HSZ], g_kl[BH*TT*HSZ];
__device__ bf16  g_vh[BH*TT*HSZ], g_vl[BH*TT*HSZ];
__device__ bf16  g_h1h[NT*CCH], g_h1l[NT*CCH];
__device__ bf16  g_aoh[NT*CCH], g_aol[NT*CCH];
__device__ float g_x2[NT*CCH];
__device__ float g_h2[NT*CCH];
__device__ f16   g_h2f[NT*CCH];
__device__ float g_gw[NT*2];
__device__ int   g_pos[NT*2];
__device__ int   g_tok[EE*NT];
__device__ int   g_cnt[EE];
__device__ f16   g_t1f[(size_t)EE*NT*FF];
__device__ f16   g_t2f[(size_t)2*NT*FF];
__device__ float g_t3[(size_t)EE*NT*CCH];
__device__ bf16  g_Bqh[3*CCH*CCH], g_Bql[3*CCH*CCH];
__device__ bf16  g_Bph[CCH*CCH],  g_Bpl[CCH*CCH];
__device__ f16   g_Bd1[2*CCH*FF];
__device__ f16   g_Bd2[(size_t)2*FF*FF];
__device__ f16   g_Bd3[2*CCH*FF];
__device__ f16   g_Bs1[(size_t)6*CCH*FF];
__device__ f16   g_Bs2[(size_t)6*CCH*FF];

__device__ __forceinline__ float geluf(float v){
    return 0.5f*v*(1.f + erff(v*0.70710678118654752440f));
}
__device__ __forceinline__ uint32_t smem_u32(const void* p){
    uint32_t a;
    asm("{ .reg .u64 t; cvta.to.shared.u64 t, %1; cvt.u32.u64 %0, t; }" : "=r"(a) : "l"(p));
    return a;
}
__device__ __forceinline__ void cp16(uint32_t d, const void* s){
    asm volatile("cp.async.cg.shared.global [%0], [%1], 16;" :: "r"(d), "l"(s));
}
__device__ __forceinline__ void ldsm4(uint32_t a, uint32_t* r){
    asm volatile("ldmatrix.sync.aligned.m8n8.x4.shared.b16 {%0,%1,%2,%3}, [%4];"
        : "=r"(r[0]),"=r"(r[1]),"=r"(r[2]),"=r"(r[3]) : "r"(a));
}
__device__ __forceinline__ void ldsm4t(uint32_t a, uint32_t* r){
    asm volatile("ldmatrix.sync.aligned.m8n8.x4.trans.shared.b16 {%0,%1,%2,%3}, [%4];"
        : "=r"(r[0]),"=r"(r[1]),"=r"(r[2]),"=r"(r[3]) : "r"(a));
}
__device__ __forceinline__ void mma16816(float* c, const uint32_t* a, const uint32_t* b){
    asm volatile("mma.sync.aligned.m16n8k16.row.col.f32.bf16.bf16.f32 "
        "{%0,%1,%2,%3},{%4,%5,%6,%7},{%8,%9},{%0,%1,%2,%3};"
        : "+f"(c[0]),"+f"(c[1]),"+f"(c[2]),"+f"(c[3])
        : "r"(a[0]),"r"(a[1]),"r"(a[2]),"r"(a[3]), "r"(b[0]),"r"(b[1]));
}
__device__ __forceinline__ void mmah16816(float* c, const uint32_t* a, const uint32_t* b){
    asm volatile("mma.sync.aligned.m16n8k16.row.col.f32.f16.f16.f32 "
        "{%0,%1,%2,%3},{%4,%5,%6,%7},{%8,%9},{%0,%1,%2,%3};"
        : "+f"(c[0]),"+f"(c[1]),"+f"(c[2]),"+f"(c[3])
        : "r"(a[0]),"r"(a[1]),"r"(a[2]),"r"(a[3]), "r"(b[0]),"r"(b[1]));
}
__device__ __forceinline__ uint32_t packbf(float a, float b){
    __nv_bfloat162 p; p.x=__float2bfloat16(a); p.y=__float2bfloat16(b);
    return *reinterpret_cast<uint32_t*>(&p);
}

__global__ void k_reset(){ if(threadIdx.x < EE) g_cnt[threadIdx.x] = 0; }

// W[K][N] -> out[N][K] hi/lo bf16 (attention weights)
__global__ void k_wsplit2(const float* __restrict__ W, bf16* __restrict__ oh,
                          bf16* __restrict__ ol, int K, int N){
    int e = blockIdx.z;
    W += (size_t)e*K*N; oh += (size_t)e*K*N; ol += (size_t)e*K*N;
    __shared__ float s[64][33];
    int n0 = blockIdx.x*32, k0 = blockIdx.y*64;
    int tx = threadIdx.x, ty = threadIdx.y;
#pragma unroll
    for(int r=0;r<8;r++){ int kk=ty+r*8; s[kk][tx] = W[(size_t)(k0+kk)*N + n0+tx]; }
    __syncthreads();
#pragma unroll
    for(int r=0;r<4;r++){
        int n = ty + r*8;
        float v0 = s[2*tx][n], v1 = s[2*tx+1][n];
        bf16 h0 = __float2bfloat16(v0), h1 = __float2bfloat16(v1);
        bf16 hh[2] = {h0, h1};
        bf16 ll[2] = {__float2bfloat16(v0-__bfloat162float(h0)),
                      __float2bfloat16(v1-__bfloat162float(h1))};
        size_t o = (size_t)(n0+n)*K + k0 + 2*tx;
        *reinterpret_cast<uint32_t*>(&oh[o]) = *reinterpret_cast<uint32_t*>(hh);
        *reinterpret_cast<uint32_t*>(&ol[o]) = *reinterpret_cast<uint32_t*>(ll);
    }
}

// W[K][N] -> out[N][K] single fp16 (expert weights)
__global__ void k_wcvt(const float* __restrict__ W, f16* __restrict__ oh, int K, int N){
    int e = blockIdx.z;
    W += (size_t)e*K*N; oh += (size_t)e*K*N;
    __shared__ float s[64][33];
    int n0 = blockIdx.x*32, k0 = blockIdx.y*64;
    int tx = threadIdx.x, ty = threadIdx.y;
#pragma unroll
    for(int r=0;r<8;r++){ int kk=ty+r*8; s[kk][tx] = W[(size_t)(k0+kk)*N + n0+tx]; }
    __syncthreads();
#pragma unroll
    for(int r=0;r<4;r++){
        int n = ty + r*8;
        __half2 hp; hp.x=__float2half(s[2*tx][n]); hp.y=__float2half(s[2*tx+1][n]);
        size_t o = (size_t)(n0+n)*K + k0 + 2*tx;
        *reinterpret_cast<__half2*>(&oh[o]) = hp;
    }
}

__global__ void k_ln(const float* __restrict__ in, const float* __restrict__ gam,
                     const float* __restrict__ bet, float* __restrict__ out,
                     bf16* __restrict__ oh, bf16* __restrict__ ol, f16* __restrict__ of){
    int n = blockIdx.x, t = threadIdx.x;
    const float* row = in + (size_t)n*CCH;
    float v[3], s=0.f, s2=0.f;
#pragma unroll
    for(int i=0;i<3;i++){ v[i]=row[t+256*i]; s+=v[i]; s2+=v[i]*v[i]; }
    __shared__ float shs[8], shq[8];
#pragma unroll
    for(int o=16;o;o>>=1){ s+=__shfl_xor_sync(~0u,s,o); s2+=__shfl_xor_sync(~0u,s2,o); }
    if((t&31)==0){ shs[t>>5]=s; shq[t>>5]=s2; }
    __syncthreads();
    s=0.f; s2=0.f;
#pragma unroll
    for(int i=0;i<8;i++){ s+=shs[i]; s2+=shq[i]; }
    float mean=s*(1.f/768.f), var=s2*(1.f/768.f)-mean*mean, r=rsqrtf(var+1e-5f);
#pragma unroll
    for(int i=0;i<3;i++){
        int c=t+256*i;
        float o=(v[i]-mean)*r*gam[c]+bet[c];
        if(out) out[(size_t)n*CCH+c]=o;
        if(oh){
            bf16 hi=__float2bfloat16(o);
            oh[(size_t)n*CCH+c]=hi;
            ol[(size_t)n*CCH+c]=__float2bfloat16(o-__bfloat162float(hi));
        }
        if(of) of[(size_t)n*CCH+c]=__float2half(o);
    }
}

// ---- bf16 3-product GEMM (QKV + proj), 3-stage ----
#define PITCH 80
#define TILEB 10240
#define STAGEB 40960
#define SMEMSZ (3*STAGEB)
template<int EPI>
__global__ void __launch_bounds__(256,1)
k_mma(const bf16* __restrict__ Ah, const bf16* __restrict__ Al,
      const bf16* __restrict__ Bh, const bf16* __restrict__ Bl,
      const float* __restrict__ bias, const float* __restrict__ resid,
      float* __restrict__ out32, int M, int Nn, int K){
    int by = blockIdx.y, bx = blockIdx.x;
    extern __shared__ char smem[];
    uint32_t su = smem_u32(smem);
    int tid=threadIdx.x, lane=tid&31, wid=tid>>5;
    int wm=wid&3, wn=wid>>2;
    const int KT = K/32;
    float acc[2][8][4];
#pragma unroll
    for(int a=0;a<2;a++)
#pragma unroll
        for(int b=0;b<8;b++)
#pragma unroll
            for(int c=0;c<4;c++) acc[a][b][c]=0.f;
    auto load_stage = [&](int kt){
        uint32_t sb = su + (kt%3)*STAGEB;
#pragma unroll
        for(int i=0;i<8;i++){
            int c = tid + i*256;
            int tile=c>>9, w=c&511, row=w>>2, q=w&3;
            uint32_t d = sb + tile*TILEB + row*PITCH + q*16;
            const bf16* src;
            if(tile<2) src = (tile==0?Ah:Al) + (size_t)(by*128+row)*K + kt*32 + q*8;
            else       src = (tile==2?Bh:Bl) + (size_t)(bx*128+row)*K + kt*32 + q*8;
            cp16(d, src);
        }
        asm volatile("cp.async.commit_group;" ::: "memory");
    };
    load_stage(0);
    if(KT>1) load_stage(1);
    for(int kt=0; kt<KT; kt++){
        if(kt+2<KT) load_stage(kt+2);
        if(kt+2<KT)      asm volatile("cp.async.wait_group 2;" ::: "memory");
        else if(kt+1<KT) asm volatile("cp.async.wait_group 1;" ::: "memory");
        else             asm volatile("cp.async.wait_group 0;" ::: "memory");
        __syncthreads();
        uint32_t sb = su + (kt%3)*STAGEB;
#pragma unroll
        for(int kh=0; kh<2; kh++){
            uint32_t aH[2][4], aL[2][4];
            int arow = wm*32 + (lane&15);
            uint32_t ako = kh*32 + (lane>>4)*16;
#pragma unroll
            for(int mt=0;mt<2;mt++){
                uint32_t ad = sb + (arow+mt*16)*PITCH + ako;
                ldsm4(ad, aH[mt]); ldsm4(ad + TILEB, aL[mt]);
            }
            uint32_t bHf[4][4], bLf[4][4];
            int brow = wn*64 + ((lane&7) | ((lane&16)>>1));
            uint32_t bko = kh*32 + ((lane>>3)&1)*16;
#pragma unroll
            for(int nt=0;nt<4;nt++){
                uint32_t bd = sb + 2*TILEB + (brow+nt*16)*PITCH + bko;
                ldsm4(bd, bHf[nt]); ldsm4(bd + TILEB, bLf[nt]);
            }
#pragma unroll
            for(int mt=0;mt<2;mt++)
#pragma unroll
            for(int n8=0;n8<8;n8++){
                uint32_t* bh = &bHf[n8>>1][(n8&1)*2];
                uint32_t* bl = &bLf[n8>>1][(n8&1)*2];
                mma16816(acc[mt][n8], aH[mt], bh);
                mma16816(acc[mt][n8], aH[mt], bl);
                mma16816(acc[mt][n8], aL[mt], bh);
            }
        }
        __syncthreads();
    }
    int g = lane>>2, t4 = lane&3;
#pragma unroll
    for(int mt=0;mt<2;mt++)
#pragma unroll
    for(int n8=0;n8<8;n8++){
        int col = bx*128 + wn*64 + n8*8 + t4*2;
#pragma unroll
        for(int hf=0; hf<2; hf++){
            int row = by*128 + wm*32 + mt*16 + g + hf*8;
            float v0 = acc[mt][n8][hf*2+0];
            float v1 = acc[mt][n8][hf*2+1];
            if(EPI==0){
                int which = col/CCH, rem = col - which*CCH;
                int h = rem>>6, d0 = rem&63;
                int b = row>>10, t = row&1023;
                size_t o = ((size_t)(b*HH+h)*TT + t)*HSZ + d0;
                bf16* dh = which==0? g_qh : which==1? g_kh : g_vh;
                bf16* dl = which==0? g_ql : which==1? g_kl : g_vl;
                bf16 h0=__float2bfloat16(v0), h1=__float2bfloat16(v1);
                __nv_bfloat162 hp; hp.x=h0; hp.y=h1;
                __nv_bfloat162 lp;
                lp.x=__float2bfloat16(v0-__bfloat162float(h0));
                lp.y=__float2bfloat16(v1-__bfloat162float(h1));
                *reinterpret_cast<__nv_bfloat162*>(&dh[o]) = hp;
                *reinterpret_cast<__nv_bfloat162*>(&dl[o]) = lp;
            } else {
                size_t o=(size_t)row*Nn+col;
                out32[o]   = v0 + bias[col]   + resid[o];
                out32[o+1] = v1 + bias[col+1] + resid[o+1];
            }
        }
    }
}

// ---- fp16 single-product GEMM (experts), 3-stage, 2 CTAs/SM, z-batched ----
#define HSTG (2*TILEB)
#define HSMEM (3*HSTG)
template<int EPI>
__global__ void __launch_bounds__(256,2)
k_mmah(const f16* __restrict__ A1, size_t zsA, const f16* __restrict__ A2, size_t zsA2,
       int zSplitA,
       const f16* __restrict__ B1, const f16* __restrict__ B2, size_t zsB, int zSplit,
       const float* __restrict__ b1, const float* __restrict__ b2,
       float* __restrict__ out32, f16* __restrict__ outH, size_t zsOut,
       int M, int Nn, int K,
       const int* __restrict__ tok, const int* __restrict__ cnt){
    int z = blockIdx.z;
    if(cnt) M = cnt[z];
    int by = blockIdx.y, bx = blockIdx.x;
    if(by*128 >= M) return;
    const f16* A = (z < zSplitA) ? A1 + (size_t)z*zsA : A2 + (size_t)z*zsA2;
    const f16* Bp; const float* bias;
    if(z < zSplit){ Bp=B1+(size_t)z*zsB; bias=b1+(size_t)z*Nn; }
    else { Bp=B2+(size_t)(z-zSplit)*zsB; bias=b2+(size_t)(z-zSplit)*Nn; }
    if(out32) out32 += (size_t)z*zsOut;
    if(outH)  outH  += (size_t)z*zsOut;
    if(tok) tok += (size_t)z*NT;
    extern __shared__ char smem[];
    uint32_t su = smem_u32(smem);
    int tid=threadIdx.x, lane=tid&31, wid=tid>>5;
    int wm=wid&3, wn=wid>>2;
    const int KT = K/32;
    float acc[2][8][4];
#pragma unroll
    for(int a=0;a<2;a++)
#pragma unroll
        for(int b=0;b<8;b++)
#pragma unroll
            for(int c=0;c<4;c++) acc[a][b][c]=0.f;
    auto load_stage = [&](int kt){
        uint32_t sb = su + (kt%3)*HSTG;
#pragma unroll
        for(int i=0;i<4;i++){
            int c = tid + i*256;
            int tile=c>>9, w=c&511, row=w>>2, q=w&3;
            uint32_t d = sb + tile*TILEB + row*PITCH + q*16;
            const f16* src;
            if(tile==0){
                int rg=by*128+row; if(rg>=M) rg=M-1;
                int asrc = tok ? tok[rg] : rg;
                src = A + (size_t)asrc*K + kt*32 + q*8;
            } else {
                src = Bp + (size_t)(bx*128+row)*K + kt*32 + q*8;
            }
            cp16(d, src);
        }
        asm volatile("cp.async.commit_group;" ::: "memory");
    };
    load_stage(0);
    if(KT>1) load_stage(1);
    for(int kt=0; kt<KT; kt++){
        if(kt+2<KT) load_stage(kt+2);
        if(kt+2<KT)      asm volatile("cp.async.wait_group 2;" ::: "memory");
        else if(kt+1<KT) asm volatile("cp.async.wait_group 1;" ::: "memory");
        else             asm volatile("cp.async.wait_group 0;" ::: "memory");
        __syncthreads();
        uint32_t sb = su + (kt%3)*HSTG;
#pragma unroll
        for(int kh=0; kh<2; kh++){
            uint32_t aF[2][4];
            int arow = wm*32 + (lane&15);
            uint32_t ako = kh*32 + (lane>>4)*16;
#pragma unroll
            for(int mt=0;mt<2;mt++)
                ldsm4(sb + (arow+mt*16)*PITCH + ako, aF[mt]);
            uint32_t bF[4][4];
            int brow = wn*64 + ((lane&7) | ((lane&16)>>1));
            uint32_t bko = kh*32 + ((lane>>3)&1)*16;
#pragma unroll
            for(int nt=0;nt<4;nt++)
                ldsm4(sb + TILEB + (brow+nt*16)*PITCH + bko, bF[nt]);
#pragma unroll
            for(int mt=0;mt<2;mt++)
#pragma unroll
            for(int n8=0;n8<8;n8++)
                mmah16816(acc[mt][n8], aF[mt], &bF[n8>>1][(n8&1)*2]);
        }
        __syncthreads();
    }
    int g = lane>>2, t4 = lane&3;
#pragma unroll
    for(int mt=0;mt<2;mt++)
#pragma unroll
    for(int n8=0;n8<8;n8++){
        int col = bx*128 + wn*64 + n8*8 + t4*2;
#pragma unroll
        for(int hf=0; hf<2; hf++){
            int row = by*128 + wm*32 + mt*16 + g + hf*8;
            if(row >= M) continue;
            float v0 = acc[mt][n8][hf*2+0];
            float v1 = acc[mt][n8][hf*2+1];
            size_t o=(size_t)row*Nn+col;
            if(EPI==2){
                __half2 hp;
                hp.x = __float2half(geluf(v0 + bias[col]));
                hp.y = __float2half(geluf(v1 + bias[col+1]));
                *reinterpret_cast<__half2*>(&outH[o]) = hp;
            } else {
                out32[o]   = v0 + bias[col];
                out32[o+1] = v1 + bias[col+1];
            }
        }
    }
}

// ---- flash attention v2 ----
#define FP2 144
#define QT (128*FP2)
#define KT2 (64*FP2)
#define STG2 (4*KT2)
#define FSM2 (2*QT + 2*STG2)
__global__ void __launch_bounds__(256,1) k_flash(){
    int tb = 7 - blockIdx.x, bh = blockIdx.y;
    extern __shared__ char fsm[];
    uint32_t su = smem_u32(fsm);
    uint32_t qb = su, kvb = su + 2*QT;
    int tid=threadIdx.x, lane=tid&31, w=tid>>5;
    const size_t hb = (size_t)bh*TT*HSZ;
#pragma unroll
    for(int i=0;i<8;i++){
        int c = tid + i*256;
        int half = c>>10, w2 = c&1023, row = w2>>3, q = w2&7;
        cp16(qb + half*QT + row*FP2 + q*16,
             (half? g_ql : g_qh) + hb + (size_t)(tb*128+row)*HSZ + q*8);
    }
    auto loadKV = [&](int sb){
        uint32_t base = kvb + (sb&1)*STG2;
#pragma unroll
        for(int i=0;i<8;i++){
            int c = tid + i*256;
            int arr = c>>9, w2 = c&511, row = w2>>3, q = w2&7;
            const bf16* src = (arr==0? g_kh : arr==1? g_kl : arr==2? g_vh : g_vl)
                            + hb + (size_t)(sb*64+row)*HSZ + q*8;
            cp16(base + arr*KT2 + row*FP2 + q*16, src);
        }
        asm volatile("cp.async.commit_group;" ::: "memory");
    };
    loadKV(0);
    float m0=-1e30f, m1=-1e30f, l0=0.f, l1=0.f;
    float O[8][4];
#pragma unroll
    for(int n8=0;n8<8;n8++)
#pragma unroll
        for(int c=0;c<4;c++) O[n8][c]=0.f;
    const float scale=0.036084391824351615f;
    int brow = (lane&7) | ((lane&16)>>1);
    int t4 = lane&3, g = lane>>2;
    int smax = 2*tb+1;
    for(int sb=0; sb<=smax; sb++){
        if(sb<smax) loadKV(sb+1);
        if(sb<smax) asm volatile("cp.async.wait_group 1;" ::: "memory");
        else        asm volatile("cp.async.wait_group 0;" ::: "memory");
        __syncthreads();
        uint32_t kb = kvb + (sb&1)*STG2;
        uint32_t vb = kb + 2*KT2;
        float S[8][4];
#pragma unroll
        for(int n8=0;n8<8;n8++)
#pragma unroll
            for(int c=0;c<4;c++) S[n8][c]=0.f;
#pragma unroll
        for(int kc=0;kc<4;kc++){
            uint32_t aH[4], aL[4];
            uint32_t ad = qb + (w*16+(lane&15))*FP2 + kc*32 + (lane>>4)*16;
            ldsm4(ad, aH); ldsm4(ad+QT, aL);
            uint32_t bHt[4][4], bLt[4][4];
#pragma unroll
            for(int nt=0;nt<4;nt++){
                uint32_t bd = kb + (nt*16+brow)*FP2 + kc*32 + ((lane>>3)&1)*16;
                ldsm4(bd, bHt[nt]); ldsm4(bd+KT2, bLt[nt]);
            }
#pragma unroll
            for(int n8=0;n8<8;n8++){
                uint32_t* bh2=&bHt[n8>>1][(n8&1)*2];
                uint32_t* bl2=&bLt[n8>>1][(n8&1)*2];
                mma16816(S[n8], aH, bh2);
                mma16816(S[n8], aH, bl2);
                mma16816(S[n8], aL, bh2);
            }
        }
        int rg0 = tb*128 + w*16 + g;
#pragma unroll
        for(int n8=0;n8<8;n8++)
#pragma unroll
            for(int c=0;c<4;c++){
                S[n8][c] *= scale;
                if(sb >= 2*tb){
                    int sg = sb*64 + n8*8 + t4*2 + (c&1);
                    int rg = rg0 + ((c>=2)?8:0);
                    if(sg > rg) S[n8][c] = -1e30f;
                }
            }
        float mx0=-1e30f, mx1=-1e30f;
#pragma unroll
        for(int n8=0;n8<8;n8++){
            mx0=fmaxf(mx0,fmaxf(S[n8][0],S[n8][1]));
            mx1=fmaxf(mx1,fmaxf(S[n8][2],S[n8][3]));
        }
        mx0=fmaxf(mx0,__shfl_xor_sync(~0u,mx0,1)); mx0=fmaxf(mx0,__shfl_xor_sync(~0u,mx0,2));
        mx1=fmaxf(mx1,__shfl_xor_sync(~0u,mx1,1)); mx1=fmaxf(mx1,__shfl_xor_sync(~0u,mx1,2));
        float mn0=fmaxf(m0,mx0), mn1=fmaxf(m1,mx1);
        float f0=expf(m0-mn0), f1=expf(m1-mn1);
        m0=mn0; m1=mn1;
        float rs0=0.f, rs1=0.f;
#pragma unroll
        for(int n8=0;n8<8;n8++){
            S[n8][0]=expf(S[n8][0]-mn0); S[n8][1]=expf(S[n8][1]-mn0);
            S[n8][2]=expf(S[n8][2]-mn1); S[n8][3]=expf(S[n8][3]-mn1);
            rs0+=S[n8][0]+S[n8][1]; rs1+=S[n8][2]+S[n8][3];
        }
        rs0+=__shfl_xor_sync(~0u,rs0,1); rs0+=__shfl_xor_sync(~0u,rs0,2);
        rs1+=__shfl_xor_sync(~0u,rs1,1); rs1+=__shfl_xor_sync(~0u,rs1,2);
        l0=l0*f0+rs0; l1=l1*f1+rs1;
#pragma unroll
        for(int n8=0;n8<8;n8++){
            O[n8][0]*=f0; O[n8][1]*=f0; O[n8][2]*=f1; O[n8][3]*=f1;
        }
#pragma unroll
        for(int j=0;j<4;j++){
            float p00=S[2*j][0], p01=S[2*j][1], p02=S[2*j][2], p03=S[2*j][3];
            float p10=S[2*j+1][0], p11=S[2*j+1][1], p12=S[2*j+1][2], p13=S[2*j+1][3];
            uint32_t aPh[4], aPl[4];
            aPh[0]=packbf(p00,p01); aPh[1]=packbf(p02,p03);
            aPh[2]=packbf(p10,p11); aPh[3]=packbf(p12,p13);
            {
                __nv_bfloat162 t;
                t=*(__nv_bfloat162*)&aPh[0];
                aPl[0]=packbf(p00-__bfloat162float(t.x), p01-__bfloat162float(t.y));
                t=*(__nv_bfloat162*)&aPh[1];
                aPl[1]=packbf(p02-__bfloat162float(t.x), p03-__bfloat162float(t.y));
                t=*(__nv_bfloat162*)&aPh[2];
                aPl[2]=packbf(p10-__bfloat162float(t.x), p11-__bfloat162float(t.y));
                t=*(__nv_bfloat162*)&aPh[3];
                aPl[3]=packbf(p12-__bfloat162float(t.x), p13-__bfloat162float(t.y));
            }
            uint32_t bHt[4][4], bLt[4][4];
            uint32_t vrow = (j*16 + (lane&15))*FP2 + (lane>>4)*16;
#pragma unroll
            for(int nt=0;nt<4;nt++){
                uint32_t bd = vb + vrow + nt*32;
                ldsm4t(bd, bHt[nt]); ldsm4t(bd+KT2, bLt[nt]);
            }
#pragma unroll
            for(int n8=0;n8<8;n8++){
                uint32_t* bh2=&bHt[n8>>1][(n8&1)*2];
                uint32_t* bl2=&bLt[n8>>1][(n8&1)*2];
                mma16816(O[n8], aPh, bh2);
                mma16816(O[n8], aPh, bl2);
                mma16816(O[n8], aPl, bh2);
            }
        }
        __syncthreads();
    }
    float i0=1.f/l0, i1=1.f/l1;
    int b = bh/HH, h = bh%HH;
#pragma unroll
    for(int n8=0;n8<8;n8++){
        int col = h*64 + n8*8 + t4*2;
#pragma unroll
        for(int hf=0;hf<2;hf++){
            int tokr = b*1024 + tb*128 + w*16 + g + hf*8;
            float v0 = O[n8][hf*2+0]*(hf?i1:i0);
            float v1 = O[n8][hf*2+1]*(hf?i1:i0);
            size_t o=(size_t)tokr*CCH+col;
            bf16 h0=__float2bfloat16(v0), h1=__float2bfloat16(v1);
            __nv_bfloat162 hp2; hp2.x=h0; hp2.y=h1;
            __nv_bfloat162 lp;
            lp.x=__float2bfloat16(v0-__bfloat162float(h0));
            lp.y=__float2bfloat16(v1-__bfloat162float(h1));
            *reinterpret_cast<__nv_bfloat162*>(&g_aoh[o]) = hp2;
            *reinterpret_cast<__nv_bfloat162*>(&g_aol[o]) = lp;
        }
    }
}

__global__ void k_router(const float* __restrict__ wr, const float* __restrict__ br,
                         const float* __restrict__ wn, const float* __restrict__ bnn,
                         const float* __restrict__ temp, const float* __restrict__ noise){
    int warp=threadIdx.x>>5, lane=threadIdx.x&31;
    int n=blockIdx.x*8+warp;
    const float* hp = g_h2 + (size_t)n*CCH;
    float r[8]={}, q[8]={};
    for(int c=lane;c<CCH;c+=32){
        float hv=hp[c];
        const float* wrp=wr+c*EE; const float* wnp=wn+c*EE;
#pragma unroll
        for(int e=0;e<8;e++){ r[e]+=hv*wrp[e]; q[e]+=hv*wnp[e]; }
    }
#pragma unroll
    for(int e=0;e<8;e++)
#pragma unroll
        for(int o=16;o;o>>=1){
            r[e]+=__shfl_xor_sync(~0u,r[e],o);
            q[e]+=__shfl_xor_sync(~0u,q[e],o);
        }
    if(lane==0){
        float t=fminf(fmaxf(temp[0],0.5f),2.0f);
        float ny[8];
#pragma unroll
        for(int e=0;e<8;e++){
            float z=q[e]+bnn[e];
            float sp=(z>20.f)? z : log1pf(expf(z));
            ny[e]=r[e]+br[e] + t*noise[(size_t)n*EE+e]*sp;
        }
        int i1=0;
#pragma unroll
        for(int e=1;e<8;e++) if(ny[e]>ny[i1]) i1=e;
        int i2=-1;
#pragma unroll
        for(int e=0;e<8;e++){ if(e==i1) continue; if(i2<0||ny[e]>ny[i2]) i2=e; }
        float e2=expf(ny[i2]-ny[i1]);
        float gv[2]={1.f/(1.f+e2), e2/(1.f+e2)};
        int id[2]={i1,i2};
#pragma unroll
        for(int k2=0;k2<2;k2++){
            int e=id[k2];
            int row=atomicAdd(&g_cnt[e],1);
            g_tok[e*NT+row]=n;
            g_pos[n*2+k2]=e*NT+row;
            g_gw[n*2+k2]=gv[k2];
        }
    }
}

// fused dual residual-LN + gated combine
__global__ void k_fin(const float* __restrict__ t3,
                      const float* __restrict__ dg, const float* __restrict__ db_,
                      const float* __restrict__ sg, const float* __restrict__ sb_,
                      float* __restrict__ out){
    int n=blockIdx.x, t=threadIdx.x;
    int s0=g_pos[2*n], s1=g_pos[2*n+1];
    int e0=s0>>13, r0=s0&8191, e1=s1>>13, r1=s1&8191;
    const float* ta = t3 + (size_t)e0*NT*CCH + (size_t)r0*CCH;
    const float* tb = t3 + (size_t)e1*NT*CCH + (size_t)r1*CCH;
    float va[3], vb[3];
    float sa=0.f,qa=0.f,sb2=0.f,qb=0.f;
#pragma unroll
    for(int i=0;i<3;i++){
        int c=t+256*i;
        float h = g_h2[(size_t)n*CCH+c];
        va[i]=h+ta[c]; vb[i]=h+tb[c];
        sa+=va[i]; qa+=va[i]*va[i]; sb2+=vb[i]; qb+=vb[i]*vb[i];
    }
    __shared__ float sh[8][4];
#pragma unroll
    for(int o=16;o;o>>=1){
        sa+=__shfl_xor_sync(~0u,sa,o); qa+=__shfl_xor_sync(~0u,qa,o);
        sb2+=__shfl_xor_sync(~0u,sb2,o); qb+=__shfl_xor_sync(~0u,qb,o);
    }
    if((t&31)==0){ sh[t>>5][0]=sa; sh[t>>5][1]=qa; sh[t>>5][2]=sb2; sh[t>>5][3]=qb; }
    __syncthreads();
    sa=0.f; qa=0.f; sb2=0.f; qb=0.f;
#pragma unroll
    for(int i=0;i<8;i++){ sa+=sh[i][0]; qa+=sh[i][1]; sb2+=sh[i][2]; qb+=sh[i][3]; }
    float ma=sa*(1.f/768.f), ra=rsqrtf(qa*(1.f/768.f)-ma*ma+1e-5f);
    float mb=sb2*(1.f/768.f), rb=rsqrtf(qb*(1.f/768.f)-mb*mb+1e-5f);
    const float* g0p = (e0<2)? dg+e0*CCH : sg+(e0-2)*CCH;
    const float* b0p = (e0<2)? db_+e0*CCH : sb_+(e0-2)*CCH;
    const float* g1p = (e1<2)? dg+e1*CCH : sg+(e1-2)*CCH;
    const float* b1p = (e1<2)? db_+e1*CCH : sb_+(e1-2)*CCH;
    float gw0=g_gw[2*n], gw1=g_gw[2*n+1];
#pragma unroll
    for(int i=0;i<3;i++){
        int c=t+256*i;
        float o0=(va[i]-ma)*ra*g0p[c]+b0p[c];
        float o1=(vb[i]-mb)*rb*g1p[c]+b1p[c];
        out[(size_t)n*CCH+c]=g_x2[(size_t)n*CCH+c]+gw0*o0+gw1*o1;
    }
}

extern "C" void kernel_launch(void* const* d_in, const int* in_sizes, int n_in,
                              void* d_out, int out_size){
    const float *x=(const float*)d_in[0], *rno=(const float*)d_in[1];
    const float *wq=(const float*)d_in[2], *wk=(const float*)d_in[3], *wv=(const float*)d_in[4];
    const float *w_proj=(const float*)d_in[5], *b_proj=(const float*)d_in[6];
    const float *ln1g=(const float*)d_in[7], *ln1b=(const float*)d_in[8];
    const float *ln2g=(const float*)d_in[9], *ln2b=(const float*)d_in[10];
    const float *wr=(const float*)d_in[11], *br=(const float*)d_in[12];
    const float *wn=(const float*)d_in[13], *bn=(const float*)d_in[14];
    const float *temp=(const float*)d_in[15];
    const float *dw1=(const float*)d_in[16], *db1=(const float*)d_in[17];
    const float *dw2=(const float*)d_in[18], *db2=(const float*)d_in[19];
    const float *dw3=(const float*)d_in[20], *db3=(const float*)d_in[21];
    const float *dlng=(const float*)d_in[22], *dlnb=(const float*)d_in[23];
    const float *sw1=(const float*)d_in[24], *sb1=(const float*)d_in[25];
    const float *sw2=(const float*)d_in[26], *sb2=(const float*)d_in[27];
    const float *slng=(const float*)d_in[28], *slnb=(const float*)d_in[29];
    float* out=(float*)d_out;

    cudaFuncSetAttribute(k_mma<0>, cudaFuncAttributeMaxDynamicSharedMemorySize, SMEMSZ);
    cudaFuncSetAttribute(k_mma<1>, cudaFuncAttributeMaxDynamicSharedMemorySize, SMEMSZ);
    cudaFuncSetAttribute(k_mmah<2>, cudaFuncAttributeMaxDynamicSharedMemorySize, HSMEM);
    cudaFuncSetAttribute(k_mmah<3>, cudaFuncAttributeMaxDynamicSharedMemorySize, HSMEM);
    cudaFuncSetAttribute(k_flash, cudaFuncAttributeMaxDynamicSharedMemorySize, FSM2);

    bf16 *Bqh,*Bql,*Bph,*Bpl,*h1h,*h1l,*aoh,*aol;
    f16 *Bd1,*Bd2,*Bd3,*Bs1,*Bs2,*h2f,*t1f,*t2f;
    float *x2,*h2,*t3; int *tok,*cnt;
    cudaGetSymbolAddress((void**)&Bqh,g_Bqh); cudaGetSymbolAddress((void**)&Bql,g_Bql);
    cudaGetSymbolAddress((void**)&Bph,g_Bph); cudaGetSymbolAddress((void**)&Bpl,g_Bpl);
    cudaGetSymbolAddress((void**)&Bd1,g_Bd1);
    cudaGetSymbolAddress((void**)&Bd2,g_Bd2);
    cudaGetSymbolAddress((void**)&Bd3,g_Bd3);
    cudaGetSymbolAddress((void**)&Bs1,g_Bs1);
    cudaGetSymbolAddress((void**)&Bs2,g_Bs2);
    cudaGetSymbolAddress((void**)&h1h,g_h1h); cudaGetSymbolAddress((void**)&h1l,g_h1l);
    cudaGetSymbolAddress((void**)&aoh,g_aoh); cudaGetSymbolAddress((void**)&aol,g_aol);
    cudaGetSymbolAddress((void**)&h2f,g_h2f);
    cudaGetSymbolAddress((void**)&t1f,g_t1f); cudaGetSymbolAddress((void**)&t2f,g_t2f);
    cudaGetSymbolAddress((void**)&x2,g_x2); cudaGetSymbolAddress((void**)&h2,g_h2);
    cudaGetSymbolAddress((void**)&t3,g_t3);
    cudaGetSymbolAddress((void**)&tok,g_tok); cudaGetSymbolAddress((void**)&cnt,g_cnt);
    const size_t ZT1=(size_t)NT*FF, ZT3=(size_t)NT*CCH;

    dim3 wb(32,8);
    k_reset<<<1,32>>>();
    k_wsplit2<<<dim3(2,12,12),wb>>>(wq, Bqh,           Bql,           CCH, HSZ);
    k_wsplit2<<<dim3(2,12,12),wb>>>(wk, Bqh+CCH*CCH,   Bql+CCH*CCH,   CCH, HSZ);
    k_wsplit2<<<dim3(2,12,12),wb>>>(wv, Bqh+2*CCH*CCH, Bql+2*CCH*CCH, CCH, HSZ);
    k_wsplit2<<<dim3(24,12,1),wb>>>(w_proj, Bph, Bpl, CCH, CCH);
    k_wcvt<<<dim3(96,12,2),wb>>>(dw1, Bd1, CCH, FF);
    k_wcvt<<<dim3(96,48,2),wb>>>(dw2, Bd2, FF, FF);
    k_wcvt<<<dim3(24,48,2),wb>>>(dw3, Bd3, FF, CCH);
    k_wcvt<<<dim3(96,12,6),wb>>>(sw1, Bs1, CCH, FF);
    k_wcvt<<<dim3(24,48,6),wb>>>(sw2, Bs2, FF, CCH);
    // attention
    k_ln<<<NT,256>>>(x, ln1g, ln1b, nullptr, h1h, h1l, nullptr);
    k_mma<0><<<dim3(18,64),256,SMEMSZ>>>(h1h,h1l,Bqh,Bql,nullptr,nullptr,nullptr,
                                         NT,3*CCH,CCH);
    k_flash<<<dim3(8,BH),256,FSM2>>>();
    k_mma<1><<<dim3(6,64),256,SMEMSZ>>>(aoh,aol,Bph,Bpl,b_proj,x,x2, NT,CCH,CCH);
    // router
    k_ln<<<NT,256>>>(x2, ln2g, ln2b, h2, nullptr, nullptr, h2f);
    k_router<<<NT/8,256>>>(wr,br,wn,bn,temp,rno);
    // experts
    k_mmah<2><<<dim3(24,64,8),256,HSMEM>>>(h2f,0, nullptr,0, 99,
        Bd1, Bs1,(size_t)CCH*FF, 2, db1,sb1,
        nullptr, t1f, ZT1, NT,FF,CCH, tok, cnt);
    k_mmah<2><<<dim3(24,64,2),256,HSMEM>>>(t1f,ZT1, nullptr,0, 99,
        Bd2, nullptr,(size_t)FF*FF, 99, db2,nullptr,
        nullptr, t2f, ZT1, NT,FF,FF, nullptr, cnt);
    k_mmah<3><<<dim3(6,64,8),256,HSMEM>>>(t2f,ZT1, t1f,ZT1, 2,
        Bd3, Bs2,(size_t)CCH*FF, 2, db3,sb2,
        t3, nullptr, ZT3, NT,CCH,FF, nullptr, cnt);
    k_fin<<<NT,256>>>(t3, dlng, dlnb, slng, slnb, out);
}

// round 12
// speedup vs baseline: 7.2932x; 1.0410x over previous
#include <cuda_runtime.h>
#include <cuda_bf16.h>
#include <cuda_fp16.h>
#include <stdint.h>
#include <math.h>

#define BN 8
#define TT 1024
#define CCH 768
#define HH 12
#define HSZ 64
#define EE 8
#define FF 3072
#define NT (BN*TT)
#define BH (BN*HH)
typedef __nv_bfloat16 bf16;
typedef __half f16;

// ---- static scratch ----
__device__ bf16  g_qh[BH*TT*HSZ], g_ql[BH*TT*HSZ];
__device__ bf16  g_kh[BH*TT*HSZ], g_kl[BH*TT*HSZ];
__device__ bf16  g_vh[BH*TT*HSZ], g_vl[BH*TT*HSZ];
__device__ bf16  g_h1h[NT*CCH], g_h1l[NT*CCH];
__device__ bf16  g_aoh[NT*CCH], g_aol[NT*CCH];
__device__ float g_x2[NT*CCH];
__device__ float g_h2[NT*CCH];
__device__ f16   g_h2f[NT*CCH];
__device__ float g_gw[NT*2];
__device__ int   g_pos[NT*2];
__device__ int   g_tok[EE*NT];
__device__ int   g_cnt[EE];
__device__ f16   g_t1f[(size_t)EE*NT*FF];
__device__ f16   g_t2f[(size_t)2*NT*FF];
__device__ float g_t3[(size_t)EE*NT*CCH];
__device__ bf16  g_Bqh[3*CCH*CCH], g_Bql[3*CCH*CCH];
__device__ bf16  g_Bph[CCH*CCH],  g_Bpl[CCH*CCH];
__device__ f16   g_Bd1[2*CCH*FF];
__device__ f16   g_Bd2[(size_t)2*FF*FF];
__device__ f16   g_Bd3[2*CCH*FF];
__device__ f16   g_Bs1[(size_t)6*CCH*FF];
__device__ f16   g_Bs2[(size_t)6*CCH*FF];

__device__ __forceinline__ float geluf(float v){
    return 0.5f*v*(1.f + erff(v*0.70710678118654752440f));
}
__device__ __forceinline__ uint32_t smem_u32(const void* p){
    uint32_t a;
    asm("{ .reg .u64 t; cvta.to.shared.u64 t, %1; cvt.u32.u64 %0, t; }" : "=r"(a) : "l"(p));
    return a;
}
__device__ __forceinline__ void cp16(uint32_t d, const void* s){
    asm volatile("cp.async.cg.shared.global [%0], [%1], 16;" :: "r"(d), "l"(s));
}
__device__ __forceinline__ void ldsm4(uint32_t a, uint32_t* r){
    asm volatile("ldmatrix.sync.aligned.m8n8.x4.shared.b16 {%0,%1,%2,%3}, [%4];"
        : "=r"(r[0]),"=r"(r[1]),"=r"(r[2]),"=r"(r[3]) : "r"(a));
}
__device__ __forceinline__ void ldsm4t(uint32_t a, uint32_t* r){
    asm volatile("ldmatrix.sync.aligned.m8n8.x4.trans.shared.b16 {%0,%1,%2,%3}, [%4];"
        : "=r"(r[0]),"=r"(r[1]),"=r"(r[2]),"=r"(r[3]) : "r"(a));
}
__device__ __forceinline__ void mma16816(float* c, const uint32_t* a, const uint32_t* b){
    asm volatile("mma.sync.aligned.m16n8k16.row.col.f32.bf16.bf16.f32 "
        "{%0,%1,%2,%3},{%4,%5,%6,%7},{%8,%9},{%0,%1,%2,%3};"
        : "+f"(c[0]),"+f"(c[1]),"+f"(c[2]),"+f"(c[3])
        : "r"(a[0]),"r"(a[1]),"r"(a[2]),"r"(a[3]), "r"(b[0]),"r"(b[1]));
}
__device__ __forceinline__ void mmah16816(float* c, const uint32_t* a, const uint32_t* b){
    asm volatile("mma.sync.aligned.m16n8k16.row.col.f32.f16.f16.f32 "
        "{%0,%1,%2,%3},{%4,%5,%6,%7},{%8,%9},{%0,%1,%2,%3};"
        : "+f"(c[0]),"+f"(c[1]),"+f"(c[2]),"+f"(c[3])
        : "r"(a[0]),"r"(a[1]),"r"(a[2]),"r"(a[3]), "r"(b[0]),"r"(b[1]));
}
__device__ __forceinline__ uint32_t packbf(float a, float b){
    __nv_bfloat162 p; p.x=__float2bfloat16(a); p.y=__float2bfloat16(b);
    return *reinterpret_cast<uint32_t*>(&p);
}

__global__ void k_reset(){ if(threadIdx.x < EE) g_cnt[threadIdx.x] = 0; }

// W[K][N] -> out[N][K] hi/lo bf16 (attention weights)
__global__ void k_wsplit2(const float* __restrict__ W, bf16* __restrict__ oh,
                          bf16* __restrict__ ol, int K, int N){
    int e = blockIdx.z;
    W += (size_t)e*K*N; oh += (size_t)e*K*N; ol += (size_t)e*K*N;
    __shared__ float s[64][33];
    int n0 = blockIdx.x*32, k0 = blockIdx.y*64;
    int tx = threadIdx.x, ty = threadIdx.y;
#pragma unroll
    for(int r=0;r<8;r++){ int kk=ty+r*8; s[kk][tx] = W[(size_t)(k0+kk)*N + n0+tx]; }
    __syncthreads();
#pragma unroll
    for(int r=0;r<4;r++){
        int n = ty + r*8;
        float v0 = s[2*tx][n], v1 = s[2*tx+1][n];
        bf16 h0 = __float2bfloat16(v0), h1 = __float2bfloat16(v1);
        bf16 hh[2] = {h0, h1};
        bf16 ll[2] = {__float2bfloat16(v0-__bfloat162float(h0)),
                      __float2bfloat16(v1-__bfloat162float(h1))};
        size_t o = (size_t)(n0+n)*K + k0 + 2*tx;
        *reinterpret_cast<uint32_t*>(&oh[o]) = *reinterpret_cast<uint32_t*>(hh);
        *reinterpret_cast<uint32_t*>(&ol[o]) = *reinterpret_cast<uint32_t*>(ll);
    }
}

// W[K][N] -> out[N][K] single fp16 (expert weights)
__global__ void k_wcvt(const float* __restrict__ W, f16* __restrict__ oh, int K, int N){
    int e = blockIdx.z;
    W += (size_t)e*K*N; oh += (size_t)e*K*N;
    __shared__ float s[64][33];
    int n0 = blockIdx.x*32, k0 = blockIdx.y*64;
    int tx = threadIdx.x, ty = threadIdx.y;
#pragma unroll
    for(int r=0;r<8;r++){ int kk=ty+r*8; s[kk][tx] = W[(size_t)(k0+kk)*N + n0+tx]; }
    __syncthreads();
#pragma unroll
    for(int r=0;r<4;r++){
        int n = ty + r*8;
        __half2 hp; hp.x=__float2half(s[2*tx][n]); hp.y=__float2half(s[2*tx+1][n]);
        size_t o = (size_t)(n0+n)*K + k0 + 2*tx;
        *reinterpret_cast<__half2*>(&oh[o]) = hp;
    }
}

__global__ void k_ln(const float* __restrict__ in, const float* __restrict__ gam,
                     const float* __restrict__ bet, float* __restrict__ out,
                     bf16* __restrict__ oh, bf16* __restrict__ ol, f16* __restrict__ of){
    int n = blockIdx.x, t = threadIdx.x;
    const float* row = in + (size_t)n*CCH;
    float v[3], s=0.f, s2=0.f;
#pragma unroll
    for(int i=0;i<3;i++){ v[i]=row[t+256*i]; s+=v[i]; s2+=v[i]*v[i]; }
    __shared__ float shs[8], shq[8];
#pragma unroll
    for(int o=16;o;o>>=1){ s+=__shfl_xor_sync(~0u,s,o); s2+=__shfl_xor_sync(~0u,s2,o); }
    if((t&31)==0){ shs[t>>5]=s; shq[t>>5]=s2; }
    __syncthreads();
    s=0.f; s2=0.f;
#pragma unroll
    for(int i=0;i<8;i++){ s+=shs[i]; s2+=shq[i]; }
    float mean=s*(1.f/768.f), var=s2*(1.f/768.f)-mean*mean, r=rsqrtf(var+1e-5f);
#pragma unroll
    for(int i=0;i<3;i++){
        int c=t+256*i;
        float o=(v[i]-mean)*r*gam[c]+bet[c];
        if(out) out[(size_t)n*CCH+c]=o;
        if(oh){
            bf16 hi=__float2bfloat16(o);
            oh[(size_t)n*CCH+c]=hi;
            ol[(size_t)n*CCH+c]=__float2bfloat16(o-__bfloat162float(hi));
        }
        if(of) of[(size_t)n*CCH+c]=__float2half(o);
    }
}

// ---- bf16 3-product GEMM (QKV + proj), 2-stage, 2 CTAs/SM ----
#define PITCH 80
#define TILEB 10240
#define STAGEB 40960
#define SMEMSZ (2*STAGEB)
template<int EPI>
__global__ void __launch_bounds__(256,2)
k_mma(const bf16* __restrict__ Ah, const bf16* __restrict__ Al,
      const bf16* __restrict__ Bh, const bf16* __restrict__ Bl,
      const float* __restrict__ bias, const float* __restrict__ resid,
      float* __restrict__ out32, int M, int Nn, int K){
    int by = blockIdx.y, bx = blockIdx.x;
    extern __shared__ char smem[];
    uint32_t su = smem_u32(smem);
    int tid=threadIdx.x, lane=tid&31, wid=tid>>5;
    int wm=wid&3, wn=wid>>2;
    const int KT = K/32;
    float acc[2][8][4];
#pragma unroll
    for(int a=0;a<2;a++)
#pragma unroll
        for(int b=0;b<8;b++)
#pragma unroll
            for(int c=0;c<4;c++) acc[a][b][c]=0.f;
    auto load_stage = [&](int kt){
        uint32_t sb = su + (kt&1)*STAGEB;
#pragma unroll
        for(int i=0;i<8;i++){
            int c = tid + i*256;
            int tile=c>>9, w=c&511, row=w>>2, q=w&3;
            uint32_t d = sb + tile*TILEB + row*PITCH + q*16;
            const bf16* src;
            if(tile<2) src = (tile==0?Ah:Al) + (size_t)(by*128+row)*K + kt*32 + q*8;
            else       src = (tile==2?Bh:Bl) + (size_t)(bx*128+row)*K + kt*32 + q*8;
            cp16(d, src);
        }
        asm volatile("cp.async.commit_group;" ::: "memory");
    };
    load_stage(0);
    for(int kt=0; kt<KT; kt++){
        if(kt+1<KT){
            load_stage(kt+1);
            asm volatile("cp.async.wait_group 1;" ::: "memory");
        } else {
            asm volatile("cp.async.wait_group 0;" ::: "memory");
        }
        __syncthreads();
        uint32_t sb = su + (kt&1)*STAGEB;
#pragma unroll
        for(int kh=0; kh<2; kh++){
            uint32_t aH[2][4], aL[2][4];
            int arow = wm*32 + (lane&15);
            uint32_t ako = kh*32 + (lane>>4)*16;
#pragma unroll
            for(int mt=0;mt<2;mt++){
                uint32_t ad = sb + (arow+mt*16)*PITCH + ako;
                ldsm4(ad, aH[mt]); ldsm4(ad + TILEB, aL[mt]);
            }
            uint32_t bHf[4][4], bLf[4][4];
            int brow = wn*64 + ((lane&7) | ((lane&16)>>1));
            uint32_t bko = kh*32 + ((lane>>3)&1)*16;
#pragma unroll
            for(int nt=0;nt<4;nt++){
                uint32_t bd = sb + 2*TILEB + (brow+nt*16)*PITCH + bko;
                ldsm4(bd, bHf[nt]); ldsm4(bd + TILEB, bLf[nt]);
            }
#pragma unroll
            for(int mt=0;mt<2;mt++)
#pragma unroll
            for(int n8=0;n8<8;n8++){
                uint32_t* bh = &bHf[n8>>1][(n8&1)*2];
                uint32_t* bl = &bLf[n8>>1][(n8&1)*2];
                mma16816(acc[mt][n8], aH[mt], bh);
                mma16816(acc[mt][n8], aH[mt], bl);
                mma16816(acc[mt][n8], aL[mt], bh);
            }
        }
        __syncthreads();
    }
    int g = lane>>2, t4 = lane&3;
#pragma unroll
    for(int mt=0;mt<2;mt++)
#pragma unroll
    for(int n8=0;n8<8;n8++){
        int col = bx*128 + wn*64 + n8*8 + t4*2;
#pragma unroll
        for(int hf=0; hf<2; hf++){
            int row = by*128 + wm*32 + mt*16 + g + hf*8;
            float v0 = acc[mt][n8][hf*2+0];
            float v1 = acc[mt][n8][hf*2+1];
            if(EPI==0){
                int which = col/CCH, rem = col - which*CCH;
                int h = rem>>6, d0 = rem&63;
                int b = row>>10, t = row&1023;
                size_t o = ((size_t)(b*HH+h)*TT + t)*HSZ + d0;
                bf16* dh = which==0? g_qh : which==1? g_kh : g_vh;
                bf16* dl = which==0? g_ql : which==1? g_kl : g_vl;
                bf16 h0=__float2bfloat16(v0), h1=__float2bfloat16(v1);
                __nv_bfloat162 hp; hp.x=h0; hp.y=h1;
                __nv_bfloat162 lp;
                lp.x=__float2bfloat16(v0-__bfloat162float(h0));
                lp.y=__float2bfloat16(v1-__bfloat162float(h1));
                *reinterpret_cast<__nv_bfloat162*>(&dh[o]) = hp;
                *reinterpret_cast<__nv_bfloat162*>(&dl[o]) = lp;
            } else {
                size_t o=(size_t)row*Nn+col;
                out32[o]   = v0 + bias[col]   + resid[o];
                out32[o+1] = v1 + bias[col+1] + resid[o+1];
            }
        }
    }
}

// ---- fp16 single-product GEMM (experts), 3-stage, 2 CTAs/SM, z-batched ----
#define HSTG (2*TILEB)
#define HSMEM (3*HSTG)
template<int EPI>
__global__ void __launch_bounds__(256,2)
k_mmah(const f16* __restrict__ A1, size_t zsA, const f16* __restrict__ A2, size_t zsA2,
       int zSplitA,
       const f16* __restrict__ B1, const f16* __restrict__ B2, size_t zsB, int zSplit,
       const float* __restrict__ b1, const float* __restrict__ b2,
       float* __restrict__ out32, f16* __restrict__ outH, size_t zsOut,
       int M, int Nn, int K,
       const int* __restrict__ tok, const int* __restrict__ cnt){
    int z = blockIdx.z;
    if(cnt) M = cnt[z];
    int by = blockIdx.y, bx = blockIdx.x;
    if(by*128 >= M) return;
    const f16* A = (z < zSplitA) ? A1 + (size_t)z*zsA : A2 + (size_t)z*zsA2;
    const f16* Bp; const float* bias;
    if(z < zSplit){ Bp=B1+(size_t)z*zsB; bias=b1+(size_t)z*Nn; }
    else { Bp=B2+(size_t)(z-zSplit)*zsB; bias=b2+(size_t)(z-zSplit)*Nn; }
    if(out32) out32 += (size_t)z*zsOut;
    if(outH)  outH  += (size_t)z*zsOut;
    if(tok) tok += (size_t)z*NT;
    extern __shared__ char smem[];
    uint32_t su = smem_u32(smem);
    int tid=threadIdx.x, lane=tid&31, wid=tid>>5;
    int wm=wid&3, wn=wid>>2;
    const int KT = K/32;
    float acc[2][8][4];
#pragma unroll
    for(int a=0;a<2;a++)
#pragma unroll
        for(int b=0;b<8;b++)
#pragma unroll
            for(int c=0;c<4;c++) acc[a][b][c]=0.f;
    auto load_stage = [&](int kt){
        uint32_t sb = su + (kt%3)*HSTG;
#pragma unroll
        for(int i=0;i<4;i++){
            int c = tid + i*256;
            int tile=c>>9, w=c&511, row=w>>2, q=w&3;
            uint32_t d = sb + tile*TILEB + row*PITCH + q*16;
            const f16* src;
            if(tile==0){
                int rg=by*128+row; if(rg>=M) rg=M-1;
                int asrc = tok ? tok[rg] : rg;
                src = A + (size_t)asrc*K + kt*32 + q*8;
            } else {
                src = Bp + (size_t)(bx*128+row)*K + kt*32 + q*8;
            }
            cp16(d, src);
        }
        asm volatile("cp.async.commit_group;" ::: "memory");
    };
    load_stage(0);
    if(KT>1) load_stage(1);
    for(int kt=0; kt<KT; kt++){
        if(kt+2<KT) load_stage(kt+2);
        if(kt+2<KT)      asm volatile("cp.async.wait_group 2;" ::: "memory");
        else if(kt+1<KT) asm volatile("cp.async.wait_group 1;" ::: "memory");
        else             asm volatile("cp.async.wait_group 0;" ::: "memory");
        __syncthreads();
        uint32_t sb = su + (kt%3)*HSTG;
#pragma unroll
        for(int kh=0; kh<2; kh++){
            uint32_t aF[2][4];
            int arow = wm*32 + (lane&15);
            uint32_t ako = kh*32 + (lane>>4)*16;
#pragma unroll
            for(int mt=0;mt<2;mt++)
                ldsm4(sb + (arow+mt*16)*PITCH + ako, aF[mt]);
            uint32_t bF[4][4];
            int brow = wn*64 + ((lane&7) | ((lane&16)>>1));
            uint32_t bko = kh*32 + ((lane>>3)&1)*16;
#pragma unroll
            for(int nt=0;nt<4;nt++)
                ldsm4(sb + TILEB + (brow+nt*16)*PITCH + bko, bF[nt]);
#pragma unroll
            for(int mt=0;mt<2;mt++)
#pragma unroll
            for(int n8=0;n8<8;n8++)
                mmah16816(acc[mt][n8], aF[mt], &bF[n8>>1][(n8&1)*2]);
        }
        __syncthreads();
    }
    int g = lane>>2, t4 = lane&3;
#pragma unroll
    for(int mt=0;mt<2;mt++)
#pragma unroll
    for(int n8=0;n8<8;n8++){
        int col = bx*128 + wn*64 + n8*8 + t4*2;
#pragma unroll
        for(int hf=0; hf<2; hf++){
            int row = by*128 + wm*32 + mt*16 + g + hf*8;
            if(row >= M) continue;
            float v0 = acc[mt][n8][hf*2+0];
            float v1 = acc[mt][n8][hf*2+1];
            size_t o=(size_t)row*Nn+col;
            if(EPI==2){
                __half2 hp;
                hp.x = __float2half(geluf(v0 + bias[col]));
                hp.y = __float2half(geluf(v1 + bias[col+1]));
                *reinterpret_cast<__half2*>(&outH[o]) = hp;
            } else {
                out32[o]   = v0 + bias[col];
                out32[o+1] = v1 + bias[col+1];
            }
        }
    }
}

// ---- flash attention v2 ----
#define FP2 144
#define QT (128*FP2)
#define KT2 (64*FP2)
#define STG2 (4*KT2)
#define FSM2 (2*QT + 2*STG2)
__global__ void __launch_bounds__(256,1) k_flash(){
    int tb = 7 - blockIdx.x, bh = blockIdx.y;
    extern __shared__ char fsm[];
    uint32_t su = smem_u32(fsm);
    uint32_t qb = su, kvb = su + 2*QT;
    int tid=threadIdx.x, lane=tid&31, w=tid>>5;
    const size_t hb = (size_t)bh*TT*HSZ;
#pragma unroll
    for(int i=0;i<8;i++){
        int c = tid + i*256;
        int half = c>>10, w2 = c&1023, row = w2>>3, q = w2&7;
        cp16(qb + half*QT + row*FP2 + q*16,
             (half? g_ql : g_qh) + hb + (size_t)(tb*128+row)*HSZ + q*8);
    }
    auto loadKV = [&](int sb){
        uint32_t base = kvb + (sb&1)*STG2;
#pragma unroll
        for(int i=0;i<8;i++){
            int c = tid + i*256;
            int arr = c>>9, w2 = c&511, row = w2>>3, q = w2&7;
            const bf16* src = (arr==0? g_kh : arr==1? g_kl : arr==2? g_vh : g_vl)
                            + hb + (size_t)(sb*64+row)*HSZ + q*8;
            cp16(base + arr*KT2 + row*FP2 + q*16, src);
        }
        asm volatile("cp.async.commit_group;" ::: "memory");
    };
    loadKV(0);
    float m0=-1e30f, m1=-1e30f, l0=0.f, l1=0.f;
    float O[8][4];
#pragma unroll
    for(int n8=0;n8<8;n8++)
#pragma unroll
        for(int c=0;c<4;c++) O[n8][c]=0.f;
    const float scale=0.036084391824351615f;
    int brow = (lane&7) | ((lane&16)>>1);
    int t4 = lane&3, g = lane>>2;
    int smax = 2*tb+1;
    for(int sb=0; sb<=smax; sb++){
        if(sb<smax) loadKV(sb+1);
        if(sb<smax) asm volatile("cp.async.wait_group 1;" ::: "memory");
        else        asm volatile("cp.async.wait_group 0;" ::: "memory");
        __syncthreads();
        uint32_t kb = kvb + (sb&1)*STG2;
        uint32_t vb = kb + 2*KT2;
        float S[8][4];
#pragma unroll
        for(int n8=0;n8<8;n8++)
#pragma unroll
            for(int c=0;c<4;c++) S[n8][c]=0.f;
#pragma unroll
        for(int kc=0;kc<4;kc++){
            uint32_t aH[4], aL[4];
            uint32_t ad = qb + (w*16+(lane&15))*FP2 + kc*32 + (lane>>4)*16;
            ldsm4(ad, aH); ldsm4(ad+QT, aL);
            uint32_t bHt[4][4], bLt[4][4];
#pragma unroll
            for(int nt=0;nt<4;nt++){
                uint32_t bd = kb + (nt*16+brow)*FP2 + kc*32 + ((lane>>3)&1)*16;
                ldsm4(bd, bHt[nt]); ldsm4(bd+KT2, bLt[nt]);
            }
#pragma unroll
            for(int n8=0;n8<8;n8++){
                uint32_t* bh2=&bHt[n8>>1][(n8&1)*2];
                uint32_t* bl2=&bLt[n8>>1][(n8&1)*2];
                mma16816(S[n8], aH, bh2);
                mma16816(S[n8], aH, bl2);
                mma16816(S[n8], aL, bh2);
            }
        }
        int rg0 = tb*128 + w*16 + g;
#pragma unroll
        for(int n8=0;n8<8;n8++)
#pragma unroll
            for(int c=0;c<4;c++){
                S[n8][c] *= scale;
                if(sb >= 2*tb){
                    int sg = sb*64 + n8*8 + t4*2 + (c&1);
                    int rg = rg0 + ((c>=2)?8:0);
                    if(sg > rg) S[n8][c] = -1e30f;
                }
            }
        float mx0=-1e30f, mx1=-1e30f;
#pragma unroll
        for(int n8=0;n8<8;n8++){
            mx0=fmaxf(mx0,fmaxf(S[n8][0],S[n8][1]));
            mx1=fmaxf(mx1,fmaxf(S[n8][2],S[n8][3]));
        }
        mx0=fmaxf(mx0,__shfl_xor_sync(~0u,mx0,1)); mx0=fmaxf(mx0,__shfl_xor_sync(~0u,mx0,2));
        mx1=fmaxf(mx1,__shfl_xor_sync(~0u,mx1,1)); mx1=fmaxf(mx1,__shfl_xor_sync(~0u,mx1,2));
        float mn0=fmaxf(m0,mx0), mn1=fmaxf(m1,mx1);
        float f0=expf(m0-mn0), f1=expf(m1-mn1);
        m0=mn0; m1=mn1;
        float rs0=0.f, rs1=0.f;
#pragma unroll
        for(int n8=0;n8<8;n8++){
            S[n8][0]=expf(S[n8][0]-mn0); S[n8][1]=expf(S[n8][1]-mn0);
            S[n8][2]=expf(S[n8][2]-mn1); S[n8][3]=expf(S[n8][3]-mn1);
            rs0+=S[n8][0]+S[n8][1]; rs1+=S[n8][2]+S[n8][3];
        }
        rs0+=__shfl_xor_sync(~0u,rs0,1); rs0+=__shfl_xor_sync(~0u,rs0,2);
        rs1+=__shfl_xor_sync(~0u,rs1,1); rs1+=__shfl_xor_sync(~0u,rs1,2);
        l0=l0*f0+rs0; l1=l1*f1+rs1;
#pragma unroll
        for(int n8=0;n8<8;n8++){
            O[n8][0]*=f0; O[n8][1]*=f0; O[n8][2]*=f1; O[n8][3]*=f1;
        }
#pragma unroll
        for(int j=0;j<4;j++){
            float p00=S[2*j][0], p01=S[2*j][1], p02=S[2*j][2], p03=S[2*j][3];
            float p10=S[2*j+1][0], p11=S[2*j+1][1], p12=S[2*j+1][2], p13=S[2*j+1][3];
            uint32_t aPh[4], aPl[4];
            aPh[0]=packbf(p00,p01); aPh[1]=packbf(p02,p03);
            aPh[2]=packbf(p10,p11); aPh[3]=packbf(p12,p13);
            {
                __nv_bfloat162 t;
                t=*(__nv_bfloat162*)&aPh[0];
                aPl[0]=packbf(p00-__bfloat162float(t.x), p01-__bfloat162float(t.y));
                t=*(__nv_bfloat162*)&aPh[1];
                aPl[1]=packbf(p02-__bfloat162float(t.x), p03-__bfloat162float(t.y));
                t=*(__nv_bfloat162*)&aPh[2];
                aPl[2]=packbf(p10-__bfloat162float(t.x), p11-__bfloat162float(t.y));
                t=*(__nv_bfloat162*)&aPh[3];
                aPl[3]=packbf(p12-__bfloat162float(t.x), p13-__bfloat162float(t.y));
            }
            uint32_t bHt[4][4], bLt[4][4];
            uint32_t vrow = (j*16 + (lane&15))*FP2 + (lane>>4)*16;
#pragma unroll
            for(int nt=0;nt<4;nt++){
                uint32_t bd = vb + vrow + nt*32;
                ldsm4t(bd, bHt[nt]); ldsm4t(bd+KT2, bLt[nt]);
            }
#pragma unroll
            for(int n8=0;n8<8;n8++){
                uint32_t* bh2=&bHt[n8>>1][(n8&1)*2];
                uint32_t* bl2=&bLt[n8>>1][(n8&1)*2];
                mma16816(O[n8], aPh, bh2);
                mma16816(O[n8], aPh, bl2);
                mma16816(O[n8], aPl, bh2);
            }
        }
        __syncthreads();
    }
    float i0=1.f/l0, i1=1.f/l1;
    int b = bh/HH, h = bh%HH;
#pragma unroll
    for(int n8=0;n8<8;n8++){
        int col = h*64 + n8*8 + t4*2;
#pragma unroll
        for(int hf=0;hf<2;hf++){
            int tokr = b*1024 + tb*128 + w*16 + g + hf*8;
            float v0 = O[n8][hf*2+0]*(hf?i1:i0);
            float v1 = O[n8][hf*2+1]*(hf?i1:i0);
            size_t o=(size_t)tokr*CCH+col;
            bf16 h0=__float2bfloat16(v0), h1=__float2bfloat16(v1);
            __nv_bfloat162 hp2; hp2.x=h0; hp2.y=h1;
            __nv_bfloat162 lp;
            lp.x=__float2bfloat16(v0-__bfloat162float(h0));
            lp.y=__float2bfloat16(v1-__bfloat162float(h1));
            *reinterpret_cast<__nv_bfloat162*>(&g_aoh[o]) = hp2;
            *reinterpret_cast<__nv_bfloat162*>(&g_aol[o]) = lp;
        }
    }
}

__global__ void k_router(const float* __restrict__ wr, const float* __restrict__ br,
                         const float* __restrict__ wn, const float* __restrict__ bnn,
                         const float* __restrict__ temp, const float* __restrict__ noise){
    int warp=threadIdx.x>>5, lane=threadIdx.x&31;
    int n=blockIdx.x*8+warp;
    const float* hp = g_h2 + (size_t)n*CCH;
    float r[8]={}, q[8]={};
    for(int c=lane;c<CCH;c+=32){
        float hv=hp[c];
        const float* wrp=wr+c*EE; const float* wnp=wn+c*EE;
#pragma unroll
        for(int e=0;e<8;e++){ r[e]+=hv*wrp[e]; q[e]+=hv*wnp[e]; }
    }
#pragma unroll
    for(int e=0;e<8;e++)
#pragma unroll
        for(int o=16;o;o>>=1){
            r[e]+=__shfl_xor_sync(~0u,r[e],o);
            q[e]+=__shfl_xor_sync(~0u,q[e],o);
        }
    if(lane==0){
        float t=fminf(fmaxf(temp[0],0.5f),2.0f);
        float ny[8];
#pragma unroll
        for(int e=0;e<8;e++){
            float z=q[e]+bnn[e];
            float sp=(z>20.f)? z : log1pf(expf(z));
            ny[e]=r[e]+br[e] + t*noise[(size_t)n*EE+e]*sp;
        }
        int i1=0;
#pragma unroll
        for(int e=1;e<8;e++) if(ny[e]>ny[i1]) i1=e;
        int i2=-1;
#pragma unroll
        for(int e=0;e<8;e++){ if(e==i1) continue; if(i2<0||ny[e]>ny[i2]) i2=e; }
        float e2=expf(ny[i2]-ny[i1]);
        float gv[2]={1.f/(1.f+e2), e2/(1.f+e2)};
        int id[2]={i1,i2};
#pragma unroll
        for(int k2=0;k2<2;k2++){
            int e=id[k2];
            int row=atomicAdd(&g_cnt[e],1);
            g_tok[e*NT+row]=n;
            g_pos[n*2+k2]=e*NT+row;
            g_gw[n*2+k2]=gv[k2];
        }
    }
}

// fused dual residual-LN + gated combine
__global__ void k_fin(const float* __restrict__ t3,
                      const float* __restrict__ dg, const float* __restrict__ db_,
                      const float* __restrict__ sg, const float* __restrict__ sb_,
                      float* __restrict__ out){
    int n=blockIdx.x, t=threadIdx.x;
    int s0=g_pos[2*n], s1=g_pos[2*n+1];
    int e0=s0>>13, r0=s0&8191, e1=s1>>13, r1=s1&8191;
    const float* ta = t3 + (size_t)e0*NT*CCH + (size_t)r0*CCH;
    const float* tb = t3 + (size_t)e1*NT*CCH + (size_t)r1*CCH;
    float va[3], vb[3];
    float sa=0.f,qa=0.f,sb2=0.f,qb=0.f;
#pragma unroll
    for(int i=0;i<3;i++){
        int c=t+256*i;
        float h = g_h2[(size_t)n*CCH+c];
        va[i]=h+ta[c]; vb[i]=h+tb[c];
        sa+=va[i]; qa+=va[i]*va[i]; sb2+=vb[i]; qb+=vb[i]*vb[i];
    }
    __shared__ float sh[8][4];
#pragma unroll
    for(int o=16;o;o>>=1){
        sa+=__shfl_xor_sync(~0u,sa,o); qa+=__shfl_xor_sync(~0u,qa,o);
        sb2+=__shfl_xor_sync(~0u,sb2,o); qb+=__shfl_xor_sync(~0u,qb,o);
    }
    if((t&31)==0){ sh[t>>5][0]=sa; sh[t>>5][1]=qa; sh[t>>5][2]=sb2; sh[t>>5][3]=qb; }
    __syncthreads();
    sa=0.f; qa=0.f; sb2=0.f; qb=0.f;
#pragma unroll
    for(int i=0;i<8;i++){ sa+=sh[i][0]; qa+=sh[i][1]; sb2+=sh[i][2]; qb+=sh[i][3]; }
    float ma=sa*(1.f/768.f), ra=rsqrtf(qa*(1.f/768.f)-ma*ma+1e-5f);
    float mb=sb2*(1.f/768.f), rb=rsqrtf(qb*(1.f/768.f)-mb*mb+1e-5f);
    const float* g0p = (e0<2)? dg+e0*CCH : sg+(e0-2)*CCH;
    const float* b0p = (e0<2)? db_+e0*CCH : sb_+(e0-2)*CCH;
    const float* g1p = (e1<2)? dg+e1*CCH : sg+(e1-2)*CCH;
    const float* b1p = (e1<2)? db_+e1*CCH : sb_+(e1-2)*CCH;
    float gw0=g_gw[2*n], gw1=g_gw[2*n+1];
#pragma unroll
    for(int i=0;i<3;i++){
        int c=t+256*i;
        float o0=(va[i]-ma)*ra*g0p[c]+b0p[c];
        float o1=(vb[i]-mb)*rb*g1p[c]+b1p[c];
        out[(size_t)n*CCH+c]=g_x2[(size_t)n*CCH+c]+gw0*o0+gw1*o1;
    }
}

extern "C" void kernel_launch(void* const* d_in, const int* in_sizes, int n_in,
                              void* d_out, int out_size){
    const float *x=(const float*)d_in[0], *rno=(const float*)d_in[1];
    const float *wq=(const float*)d_in[2], *wk=(const float*)d_in[3], *wv=(const float*)d_in[4];
    const float *w_proj=(const float*)d_in[5], *b_proj=(const float*)d_in[6];
    const float *ln1g=(const float*)d_in[7], *ln1b=(const float*)d_in[8];
    const float *ln2g=(const float*)d_in[9], *ln2b=(const float*)d_in[10];
    const float *wr=(const float*)d_in[11], *br=(const float*)d_in[12];
    const float *wn=(const float*)d_in[13], *bn=(const float*)d_in[14];
    const float *temp=(const float*)d_in[15];
    const float *dw1=(const float*)d_in[16], *db1=(const float*)d_in[17];
    const float *dw2=(const float*)d_in[18], *db2=(const float*)d_in[19];
    const float *dw3=(const float*)d_in[20], *db3=(const float*)d_in[21];
    const float *dlng=(const float*)d_in[22], *dlnb=(const float*)d_in[23];
    const float *sw1=(const float*)d_in[24], *sb1=(const float*)d_in[25];
    const float *sw2=(const float*)d_in[26], *sb2=(const float*)d_in[27];
    const float *slng=(const float*)d_in[28], *slnb=(const float*)d_in[29];
    float* out=(float*)d_out;

    cudaFuncSetAttribute(k_mma<0>, cudaFuncAttributeMaxDynamicSharedMemorySize, SMEMSZ);
    cudaFuncSetAttribute(k_mma<1>, cudaFuncAttributeMaxDynamicSharedMemorySize, SMEMSZ);
    cudaFuncSetAttribute(k_mmah<2>, cudaFuncAttributeMaxDynamicSharedMemorySize, HSMEM);
    cudaFuncSetAttribute(k_mmah<3>, cudaFuncAttributeMaxDynamicSharedMemorySize, HSMEM);
    cudaFuncSetAttribute(k_flash, cudaFuncAttributeMaxDynamicSharedMemorySize, FSM2);

    bf16 *Bqh,*Bql,*Bph,*Bpl,*h1h,*h1l,*aoh,*aol;
    f16 *Bd1,*Bd2,*Bd3,*Bs1,*Bs2,*h2f,*t1f,*t2f;
    float *x2,*h2,*t3; int *tok,*cnt;
    cudaGetSymbolAddress((void**)&Bqh,g_Bqh); cudaGetSymbolAddress((void**)&Bql,g_Bql);
    cudaGetSymbolAddress((void**)&Bph,g_Bph); cudaGetSymbolAddress((void**)&Bpl,g_Bpl);
    cudaGetSymbolAddress((void**)&Bd1,g_Bd1);
    cudaGetSymbolAddress((void**)&Bd2,g_Bd2);
    cudaGetSymbolAddress((void**)&Bd3,g_Bd3);
    cudaGetSymbolAddress((void**)&Bs1,g_Bs1);
    cudaGetSymbolAddress((void**)&Bs2,g_Bs2);
    cudaGetSymbolAddress((void**)&h1h,g_h1h); cudaGetSymbolAddress((void**)&h1l,g_h1l);
    cudaGetSymbolAddress((void**)&aoh,g_aoh); cudaGetSymbolAddress((void**)&aol,g_aol);
    cudaGetSymbolAddress((void**)&h2f,g_h2f);
    cudaGetSymbolAddress((void**)&t1f,g_t1f); cudaGetSymbolAddress((void**)&t2f,g_t2f);
    cudaGetSymbolAddress((void**)&x2,g_x2); cudaGetSymbolAddress((void**)&h2,g_h2);
    cudaGetSymbolAddress((void**)&t3,g_t3);
    cudaGetSymbolAddress((void**)&tok,g_tok); cudaGetSymbolAddress((void**)&cnt,g_cnt);
    const size_t ZT1=(size_t)NT*FF, ZT3=(size_t)NT*CCH;

    dim3 wb(32,8);
    k_reset<<<1,32>>>();
    k_wsplit2<<<dim3(2,12,12),wb>>>(wq, Bqh,           Bql,           CCH, HSZ);
    k_wsplit2<<<dim3(2,12,12),wb>>>(wk, Bqh+CCH*CCH,   Bql+CCH*CCH,   CCH, HSZ);
    k_wsplit2<<<dim3(2,12,12),wb>>>(wv, Bqh+2*CCH*CCH, Bql+2*CCH*CCH, CCH, HSZ);
    k_wsplit2<<<dim3(24,12,1),wb>>>(w_proj, Bph, Bpl, CCH, CCH);
    k_wcvt<<<dim3(96,12,2),wb>>>(dw1, Bd1, CCH, FF);
    k_wcvt<<<dim3(96,48,2),wb>>>(dw2, Bd2, FF, FF);
    k_wcvt<<<dim3(24,48,2),wb>>>(dw3, Bd3, FF, CCH);
    k_wcvt<<<dim3(96,12,6),wb>>>(sw1, Bs1, CCH, FF);
    k_wcvt<<<dim3(24,48,6),wb>>>(sw2, Bs2, FF, CCH);
    // attention
    k_ln<<<NT,256>>>(x, ln1g, ln1b, nullptr, h1h, h1l, nullptr);
    k_mma<0><<<dim3(18,64),256,SMEMSZ>>>(h1h,h1l,Bqh,Bql,nullptr,nullptr,nullptr,
                                         NT,3*CCH,CCH);
    k_flash<<<dim3(8,BH),256,FSM2>>>();
    k_mma<1><<<dim3(6,64),256,SMEMSZ>>>(aoh,aol,Bph,Bpl,b_proj,x,x2, NT,CCH,CCH);
    // router
    k_ln<<<NT,256>>>(x2, ln2g, ln2b, h2, nullptr, nullptr, h2f);
    k_router<<<NT/8,256>>>(wr,br,wn,bn,temp,rno);
    // experts
    k_mmah<2><<<dim3(24,64,8),256,HSMEM>>>(h2f,0, nullptr,0, 99,
        Bd1, Bs1,(size_t)CCH*FF, 2, db1,sb1,
        nullptr, t1f, ZT1, NT,FF,CCH, tok, cnt);
    k_mmah<2><<<dim3(24,64,2),256,HSMEM>>>(t1f,ZT1, nullptr,0, 99,
        Bd2, nullptr,(size_t)FF*FF, 99, db2,nullptr,
        nullptr, t2f, ZT1, NT,FF,FF, nullptr, cnt);
    k_mmah<3><<<dim3(6,64,8),256,HSMEM>>>(t2f,ZT1, t1f,ZT1, 2,
        Bd3, Bs2,(size_t)CCH*FF, 2, db3,sb2,
        t3, nullptr, ZT3, NT,CCH,FF, nullptr, cnt);
    k_fin<<<NT,256>>>(t3, dlng, dlnb, slng, slnb, out);
}

// round 13
// speedup vs baseline: 7.3869x; 1.0128x over previous
#include <cuda_runtime.h>
#include <cuda_bf16.h>
#include <cuda_fp16.h>
#include <stdint.h>
#include <math.h>

#define BN 8
#define TT 1024
#define CCH 768
#define HH 12
#define HSZ 64
#define EE 8
#define FF 3072
#define NT (BN*TT)
#define BH (BN*HH)
typedef __nv_bfloat16 bf16;
typedef __half f16;

// ---- static scratch ----
__device__ bf16  g_qh[BH*TT*HSZ], g_ql[BH*TT*HSZ];
__device__ bf16  g_kh[BH*TT*HSZ], g_kl[BH*TT*HSZ];
__device__ bf16  g_vh[BH*TT*HSZ], g_vl[BH*TT*HSZ];
__device__ bf16  g_h1h[NT*CCH], g_h1l[NT*CCH];
__device__ bf16  g_aoh[NT*CCH], g_aol[NT*CCH];
__device__ float g_x2[NT*CCH];
__device__ float g_h2[NT*CCH];
__device__ f16   g_h2f[NT*CCH];
__device__ float g_gw[NT*2];
__device__ int   g_pos[NT*2];
__device__ int   g_tok[EE*NT];
__device__ int   g_cnt[EE];
__device__ f16   g_t1f[(size_t)EE*NT*FF];
__device__ f16   g_t2f[(size_t)2*NT*FF];
__device__ float g_t3[(size_t)EE*NT*CCH];
__device__ bf16  g_Bqh[3*CCH*CCH], g_Bql[3*CCH*CCH];
__device__ bf16  g_Bph[CCH*CCH],  g_Bpl[CCH*CCH];
__device__ f16   g_Bd1[2*CCH*FF];
__device__ f16   g_Bd2[(size_t)2*FF*FF];
__device__ f16   g_Bd3[2*CCH*FF];
__device__ f16   g_Bs1[(size_t)6*CCH*FF];
__device__ f16   g_Bs2[(size_t)6*CCH*FF];

__device__ __forceinline__ float geluf(float v){
    return 0.5f*v*(1.f + erff(v*0.70710678118654752440f));
}
__device__ __forceinline__ uint32_t smem_u32(const void* p){
    uint32_t a;
    asm("{ .reg .u64 t; cvta.to.shared.u64 t, %1; cvt.u32.u64 %0, t; }" : "=r"(a) : "l"(p));
    return a;
}
__device__ __forceinline__ void cp16(uint32_t d, const void* s){
    asm volatile("cp.async.cg.shared.global [%0], [%1], 16;" :: "r"(d), "l"(s));
}
__device__ __forceinline__ void ldsm4(uint32_t a, uint32_t* r){
    asm volatile("ldmatrix.sync.aligned.m8n8.x4.shared.b16 {%0,%1,%2,%3}, [%4];"
        : "=r"(r[0]),"=r"(r[1]),"=r"(r[2]),"=r"(r[3]) : "r"(a));
}
__device__ __forceinline__ void ldsm4t(uint32_t a, uint32_t* r){
    asm volatile("ldmatrix.sync.aligned.m8n8.x4.trans.shared.b16 {%0,%1,%2,%3}, [%4];"
        : "=r"(r[0]),"=r"(r[1]),"=r"(r[2]),"=r"(r[3]) : "r"(a));
}
__device__ __forceinline__ void mma16816(float* c, const uint32_t* a, const uint32_t* b){
    asm volatile("mma.sync.aligned.m16n8k16.row.col.f32.bf16.bf16.f32 "
        "{%0,%1,%2,%3},{%4,%5,%6,%7},{%8,%9},{%0,%1,%2,%3};"
        : "+f"(c[0]),"+f"(c[1]),"+f"(c[2]),"+f"(c[3])
        : "r"(a[0]),"r"(a[1]),"r"(a[2]),"r"(a[3]), "r"(b[0]),"r"(b[1]));
}
__device__ __forceinline__ void mmah16816(float* c, const uint32_t* a, const uint32_t* b){
    asm volatile("mma.sync.aligned.m16n8k16.row.col.f32.f16.f16.f32 "
        "{%0,%1,%2,%3},{%4,%5,%6,%7},{%8,%9},{%0,%1,%2,%3};"
        : "+f"(c[0]),"+f"(c[1]),"+f"(c[2]),"+f"(c[3])
        : "r"(a[0]),"r"(a[1]),"r"(a[2]),"r"(a[3]), "r"(b[0]),"r"(b[1]));
}
__device__ __forceinline__ uint32_t packbf(float a, float b){
    __nv_bfloat162 p; p.x=__float2bfloat16(a); p.y=__float2bfloat16(b);
    return *reinterpret_cast<uint32_t*>(&p);
}

__global__ void k_reset(){ if(threadIdx.x < EE) g_cnt[threadIdx.x] = 0; }

// W[K][N] -> out[N][K] hi/lo bf16 (attention weights)
__global__ void k_wsplit2(const float* __restrict__ W, bf16* __restrict__ oh,
                          bf16* __restrict__ ol, int K, int N){
    int e = blockIdx.z;
    W += (size_t)e*K*N; oh += (size_t)e*K*N; ol += (size_t)e*K*N;
    __shared__ float s[64][33];
    int n0 = blockIdx.x*32, k0 = blockIdx.y*64;
    int tx = threadIdx.x, ty = threadIdx.y;
#pragma unroll
    for(int r=0;r<8;r++){ int kk=ty+r*8; s[kk][tx] = W[(size_t)(k0+kk)*N + n0+tx]; }
    __syncthreads();
#pragma unroll
    for(int r=0;r<4;r++){
        int n = ty + r*8;
        float v0 = s[2*tx][n], v1 = s[2*tx+1][n];
        bf16 h0 = __float2bfloat16(v0), h1 = __float2bfloat16(v1);
        bf16 hh[2] = {h0, h1};
        bf16 ll[2] = {__float2bfloat16(v0-__bfloat162float(h0)),
                      __float2bfloat16(v1-__bfloat162float(h1))};
        size_t o = (size_t)(n0+n)*K + k0 + 2*tx;
        *reinterpret_cast<uint32_t*>(&oh[o]) = *reinterpret_cast<uint32_t*>(hh);
        *reinterpret_cast<uint32_t*>(&ol[o]) = *reinterpret_cast<uint32_t*>(ll);
    }
}

// W[K][N] -> out[N][K] single fp16 (expert weights)
__global__ void k_wcvt(const float* __restrict__ W, f16* __restrict__ oh, int K, int N){
    int e = blockIdx.z;
    W += (size_t)e*K*N; oh += (size_t)e*K*N;
    __shared__ float s[64][33];
    int n0 = blockIdx.x*32, k0 = blockIdx.y*64;
    int tx = threadIdx.x, ty = threadIdx.y;
#pragma unroll
    for(int r=0;r<8;r++){ int kk=ty+r*8; s[kk][tx] = W[(size_t)(k0+kk)*N + n0+tx]; }
    __syncthreads();
#pragma unroll
    for(int r=0;r<4;r++){
        int n = ty + r*8;
        __half2 hp; hp.x=__float2half(s[2*tx][n]); hp.y=__float2half(s[2*tx+1][n]);
        size_t o = (size_t)(n0+n)*K + k0 + 2*tx;
        *reinterpret_cast<__half2*>(&oh[o]) = hp;
    }
}

__global__ void k_ln(const float* __restrict__ in, const float* __restrict__ gam,
                     const float* __restrict__ bet, float* __restrict__ out,
                     bf16* __restrict__ oh, bf16* __restrict__ ol, f16* __restrict__ of){
    int n = blockIdx.x, t = threadIdx.x;
    const float* row = in + (size_t)n*CCH;
    float v[3], s=0.f, s2=0.f;
#pragma unroll
    for(int i=0;i<3;i++){ v[i]=row[t+256*i]; s+=v[i]; s2+=v[i]*v[i]; }
    __shared__ float shs[8], shq[8];
#pragma unroll
    for(int o=16;o;o>>=1){ s+=__shfl_xor_sync(~0u,s,o); s2+=__shfl_xor_sync(~0u,s2,o); }
    if((t&31)==0){ shs[t>>5]=s; shq[t>>5]=s2; }
    __syncthreads();
    s=0.f; s2=0.f;
#pragma unroll
    for(int i=0;i<8;i++){ s+=shs[i]; s2+=shq[i]; }
    float mean=s*(1.f/768.f), var=s2*(1.f/768.f)-mean*mean, r=rsqrtf(var+1e-5f);
#pragma unroll
    for(int i=0;i<3;i++){
        int c=t+256*i;
        float o=(v[i]-mean)*r*gam[c]+bet[c];
        if(out) out[(size_t)n*CCH+c]=o;
        if(oh){
            bf16 hi=__float2bfloat16(o);
            oh[(size_t)n*CCH+c]=hi;
            ol[(size_t)n*CCH+c]=__float2bfloat16(o-__bfloat162float(hi));
        }
        if(of) of[(size_t)n*CCH+c]=__float2half(o);
    }
}

// ---- bf16 3-product GEMM (QKV + proj), 2-stage, 2 CTAs/SM ----
#define PITCH 80
#define TILEB 10240
#define STAGEB 40960
#define SMEMSZ (2*STAGEB)
template<int EPI>
__global__ void __launch_bounds__(256,2)
k_mma(const bf16* __restrict__ Ah, const bf16* __restrict__ Al,
      const bf16* __restrict__ Bh, const bf16* __restrict__ Bl,
      const float* __restrict__ bias, const float* __restrict__ resid,
      float* __restrict__ out32, int M, int Nn, int K){
    int by = blockIdx.y, bx = blockIdx.x;
    extern __shared__ char smem[];
    uint32_t su = smem_u32(smem);
    int tid=threadIdx.x, lane=tid&31, wid=tid>>5;
    int wm=wid&3, wn=wid>>2;
    const int KT = K/32;
    float acc[2][8][4];
#pragma unroll
    for(int a=0;a<2;a++)
#pragma unroll
        for(int b=0;b<8;b++)
#pragma unroll
            for(int c=0;c<4;c++) acc[a][b][c]=0.f;
    auto load_stage = [&](int kt){
        uint32_t sb = su + (kt&1)*STAGEB;
#pragma unroll
        for(int i=0;i<8;i++){
            int c = tid + i*256;
            int tile=c>>9, w=c&511, row=w>>2, q=w&3;
            uint32_t d = sb + tile*TILEB + row*PITCH + q*16;
            const bf16* src;
            if(tile<2) src = (tile==0?Ah:Al) + (size_t)(by*128+row)*K + kt*32 + q*8;
            else       src = (tile==2?Bh:Bl) + (size_t)(bx*128+row)*K + kt*32 + q*8;
            cp16(d, src);
        }
        asm volatile("cp.async.commit_group;" ::: "memory");
    };
    load_stage(0);
    for(int kt=0; kt<KT; kt++){
        if(kt+1<KT){
            load_stage(kt+1);
            asm volatile("cp.async.wait_group 1;" ::: "memory");
        } else {
            asm volatile("cp.async.wait_group 0;" ::: "memory");
        }
        __syncthreads();
        uint32_t sb = su + (kt&1)*STAGEB;
#pragma unroll
        for(int kh=0; kh<2; kh++){
            uint32_t aH[2][4], aL[2][4];
            int arow = wm*32 + (lane&15);
            uint32_t ako = kh*32 + (lane>>4)*16;
#pragma unroll
            for(int mt=0;mt<2;mt++){
                uint32_t ad = sb + (arow+mt*16)*PITCH + ako;
                ldsm4(ad, aH[mt]); ldsm4(ad + TILEB, aL[mt]);
            }
            uint32_t bHf[4][4], bLf[4][4];
            int brow = wn*64 + ((lane&7) | ((lane&16)>>1));
            uint32_t bko = kh*32 + ((lane>>3)&1)*16;
#pragma unroll
            for(int nt=0;nt<4;nt++){
                uint32_t bd = sb + 2*TILEB + (brow+nt*16)*PITCH + bko;
                ldsm4(bd, bHf[nt]); ldsm4(bd + TILEB, bLf[nt]);
            }
#pragma unroll
            for(int mt=0;mt<2;mt++)
#pragma unroll
            for(int n8=0;n8<8;n8++){
                uint32_t* bh = &bHf[n8>>1][(n8&1)*2];
                uint32_t* bl = &bLf[n8>>1][(n8&1)*2];
                mma16816(acc[mt][n8], aH[mt], bh);
                mma16816(acc[mt][n8], aH[mt], bl);
                mma16816(acc[mt][n8], aL[mt], bh);
            }
        }
        __syncthreads();
    }
    int g = lane>>2, t4 = lane&3;
#pragma unroll
    for(int mt=0;mt<2;mt++)
#pragma unroll
    for(int n8=0;n8<8;n8++){
        int col = bx*128 + wn*64 + n8*8 + t4*2;
#pragma unroll
        for(int hf=0; hf<2; hf++){
            int row = by*128 + wm*32 + mt*16 + g + hf*8;
            float v0 = acc[mt][n8][hf*2+0];
            float v1 = acc[mt][n8][hf*2+1];
            if(EPI==0){
                int which = col/CCH, rem = col - which*CCH;
                int h = rem>>6, d0 = rem&63;
                int b = row>>10, t = row&1023;
                size_t o = ((size_t)(b*HH+h)*TT + t)*HSZ + d0;
                bf16* dh = which==0? g_qh : which==1? g_kh : g_vh;
                bf16* dl = which==0? g_ql : which==1? g_kl : g_vl;
                bf16 h0=__float2bfloat16(v0), h1=__float2bfloat16(v1);
                __nv_bfloat162 hp; hp.x=h0; hp.y=h1;
                __nv_bfloat162 lp;
                lp.x=__float2bfloat16(v0-__bfloat162float(h0));
                lp.y=__float2bfloat16(v1-__bfloat162float(h1));
                *reinterpret_cast<__nv_bfloat162*>(&dh[o]) = hp;
                *reinterpret_cast<__nv_bfloat162*>(&dl[o]) = lp;
            } else {
                size_t o=(size_t)row*Nn+col;
                out32[o]   = v0 + bias[col]   + resid[o];
                out32[o+1] = v1 + bias[col+1] + resid[o+1];
            }
        }
    }
}

// ---- fp16 single-product GEMM (experts), 3-stage, 2 CTAs/SM, z-batched ----
#define HSTG (2*TILEB)
#define HSMEM (3*HSTG)
template<int EPI>
__global__ void __launch_bounds__(256,2)
k_mmah(const f16* __restrict__ A1, size_t zsA, const f16* __restrict__ A2, size_t zsA2,
       int zSplitA,
       const f16* __restrict__ B1, const f16* __restrict__ B2, size_t zsB, int zSplit,
       const float* __restrict__ b1, const float* __restrict__ b2,
       float* __restrict__ out32, f16* __restrict__ outH, size_t zsOut,
       int M, int Nn, int K,
       const int* __restrict__ tok, const int* __restrict__ cnt){
    int z = blockIdx.z;
    if(cnt) M = cnt[z];
    int by = blockIdx.y, bx = blockIdx.x;
    if(by*128 >= M) return;
    const f16* A = (z < zSplitA) ? A1 + (size_t)z*zsA : A2 + (size_t)z*zsA2;
    const f16* Bp; const float* bias;
    if(z < zSplit){ Bp=B1+(size_t)z*zsB; bias=b1+(size_t)z*Nn; }
    else { Bp=B2+(size_t)(z-zSplit)*zsB; bias=b2+(size_t)(z-zSplit)*Nn; }
    if(out32) out32 += (size_t)z*zsOut;
    if(outH)  outH  += (size_t)z*zsOut;
    if(tok) tok += (size_t)z*NT;
    extern __shared__ char smem[];
    uint32_t su = smem_u32(smem);
    int tid=threadIdx.x, lane=tid&31, wid=tid>>5;
    int wm=wid&3, wn=wid>>2;
    const int KT = K/32;
    float acc[2][8][4];
#pragma unroll
    for(int a=0;a<2;a++)
#pragma unroll
        for(int b=0;b<8;b++)
#pragma unroll
            for(int c=0;c<4;c++) acc[a][b][c]=0.f;
    auto load_stage = [&](int kt){
        uint32_t sb = su + (kt%3)*HSTG;
#pragma unroll
        for(int i=0;i<4;i++){
            int c = tid + i*256;
            int tile=c>>9, w=c&511, row=w>>2, q=w&3;
            uint32_t d = sb + tile*TILEB + row*PITCH + q*16;
            const f16* src;
            if(tile==0){
                int rg=by*128+row; if(rg>=M) rg=M-1;
                int asrc = tok ? tok[rg] : rg;
                src = A + (size_t)asrc*K + kt*32 + q*8;
            } else {
                src = Bp + (size_t)(bx*128+row)*K + kt*32 + q*8;
            }
            cp16(d, src);
        }
        asm volatile("cp.async.commit_group;" ::: "memory");
    };
    load_stage(0);
    if(KT>1) load_stage(1);
    for(int kt=0; kt<KT; kt++){
        if(kt+2<KT) load_stage(kt+2);
        if(kt+2<KT)      asm volatile("cp.async.wait_group 2;" ::: "memory");
        else if(kt+1<KT) asm volatile("cp.async.wait_group 1;" ::: "memory");
        else             asm volatile("cp.async.wait_group 0;" ::: "memory");
        __syncthreads();
        uint32_t sb = su + (kt%3)*HSTG;
#pragma unroll
        for(int kh=0; kh<2; kh++){
            uint32_t aF[2][4];
            int arow = wm*32 + (lane&15);
            uint32_t ako = kh*32 + (lane>>4)*16;
#pragma unroll
            for(int mt=0;mt<2;mt++)
                ldsm4(sb + (arow+mt*16)*PITCH + ako, aF[mt]);
            uint32_t bF[4][4];
            int brow = wn*64 + ((lane&7) | ((lane&16)>>1));
            uint32_t bko = kh*32 + ((lane>>3)&1)*16;
#pragma unroll
            for(int nt=0;nt<4;nt++)
                ldsm4(sb + TILEB + (brow+nt*16)*PITCH + bko, bF[nt]);
#pragma unroll
            for(int mt=0;mt<2;mt++)
#pragma unroll
            for(int n8=0;n8<8;n8++)
                mmah16816(acc[mt][n8], aF[mt], &bF[n8>>1][(n8&1)*2]);
        }
        __syncthreads();
    }
    int g = lane>>2, t4 = lane&3;
#pragma unroll
    for(int mt=0;mt<2;mt++)
#pragma unroll
    for(int n8=0;n8<8;n8++){
        int col = bx*128 + wn*64 + n8*8 + t4*2;
#pragma unroll
        for(int hf=0; hf<2; hf++){
            int row = by*128 + wm*32 + mt*16 + g + hf*8;
            if(row >= M) continue;
            float v0 = acc[mt][n8][hf*2+0];
            float v1 = acc[mt][n8][hf*2+1];
            size_t o=(size_t)row*Nn+col;
            if(EPI==2){
                __half2 hp;
                hp.x = __float2half(geluf(v0 + bias[col]));
                hp.y = __float2half(geluf(v1 + bias[col+1]));
                *reinterpret_cast<__half2*>(&outH[o]) = hp;
            } else {
                out32[o]   = v0 + bias[col];
                out32[o+1] = v1 + bias[col+1];
            }
        }
    }
}

// ---- flash attention v2 ----
#define FP2 144
#define QT (128*FP2)
#define KT2 (64*FP2)
#define STG2 (4*KT2)
#define FSM2 (2*QT + 2*STG2)
__global__ void __launch_bounds__(256,1) k_flash(){
    int tb = 7 - blockIdx.x, bh = blockIdx.y;
    extern __shared__ char fsm[];
    uint32_t su = smem_u32(fsm);
    uint32_t qb = su, kvb = su + 2*QT;
    int tid=threadIdx.x, lane=tid&31, w=tid>>5;
    const size_t hb = (size_t)bh*TT*HSZ;
#pragma unroll
    for(int i=0;i<8;i++){
        int c = tid + i*256;
        int half = c>>10, w2 = c&1023, row = w2>>3, q = w2&7;
        cp16(qb + half*QT + row*FP2 + q*16,
             (half? g_ql : g_qh) + hb + (size_t)(tb*128+row)*HSZ + q*8);
    }
    auto loadKV = [&](int sb){
        uint32_t base = kvb + (sb&1)*STG2;
#pragma unroll
        for(int i=0;i<8;i++){
            int c = tid + i*256;
            int arr = c>>9, w2 = c&511, row = w2>>3, q = w2&7;
            const bf16* src = (arr==0? g_kh : arr==1? g_kl : arr==2? g_vh : g_vl)
                            + hb + (size_t)(sb*64+row)*HSZ + q*8;
            cp16(base + arr*KT2 + row*FP2 + q*16, src);
        }
        asm volatile("cp.async.commit_group;" ::: "memory");
    };
    loadKV(0);
    float m0=-1e30f, m1=-1e30f, l0=0.f, l1=0.f;
    float O[8][4];
#pragma unroll
    for(int n8=0;n8<8;n8++)
#pragma unroll
        for(int c=0;c<4;c++) O[n8][c]=0.f;
    const float scale=0.036084391824351615f;
    int brow = (lane&7) | ((lane&16)>>1);
    int t4 = lane&3, g = lane>>2;
    int smax = 2*tb+1;
    for(int sb=0; sb<=smax; sb++){
        if(sb<smax) loadKV(sb+1);
        if(sb<smax) asm volatile("cp.async.wait_group 1;" ::: "memory");
        else        asm volatile("cp.async.wait_group 0;" ::: "memory");
        __syncthreads();
        uint32_t kb = kvb + (sb&1)*STG2;
        uint32_t vb = kb + 2*KT2;
        float S[8][4];
#pragma unroll
        for(int n8=0;n8<8;n8++)
#pragma unroll
            for(int c=0;c<4;c++) S[n8][c]=0.f;
#pragma unroll
        for(int kc=0;kc<4;kc++){
            uint32_t aH[4], aL[4];
            uint32_t ad = qb + (w*16+(lane&15))*FP2 + kc*32 + (lane>>4)*16;
            ldsm4(ad, aH); ldsm4(ad+QT, aL);
            uint32_t bHt[4][4], bLt[4][4];
#pragma unroll
            for(int nt=0;nt<4;nt++){
                uint32_t bd = kb + (nt*16+brow)*FP2 + kc*32 + ((lane>>3)&1)*16;
                ldsm4(bd, bHt[nt]); ldsm4(bd+KT2, bLt[nt]);
            }
#pragma unroll
            for(int n8=0;n8<8;n8++){
                uint32_t* bh2=&bHt[n8>>1][(n8&1)*2];
                uint32_t* bl2=&bLt[n8>>1][(n8&1)*2];
                mma16816(S[n8], aH, bh2);
                mma16816(S[n8], aH, bl2);
                mma16816(S[n8], aL, bh2);
            }
        }
        int rg0 = tb*128 + w*16 + g;
#pragma unroll
        for(int n8=0;n8<8;n8++)
#pragma unroll
            for(int c=0;c<4;c++){
                S[n8][c] *= scale;
                if(sb >= 2*tb){
                    int sg = sb*64 + n8*8 + t4*2 + (c&1);
                    int rg = rg0 + ((c>=2)?8:0);
                    if(sg > rg) S[n8][c] = -1e30f;
                }
            }
        float mx0=-1e30f, mx1=-1e30f;
#pragma unroll
        for(int n8=0;n8<8;n8++){
            mx0=fmaxf(mx0,fmaxf(S[n8][0],S[n8][1]));
            mx1=fmaxf(mx1,fmaxf(S[n8][2],S[n8][3]));
        }
        mx0=fmaxf(mx0,__shfl_xor_sync(~0u,mx0,1)); mx0=fmaxf(mx0,__shfl_xor_sync(~0u,mx0,2));
        mx1=fmaxf(mx1,__shfl_xor_sync(~0u,mx1,1)); mx1=fmaxf(mx1,__shfl_xor_sync(~0u,mx1,2));
        float mn0=fmaxf(m0,mx0), mn1=fmaxf(m1,mx1);
        float f0=expf(m0-mn0), f1=expf(m1-mn1);
        m0=mn0; m1=mn1;
        float rs0=0.f, rs1=0.f;
#pragma unroll
        for(int n8=0;n8<8;n8++){
            S[n8][0]=expf(S[n8][0]-mn0); S[n8][1]=expf(S[n8][1]-mn0);
            S[n8][2]=expf(S[n8][2]-mn1); S[n8][3]=expf(S[n8][3]-mn1);
            rs0+=S[n8][0]+S[n8][1]; rs1+=S[n8][2]+S[n8][3];
        }
        rs0+=__shfl_xor_sync(~0u,rs0,1); rs0+=__shfl_xor_sync(~0u,rs0,2);
        rs1+=__shfl_xor_sync(~0u,rs1,1); rs1+=__shfl_xor_sync(~0u,rs1,2);
        l0=l0*f0+rs0; l1=l1*f1+rs1;
#pragma unroll
        for(int n8=0;n8<8;n8++){
            O[n8][0]*=f0; O[n8][1]*=f0; O[n8][2]*=f1; O[n8][3]*=f1;
        }
#pragma unroll
        for(int j=0;j<4;j++){
            float p00=S[2*j][0], p01=S[2*j][1], p02=S[2*j][2], p03=S[2*j][3];
            float p10=S[2*j+1][0], p11=S[2*j+1][1], p12=S[2*j+1][2], p13=S[2*j+1][3];
            uint32_t aPh[4], aPl[4];
            aPh[0]=packbf(p00,p01); aPh[1]=packbf(p02,p03);
            aPh[2]=packbf(p10,p11); aPh[3]=packbf(p12,p13);
            {
                __nv_bfloat162 t;
                t=*(__nv_bfloat162*)&aPh[0];
                aPl[0]=packbf(p00-__bfloat162float(t.x), p01-__bfloat162float(t.y));
                t=*(__nv_bfloat162*)&aPh[1];
                aPl[1]=packbf(p02-__bfloat162float(t.x), p03-__bfloat162float(t.y));
                t=*(__nv_bfloat162*)&aPh[2];
                aPl[2]=packbf(p10-__bfloat162float(t.x), p11-__bfloat162float(t.y));
                t=*(__nv_bfloat162*)&aPh[3];
                aPl[3]=packbf(p12-__bfloat162float(t.x), p13-__bfloat162float(t.y));
            }
            uint32_t bHt[4][4], bLt[4][4];
            uint32_t vrow = (j*16 + (lane&15))*FP2 + (lane>>4)*16;
#pragma unroll
            for(int nt=0;nt<4;nt++){
                uint32_t bd = vb + vrow + nt*32;
                ldsm4t(bd, bHt[nt]); ldsm4t(bd+KT2, bLt[nt]);
            }
#pragma unroll
            for(int n8=0;n8<8;n8++){
                uint32_t* bh2=&bHt[n8>>1][(n8&1)*2];
                uint32_t* bl2=&bLt[n8>>1][(n8&1)*2];
                mma16816(O[n8], aPh, bh2);
                mma16816(O[n8], aPh, bl2);
                mma16816(O[n8], aPl, bh2);
            }
        }
        __syncthreads();
    }
    float i0=1.f/l0, i1=1.f/l1;
    int b = bh/HH, h = bh%HH;
#pragma unroll
    for(int n8=0;n8<8;n8++){
        int col = h*64 + n8*8 + t4*2;
#pragma unroll
        for(int hf=0;hf<2;hf++){
            int tokr = b*1024 + tb*128 + w*16 + g + hf*8;
            float v0 = O[n8][hf*2+0]*(hf?i1:i0);
            float v1 = O[n8][hf*2+1]*(hf?i1:i0);
            size_t o=(size_t)tokr*CCH+col;
            bf16 h0=__float2bfloat16(v0), h1=__float2bfloat16(v1);
            __nv_bfloat162 hp2; hp2.x=h0; hp2.y=h1;
            __nv_bfloat162 lp;
            lp.x=__float2bfloat16(v0-__bfloat162float(h0));
            lp.y=__float2bfloat16(v1-__bfloat162float(h1));
            *reinterpret_cast<__nv_bfloat162*>(&g_aoh[o]) = hp2;
            *reinterpret_cast<__nv_bfloat162*>(&g_aol[o]) = lp;
        }
    }
}

__global__ void k_router(const float* __restrict__ wr, const float* __restrict__ br,
                         const float* __restrict__ wn, const float* __restrict__ bnn,
                         const float* __restrict__ temp, const float* __restrict__ noise){
    int warp=threadIdx.x>>5, lane=threadIdx.x&31;
    int n=blockIdx.x*8+warp;
    const float* hp = g_h2 + (size_t)n*CCH;
    float r[8]={}, q[8]={};
    for(int c=lane;c<CCH;c+=32){
        float hv=hp[c];
        const float* wrp=wr+c*EE; const float* wnp=wn+c*EE;
#pragma unroll
        for(int e=0;e<8;e++){ r[e]+=hv*wrp[e]; q[e]+=hv*wnp[e]; }
    }
#pragma unroll
    for(int e=0;e<8;e++)
#pragma unroll
        for(int o=16;o;o>>=1){
            r[e]+=__shfl_xor_sync(~0u,r[e],o);
            q[e]+=__shfl_xor_sync(~0u,q[e],o);
        }
    if(lane==0){
        float t=fminf(fmaxf(temp[0],0.5f),2.0f);
        float ny[8];
#pragma unroll
        for(int e=0;e<8;e++){
            float z=q[e]+bnn[e];
            float sp=(z>20.f)? z : log1pf(expf(z));
            ny[e]=r[e]+br[e] + t*noise[(size_t)n*EE+e]*sp;
        }
        int i1=0;
#pragma unroll
        for(int e=1;e<8;e++) if(ny[e]>ny[i1]) i1=e;
        int i2=-1;
#pragma unroll
        for(int e=0;e<8;e++){ if(e==i1) continue; if(i2<0||ny[e]>ny[i2]) i2=e; }
        float e2=expf(ny[i2]-ny[i1]);
        float gv[2]={1.f/(1.f+e2), e2/(1.f+e2)};
        int id[2]={i1,i2};
#pragma unroll
        for(int k2=0;k2<2;k2++){
            int e=id[k2];
            int row=atomicAdd(&g_cnt[e],1);
            g_tok[e*NT+row]=n;
            g_pos[n*2+k2]=e*NT+row;
            g_gw[n*2+k2]=gv[k2];
        }
    }
}

// fused dual residual-LN + gated combine
__global__ void k_fin(const float* __restrict__ t3,
                      const float* __restrict__ dg, const float* __restrict__ db_,
                      const float* __restrict__ sg, const float* __restrict__ sb_,
                      float* __restrict__ out){
    int n=blockIdx.x, t=threadIdx.x;
    int s0=g_pos[2*n], s1=g_pos[2*n+1];
    int e0=s0>>13, r0=s0&8191, e1=s1>>13, r1=s1&8191;
    const float* ta = t3 + (size_t)e0*NT*CCH + (size_t)r0*CCH;
    const float* tb = t3 + (size_t)e1*NT*CCH + (size_t)r1*CCH;
    float va[3], vb[3];
    float sa=0.f,qa=0.f,sb2=0.f,qb=0.f;
#pragma unroll
    for(int i=0;i<3;i++){
        int c=t+256*i;
        float h = g_h2[(size_t)n*CCH+c];
        va[i]=h+ta[c]; vb[i]=h+tb[c];
        sa+=va[i]; qa+=va[i]*va[i]; sb2+=vb[i]; qb+=vb[i]*vb[i];
    }
    __shared__ float sh[8][4];
#pragma unroll
    for(int o=16;o;o>>=1){
        sa+=__shfl_xor_sync(~0u,sa,o); qa+=__shfl_xor_sync(~0u,qa,o);
        sb2+=__shfl_xor_sync(~0u,sb2,o); qb+=__shfl_xor_sync(~0u,qb,o);
    }
    if((t&31)==0){ sh[t>>5][0]=sa; sh[t>>5][1]=qa; sh[t>>5][2]=sb2; sh[t>>5][3]=qb; }
    __syncthreads();
    sa=0.f; qa=0.f; sb2=0.f; qb=0.f;
#pragma unroll
    for(int i=0;i<8;i++){ sa+=sh[i][0]; qa+=sh[i][1]; sb2+=sh[i][2]; qb+=sh[i][3]; }
    float ma=sa*(1.f/768.f), ra=rsqrtf(qa*(1.f/768.f)-ma*ma+1e-5f);
    float mb=sb2*(1.f/768.f), rb=rsqrtf(qb*(1.f/768.f)-mb*mb+1e-5f);
    const float* g0p = (e0<2)? dg+e0*CCH : sg+(e0-2)*CCH;
    const float* b0p = (e0<2)? db_+e0*CCH : sb_+(e0-2)*CCH;
    const float* g1p = (e1<2)? dg+e1*CCH : sg+(e1-2)*CCH;
    const float* b1p = (e1<2)? db_+e1*CCH : sb_+(e1-2)*CCH;
    float gw0=g_gw[2*n], gw1=g_gw[2*n+1];
#pragma unroll
    for(int i=0;i<3;i++){
        int c=t+256*i;
        float o0=(va[i]-ma)*ra*g0p[c]+b0p[c];
        float o1=(vb[i]-mb)*rb*g1p[c]+b1p[c];
        out[(size_t)n*CCH+c]=g_x2[(size_t)n*CCH+c]+gw0*o0+gw1*o1;
    }
}

extern "C" void kernel_launch(void* const* d_in, const int* in_sizes, int n_in,
                              void* d_out, int out_size){
    const float *x=(const float*)d_in[0], *rno=(const float*)d_in[1];
    const float *wq=(const float*)d_in[2], *wk=(const float*)d_in[3], *wv=(const float*)d_in[4];
    const float *w_proj=(const float*)d_in[5], *b_proj=(const float*)d_in[6];
    const float *ln1g=(const float*)d_in[7], *ln1b=(const float*)d_in[8];
    const float *ln2g=(const float*)d_in[9], *ln2b=(const float*)d_in[10];
    const float *wr=(const float*)d_in[11], *br=(const float*)d_in[12];
    const float *wn=(const float*)d_in[13], *bn=(const float*)d_in[14];
    const float *temp=(const float*)d_in[15];
    const float *dw1=(const float*)d_in[16], *db1=(const float*)d_in[17];
    const float *dw2=(const float*)d_in[18], *db2=(const float*)d_in[19];
    const float *dw3=(const float*)d_in[20], *db3=(const float*)d_in[21];
    const float *dlng=(const float*)d_in[22], *dlnb=(const float*)d_in[23];
    const float *sw1=(const float*)d_in[24], *sb1=(const float*)d_in[25];
    const float *sw2=(const float*)d_in[26], *sb2=(const float*)d_in[27];
    const float *slng=(const float*)d_in[28], *slnb=(const float*)d_in[29];
    float* out=(float*)d_out;

    static cudaStream_t s2 = nullptr;
    static cudaEvent_t evF = nullptr, evP = nullptr, evE = nullptr;
    if(!s2){
        cudaStreamCreateWithFlags(&s2, cudaStreamNonBlocking);
        cudaEventCreateWithFlags(&evF, cudaEventDisableTiming);
        cudaEventCreateWithFlags(&evP, cudaEventDisableTiming);
        cudaEventCreateWithFlags(&evE, cudaEventDisableTiming);
        cudaFuncSetAttribute(k_mma<0>, cudaFuncAttributeMaxDynamicSharedMemorySize, SMEMSZ);
        cudaFuncSetAttribute(k_mma<1>, cudaFuncAttributeMaxDynamicSharedMemorySize, SMEMSZ);
        cudaFuncSetAttribute(k_mmah<2>, cudaFuncAttributeMaxDynamicSharedMemorySize, HSMEM);
        cudaFuncSetAttribute(k_mmah<3>, cudaFuncAttributeMaxDynamicSharedMemorySize, HSMEM);
        cudaFuncSetAttribute(k_flash, cudaFuncAttributeMaxDynamicSharedMemorySize, FSM2);
    }

    bf16 *Bqh,*Bql,*Bph,*Bpl,*h1h,*h1l,*aoh,*aol;
    f16 *Bd1,*Bd2,*Bd3,*Bs1,*Bs2,*h2f,*t1f,*t2f;
    float *x2,*h2,*t3; int *tok,*cnt;
    cudaGetSymbolAddress((void**)&Bqh,g_Bqh); cudaGetSymbolAddress((void**)&Bql,g_Bql);
    cudaGetSymbolAddress((void**)&Bph,g_Bph); cudaGetSymbolAddress((void**)&Bpl,g_Bpl);
    cudaGetSymbolAddress((void**)&Bd1,g_Bd1);
    cudaGetSymbolAddress((void**)&Bd2,g_Bd2);
    cudaGetSymbolAddress((void**)&Bd3,g_Bd3);
    cudaGetSymbolAddress((void**)&Bs1,g_Bs1);
    cudaGetSymbolAddress((void**)&Bs2,g_Bs2);
    cudaGetSymbolAddress((void**)&h1h,g_h1h); cudaGetSymbolAddress((void**)&h1l,g_h1l);
    cudaGetSymbolAddress((void**)&aoh,g_aoh); cudaGetSymbolAddress((void**)&aol,g_aol);
    cudaGetSymbolAddress((void**)&h2f,g_h2f);
    cudaGetSymbolAddress((void**)&t1f,g_t1f); cudaGetSymbolAddress((void**)&t2f,g_t2f);
    cudaGetSymbolAddress((void**)&x2,g_x2); cudaGetSymbolAddress((void**)&h2,g_h2);
    cudaGetSymbolAddress((void**)&t3,g_t3);
    cudaGetSymbolAddress((void**)&tok,g_tok); cudaGetSymbolAddress((void**)&cnt,g_cnt);
    const size_t ZT1=(size_t)NT*FF, ZT3=(size_t)NT*CCH;

    dim3 wb(32,8);
    k_reset<<<1,32>>>();
    // fork: weight prep for proj + experts on s2, overlapped with attention
    cudaEventRecord(evF, 0);
    cudaStreamWaitEvent(s2, evF, 0);
    k_wsplit2<<<dim3(24,12,1),wb,0,s2>>>(w_proj, Bph, Bpl, CCH, CCH);
    cudaEventRecord(evP, s2);
    k_wcvt<<<dim3(96,12,2),wb,0,s2>>>(dw1, Bd1, CCH, FF);
    k_wcvt<<<dim3(96,48,2),wb,0,s2>>>(dw2, Bd2, FF, FF);
    k_wcvt<<<dim3(24,48,2),wb,0,s2>>>(dw3, Bd3, FF, CCH);
    k_wcvt<<<dim3(96,12,6),wb,0,s2>>>(sw1, Bs1, CCH, FF);
    k_wcvt<<<dim3(24,48,6),wb,0,s2>>>(sw2, Bs2, FF, CCH);
    cudaEventRecord(evE, s2);
    // main: QKV weight split + attention
    k_wsplit2<<<dim3(2,12,12),wb>>>(wq, Bqh,           Bql,           CCH, HSZ);
    k_wsplit2<<<dim3(2,12,12),wb>>>(wk, Bqh+CCH*CCH,   Bql+CCH*CCH,   CCH, HSZ);
    k_wsplit2<<<dim3(2,12,12),wb>>>(wv, Bqh+2*CCH*CCH, Bql+2*CCH*CCH, CCH, HSZ);
    k_ln<<<NT,256>>>(x, ln1g, ln1b, nullptr, h1h, h1l, nullptr);
    k_mma<0><<<dim3(18,64),256,SMEMSZ>>>(h1h,h1l,Bqh,Bql,nullptr,nullptr,nullptr,
                                         NT,3*CCH,CCH);
    k_flash<<<dim3(8,BH),256,FSM2>>>();
    cudaStreamWaitEvent(0, evP, 0);
    k_mma<1><<<dim3(6,64),256,SMEMSZ>>>(aoh,aol,Bph,Bpl,b_proj,x,x2, NT,CCH,CCH);
    // router
    k_ln<<<NT,256>>>(x2, ln2g, ln2b, h2, nullptr, nullptr, h2f);
    k_router<<<NT/8,256>>>(wr,br,wn,bn,temp,rno);
    // experts (join expert weight prep)
    cudaStreamWaitEvent(0, evE, 0);
    k_mmah<2><<<dim3(24,64,8),256,HSMEM>>>(h2f,0, nullptr,0, 99,
        Bd1, Bs1,(size_t)CCH*FF, 2, db1,sb1,
        nullptr, t1f, ZT1, NT,FF,CCH, tok, cnt);
    k_mmah<2><<<dim3(24,64,2),256,HSMEM>>>(t1f,ZT1, nullptr,0, 99,
        Bd2, nullptr,(size_t)FF*FF, 99, db2,nullptr,
        nullptr, t2f, ZT1, NT,FF,FF, nullptr, cnt);
    k_mmah<3><<<dim3(6,64,8),256,HSMEM>>>(t2f,ZT1, t1f,ZT1, 2,
        Bd3, Bs2,(size_t)CCH*FF, 2, db3,sb2,
        t3, nullptr, ZT3, NT,CCH,FF, nullptr, cnt);
    k_fin<<<NT,256>>>(t3, dlng, dlnb, slng, slnb, out);
}